// round 1
// baseline (speedup 1.0000x reference)
#include <cuda_runtime.h>
#include <math.h>

#define NL 6
#define D 512
#define S 2048
#define B 8
#define FF (4*D)
#define ROWS (B*S)          // 16384

// ---------------- scratch (device globals: allocation-free) ----------------
__device__ float g_x  [ROWS*(size_t)D];
__device__ float g_xn [ROWS*(size_t)D];
__device__ float g_q  [ROWS*(size_t)D];
__device__ float g_k  [ROWS*(size_t)D];
__device__ float g_v  [ROWS*(size_t)D];
__device__ float g_att[ROWS*(size_t)D];
__device__ float g_sc [(size_t)B*S*S];
__device__ float g_h  [ROWS*(size_t)FF];

// ---------------- encoder: cat(z,c)@W^T + b + posenc ----------------
__global__ void encoder_kernel(const float* __restrict__ z, const float* __restrict__ c,
                               const float* __restrict__ ew, const float* __restrict__ eb,
                               float* __restrict__ x) {
    int i = blockIdx.x * blockDim.x + threadIdx.x;
    if (i >= ROWS * D) return;
    int d  = i % D;
    int bs = i / D;
    int s  = bs % S;
    float val = z[bs] * ew[d*2+0] + c[bs] * ew[d*2+1] + eb[d];
    int k2 = d & ~1;
    float div = expf(-(float)k2 * (logf(10000.0f) / (float)D));
    float ang = (float)s * div;
    val += (d & 1) ? cosf(ang) : sinf(ang);
    x[i] = val;
}

// ---------------- layernorm (optional residual), row length D=512 ----------
__global__ void ln_kernel(const float* __restrict__ in, const float* __restrict__ res,
                          const float* __restrict__ w, const float* __restrict__ b,
                          float* __restrict__ out) {
    int row = blockIdx.x;
    const float* ip = in + (size_t)row * D;
    int t = threadIdx.x;            // 256 threads, 2 elems each
    float v0 = ip[t];
    float v1 = ip[t + 256];
    if (res) {
        const float* rp = res + (size_t)row * D;
        v0 += rp[t];
        v1 += rp[t + 256];
    }
    float s = v0 + v1, ss = v0*v0 + v1*v1;
    #pragma unroll
    for (int o = 16; o; o >>= 1) {
        s  += __shfl_xor_sync(0xffffffffu, s,  o);
        ss += __shfl_xor_sync(0xffffffffu, ss, o);
    }
    __shared__ float sh_s[8], sh_ss[8];
    int wid = t >> 5, lid = t & 31;
    if (lid == 0) { sh_s[wid] = s; sh_ss[wid] = ss; }
    __syncthreads();
    float ts = 0.f, tss = 0.f;
    #pragma unroll
    for (int i = 0; i < 8; i++) { ts += sh_s[i]; tss += sh_ss[i]; }
    float mean = ts * (1.0f / D);
    float var  = tss * (1.0f / D) - mean * mean;
    float rstd = rsqrtf(var + 1e-5f);
    float* op = out + (size_t)row * D;
    op[t]       = (v0 - mean) * rstd * w[t]       + b[t];
    op[t + 256] = (v1 - mean) * rstd * w[t + 256] + b[t + 256];
}

// ---------------- NT GEMM: C[m,n] = sum_k A[m,k]*W[n,k] (+bias)(+relu)(+resid)
// BM=BN=64, BK=16, 256 threads, 4x4 microtile. M%64==N%64==K%16==0 assumed.
__global__ void gemm_nt(const float* __restrict__ A, const float* __restrict__ W,
                        const float* __restrict__ bias, const float* __restrict__ resid,
                        float* __restrict__ C, int M, int N, int K, int relu) {
    __shared__ float As[16][64];
    __shared__ float Bs[16][64];
    int tid = threadIdx.x;
    int tx = tid & 15, ty = tid >> 4;
    int rowBase = blockIdx.y * 64, colBase = blockIdx.x * 64;

    int lr = tid >> 2;           // 0..63 tile row
    int lc = (tid & 3) * 4;      // k offset 0/4/8/12
    const float* Ap = A + (size_t)(rowBase + lr) * K + lc;
    const float* Wp = W + (size_t)(colBase + lr) * K + lc;

    float acc[4][4] = {};
    for (int k0 = 0; k0 < K; k0 += 16) {
        float4 a = *(const float4*)(Ap + k0);
        float4 w4 = *(const float4*)(Wp + k0);
        As[lc+0][lr] = a.x;  As[lc+1][lr] = a.y;  As[lc+2][lr] = a.z;  As[lc+3][lr] = a.w;
        Bs[lc+0][lr] = w4.x; Bs[lc+1][lr] = w4.y; Bs[lc+2][lr] = w4.z; Bs[lc+3][lr] = w4.w;
        __syncthreads();
        #pragma unroll
        for (int k = 0; k < 16; k++) {
            float4 av = *(const float4*)&As[k][ty*4];
            float4 bv = *(const float4*)&Bs[k][tx*4];
            acc[0][0] += av.x*bv.x; acc[0][1] += av.x*bv.y; acc[0][2] += av.x*bv.z; acc[0][3] += av.x*bv.w;
            acc[1][0] += av.y*bv.x; acc[1][1] += av.y*bv.y; acc[1][2] += av.y*bv.z; acc[1][3] += av.y*bv.w;
            acc[2][0] += av.z*bv.x; acc[2][1] += av.z*bv.y; acc[2][2] += av.z*bv.z; acc[2][3] += av.z*bv.w;
            acc[3][0] += av.w*bv.x; acc[3][1] += av.w*bv.y; acc[3][2] += av.w*bv.z; acc[3][3] += av.w*bv.w;
        }
        __syncthreads();
    }
    #pragma unroll
    for (int i = 0; i < 4; i++) {
        int r = rowBase + ty*4 + i;
        #pragma unroll
        for (int j = 0; j < 4; j++) {
            int cc = colBase + tx*4 + j;
            float v = acc[i][j] + bias[cc];
            if (relu) v = fmaxf(v, 0.0f);
            if (resid) v += resid[(size_t)r * N + cc];
            C[(size_t)r * N + cc] = v;
        }
    }
}

// ---------------- batched NT GEMM for attention scores + cosine bias -------
__global__ void gemm_scores(const float* __restrict__ Q, const float* __restrict__ Km,
                            const float* __restrict__ beta, int layer,
                            float* __restrict__ Sc) {
    __shared__ float As[16][64];
    __shared__ float Bs[16][64];
    int bb = blockIdx.z;
    const float* A = Q  + (size_t)bb * S * D;
    const float* W = Km + (size_t)bb * S * D;
    int tid = threadIdx.x;
    int tx = tid & 15, ty = tid >> 4;
    int rowBase = blockIdx.y * 64, colBase = blockIdx.x * 64;

    int lr = tid >> 2;
    int lc = (tid & 3) * 4;
    const float* Ap = A + (size_t)(rowBase + lr) * D + lc;
    const float* Wp = W + (size_t)(colBase + lr) * D + lc;

    float acc[4][4] = {};
    for (int k0 = 0; k0 < D; k0 += 16) {
        float4 a = *(const float4*)(Ap + k0);
        float4 w4 = *(const float4*)(Wp + k0);
        As[lc+0][lr] = a.x;  As[lc+1][lr] = a.y;  As[lc+2][lr] = a.z;  As[lc+3][lr] = a.w;
        Bs[lc+0][lr] = w4.x; Bs[lc+1][lr] = w4.y; Bs[lc+2][lr] = w4.z; Bs[lc+3][lr] = w4.w;
        __syncthreads();
        #pragma unroll
        for (int k = 0; k < 16; k++) {
            float4 av = *(const float4*)&As[k][ty*4];
            float4 bv = *(const float4*)&Bs[k][tx*4];
            acc[0][0] += av.x*bv.x; acc[0][1] += av.x*bv.y; acc[0][2] += av.x*bv.z; acc[0][3] += av.x*bv.w;
            acc[1][0] += av.y*bv.x; acc[1][1] += av.y*bv.y; acc[1][2] += av.y*bv.z; acc[1][3] += av.y*bv.w;
            acc[2][0] += av.z*bv.x; acc[2][1] += av.z*bv.y; acc[2][2] += av.z*bv.z; acc[2][3] += av.z*bv.w;
            acc[3][0] += av.w*bv.x; acc[3][1] += av.w*bv.y; acc[3][2] += av.w*bv.z; acc[3][3] += av.w*bv.w;
        }
        __syncthreads();
    }
    const float scale = 0.044194173824159216f;  // 1/sqrt(512)
    float b0 = beta[layer*2 + 0];
    float b1 = beta[layer*2 + 1];
    const float w0 = 6.283185307179586f / 24.0f;
    const float w1 = 6.283185307179586f / 720.0f;
    float* Cb = Sc + (size_t)bb * S * S;
    #pragma unroll
    for (int i = 0; i < 4; i++) {
        int r = rowBase + ty*4 + i;
        #pragma unroll
        for (int j = 0; j < 4; j++) {
            int cc = colBase + tx*4 + j;
            float dist = fabsf((float)(r - cc));
            float v = acc[i][j] * scale + b0 * cosf(dist * w0) + b1 * cosf(dist * w1);
            Cb[(size_t)r * S + cc] = v;
        }
    }
}

// ---------------- batched NN GEMM: att_out = P @ V --------------------------
__global__ void gemm_nn_pv(const float* __restrict__ P, const float* __restrict__ V,
                           float* __restrict__ C) {
    __shared__ float As[16][64];
    __shared__ float Bs[16][64];
    int bb = blockIdx.z;
    const float* A  = P + (size_t)bb * S * S;   // [S, S]
    const float* Bm = V + (size_t)bb * S * D;   // [S, D]
    int tid = threadIdx.x;
    int tx = tid & 15, ty = tid >> 4;
    int rowBase = blockIdx.y * 64, colBase = blockIdx.x * 64;

    int lr  = tid >> 2;
    int lc  = (tid & 3) * 4;
    int kr  = tid >> 4;           // 0..15
    int nc  = (tid & 15) * 4;     // 0..60
    const float* Ap = A + (size_t)(rowBase + lr) * S + lc;

    float acc[4][4] = {};
    for (int k0 = 0; k0 < S; k0 += 16) {
        float4 a = *(const float4*)(Ap + k0);
        float4 b4 = *(const float4*)(Bm + (size_t)(k0 + kr) * D + colBase + nc);
        As[lc+0][lr] = a.x; As[lc+1][lr] = a.y; As[lc+2][lr] = a.z; As[lc+3][lr] = a.w;
        *(float4*)&Bs[kr][nc] = b4;
        __syncthreads();
        #pragma unroll
        for (int k = 0; k < 16; k++) {
            float4 av = *(const float4*)&As[k][ty*4];
            float4 bv = *(const float4*)&Bs[k][tx*4];
            acc[0][0] += av.x*bv.x; acc[0][1] += av.x*bv.y; acc[0][2] += av.x*bv.z; acc[0][3] += av.x*bv.w;
            acc[1][0] += av.y*bv.x; acc[1][1] += av.y*bv.y; acc[1][2] += av.y*bv.z; acc[1][3] += av.y*bv.w;
            acc[2][0] += av.z*bv.x; acc[2][1] += av.z*bv.y; acc[2][2] += av.z*bv.z; acc[2][3] += av.z*bv.w;
            acc[3][0] += av.w*bv.x; acc[3][1] += av.w*bv.y; acc[3][2] += av.w*bv.z; acc[3][3] += av.w*bv.w;
        }
        __syncthreads();
    }
    float* Cb = C + (size_t)bb * S * D;
    #pragma unroll
    for (int i = 0; i < 4; i++) {
        int r = rowBase + ty*4 + i;
        #pragma unroll
        for (int j = 0; j < 4; j++) {
            int cc = colBase + tx*4 + j;
            Cb[(size_t)r * D + cc] = acc[i][j];
        }
    }
}

// ---------------- softmax over rows of length S ----------------------------
__global__ void softmax_kernel(float* __restrict__ Sc) {
    int row = blockIdx.x;                // B*S rows
    float* p = Sc + (size_t)row * S;
    int t = threadIdx.x;                 // 256 threads x 8 elems
    float v[8];
    float m = -1e30f;
    #pragma unroll
    for (int i = 0; i < 8; i++) { v[i] = p[t + i*256]; m = fmaxf(m, v[i]); }
    #pragma unroll
    for (int o = 16; o; o >>= 1) m = fmaxf(m, __shfl_xor_sync(0xffffffffu, m, o));
    __shared__ float shm[8], shs[8];
    int wid = t >> 5, lid = t & 31;
    if (lid == 0) shm[wid] = m;
    __syncthreads();
    float mm = -1e30f;
    #pragma unroll
    for (int i = 0; i < 8; i++) mm = fmaxf(mm, shm[i]);
    float s = 0.f;
    #pragma unroll
    for (int i = 0; i < 8; i++) { v[i] = __expf(v[i] - mm); s += v[i]; }
    #pragma unroll
    for (int o = 16; o; o >>= 1) s += __shfl_xor_sync(0xffffffffu, s, o);
    if (lid == 0) shs[wid] = s;
    __syncthreads();
    float ts = 0.f;
    #pragma unroll
    for (int i = 0; i < 8; i++) ts += shs[i];
    float inv = 1.0f / ts;
    #pragma unroll
    for (int i = 0; i < 8; i++) p[t + i*256] = v[i] * inv;
}

// ---------------- final projection D -> 1 ----------------------------------
__global__ void out_kernel(const float* __restrict__ x, const float* __restrict__ ow,
                           const float* __restrict__ ob, float* __restrict__ out) {
    int row = blockIdx.x;
    const float* p = x + (size_t)row * D;
    int t = threadIdx.x;
    float s = p[t] * ow[t] + p[t + 256] * ow[t + 256];
    #pragma unroll
    for (int o = 16; o; o >>= 1) s += __shfl_xor_sync(0xffffffffu, s, o);
    __shared__ float sh[8];
    int wid = t >> 5, lid = t & 31;
    if (lid == 0) sh[wid] = s;
    __syncthreads();
    if (t == 0) {
        float ts = 0.f;
        #pragma unroll
        for (int i = 0; i < 8; i++) ts += sh[i];
        out[row] = ts + ob[0];
    }
}

// ---------------------------------------------------------------------------
extern "C" void kernel_launch(void* const* d_in, const int* in_sizes, int n_in,
                              void* d_out, int out_size) {
    const float* z     = (const float*)d_in[0];
    const float* c     = (const float*)d_in[1];
    const float* enc_w = (const float*)d_in[2];
    const float* enc_b = (const float*)d_in[3];
    const float* beta  = (const float*)d_in[4];
    const float* wq    = (const float*)d_in[5];
    const float* bq    = (const float*)d_in[6];
    const float* wk    = (const float*)d_in[7];
    const float* bk    = (const float*)d_in[8];
    const float* wv    = (const float*)d_in[9];
    const float* bv    = (const float*)d_in[10];
    const float* ln1w  = (const float*)d_in[11];
    const float* ln1b  = (const float*)d_in[12];
    const float* ln2w  = (const float*)d_in[13];
    const float* ln2b  = (const float*)d_in[14];
    const float* ff1w  = (const float*)d_in[15];
    const float* ff1b  = (const float*)d_in[16];
    const float* ff2w  = (const float*)d_in[17];
    const float* ff2b  = (const float*)d_in[18];
    const float* outw  = (const float*)d_in[19];
    const float* outb  = (const float*)d_in[20];
    float* out = (float*)d_out;

    float *px, *pxn, *pq, *pk, *pv, *patt, *psc, *ph;
    cudaGetSymbolAddress((void**)&px,   g_x);
    cudaGetSymbolAddress((void**)&pxn,  g_xn);
    cudaGetSymbolAddress((void**)&pq,   g_q);
    cudaGetSymbolAddress((void**)&pk,   g_k);
    cudaGetSymbolAddress((void**)&pv,   g_v);
    cudaGetSymbolAddress((void**)&patt, g_att);
    cudaGetSymbolAddress((void**)&psc,  g_sc);
    cudaGetSymbolAddress((void**)&ph,   g_h);

    // encoder + positional encoding
    {
        int total = ROWS * D;
        encoder_kernel<<<(total + 255) / 256, 256>>>(z, c, enc_w, enc_b, px);
    }

    for (int l = 0; l < NL; l++) {
        const float* l1w = ln1w + l * D;
        const float* l1b = ln1b + l * D;
        const float* l2w = ln2w + l * D;
        const float* l2b = ln2b + l * D;

        // pre-norm
        ln_kernel<<<ROWS, 256>>>(px, nullptr, l1w, l1b, pxn);

        // QKV projections
        dim3 gqkv(D / 64, ROWS / 64);
        gemm_nt<<<gqkv, 256>>>(pxn, wq + (size_t)l * D * D, bq + l * D, nullptr, pq, ROWS, D, D, 0);
        gemm_nt<<<gqkv, 256>>>(pxn, wk + (size_t)l * D * D, bk + l * D, nullptr, pk, ROWS, D, D, 0);
        gemm_nt<<<gqkv, 256>>>(pxn, wv + (size_t)l * D * D, bv + l * D, nullptr, pv, ROWS, D, D, 0);

        // attention scores + cosine bias
        dim3 gsc(S / 64, S / 64, B);
        gemm_scores<<<gsc, 256>>>(pq, pk, beta, l, psc);

        // softmax
        softmax_kernel<<<B * S, 256>>>(psc);

        // P @ V
        dim3 gpv(D / 64, S / 64, B);
        gemm_nn_pv<<<gpv, 256>>>(psc, pv, patt);

        // x = LN(x + att_out) with ln1 (reference applies ln1 twice)
        ln_kernel<<<ROWS, 256>>>(px, patt, l1w, l1b, px);

        // xn2 = LN(x) with ln2
        ln_kernel<<<ROWS, 256>>>(px, nullptr, l2w, l2b, pxn);

        // FF1 + relu
        dim3 gff1(FF / 64, ROWS / 64);
        gemm_nt<<<gff1, 256>>>(pxn, ff1w + (size_t)l * FF * D, ff1b + l * FF, nullptr, ph, ROWS, FF, D, 1);

        // FF2 + residual
        dim3 gff2(D / 64, ROWS / 64);
        gemm_nt<<<gff2, 256>>>(ph, ff2w + (size_t)l * D * FF, ff2b + l * D, px, px, ROWS, D, FF, 0);
    }

    // final projection to ODIM=1
    out_kernel<<<ROWS, 256>>>(px, outw, outb, out);
}

// round 2
// speedup vs baseline: 2.8302x; 2.8302x over previous
#include <cuda_runtime.h>
#include <math.h>

#define NL 6
#define D 512
#define S 2048
#define B 8
#define FF 2048
#define ROWS 16384

#define BM 128
#define BN 128
#define BK 16
#define ASTR (BK + 4)     // 20 floats  -> conflict-free A-frag loads
#define BSTR (BN + 8)     // 136 floats -> conflict-free B-frag loads

// ---------------- scratch (device globals: allocation-free) ----------------
__device__ float g_x  [ROWS*(size_t)D];
__device__ float g_xn [ROWS*(size_t)D];
__device__ float g_q  [ROWS*(size_t)D];
__device__ float g_k  [ROWS*(size_t)D];
__device__ float g_v  [ROWS*(size_t)D];
__device__ float g_att[ROWS*(size_t)D];
__device__ float g_sc [(size_t)B*S*S];
__device__ float g_h  [ROWS*(size_t)FF];
__device__ float g_bt [NL*S];             // per-layer cosine bias table

// ---------------- helpers ---------------------------------------------------
__device__ __forceinline__ float tf32r(float x) {
    unsigned u;
    asm("cvt.rna.tf32.f32 %0, %1;" : "=r"(u) : "f"(x));
    return __uint_as_float(u);
}

__device__ __forceinline__ void mma_tf32(float* c, const unsigned* a, const unsigned* b) {
    asm volatile(
        "mma.sync.aligned.m16n8k8.row.col.f32.tf32.tf32.f32 "
        "{%0,%1,%2,%3}, {%4,%5,%6,%7}, {%8,%9}, {%0,%1,%2,%3};\n"
        : "+f"(c[0]), "+f"(c[1]), "+f"(c[2]), "+f"(c[3])
        : "r"(a[0]), "r"(a[1]), "r"(a[2]), "r"(a[3]), "r"(b[0]), "r"(b[1]));
}

// ---------------- tensor-core GEMM ------------------------------------------
// C[M,N] = A[M,K] @ B  where B is W[N,K] (TRANSB=true, "NT") or B[K,N] (false, "NN")
// EPI: 0=bias  1=bias+relu  2=bias+resid  3=scores(scale+table)  4=plain
template<int EPI, bool TRANSB>
__global__ void __launch_bounds__(256) mma_gemm(
    const float* __restrict__ A, const float* __restrict__ Bg,
    const float* __restrict__ bias, const float* __restrict__ resid,
    float* __restrict__ C, int M, int N, int K,
    size_t batchA, size_t batchB, size_t batchC,
    const float* __restrict__ table)
{
    __shared__ float As[2][BM][ASTR];
    __shared__ float Bs[2][BK][BSTR];

    const int bz = blockIdx.z;
    A  += (size_t)bz * batchA;
    Bg += (size_t)bz * batchB;
    C  += (size_t)bz * batchC;

    const int tid  = threadIdx.x;
    const int wid  = tid >> 5;
    const int lane = tid & 31;
    const int g    = lane >> 2;
    const int tg   = lane & 3;
    const int wm   = wid >> 2;          // 0..1  (64-row slab)
    const int wn   = wid & 3;           // 0..3  (32-col slab)
    const int rowBase = blockIdx.y * BM;
    const int colBase = blockIdx.x * BN;
    const int m0 = wm * 64;
    const int n0 = wn * 32;

    // gmem load assignments (256 threads)
    const int aRow = tid >> 2;            // 0..63  (+64 for second load)
    const int aCol = (tid & 3) << 2;      // 0,4,8,12
    const int bRowT = tid >> 2;           // NT: W row (n), 0..63 (+64)
    const int bColT = (tid & 3) << 2;     // NT: k sub-col
    const int bRowN = tid >> 5;           // NN: k row, 0..7 (+8)
    const int bColN = (tid & 31) << 2;    // NN: n sub-col, 0..124

    float4 la0, la1, lb0, lb1;
    float acc[4][4][4] = {};

    const int nk = K / BK;

    // ---- prologue: load tile 0 ----
    la0 = *(const float4*)(A + (size_t)(rowBase + aRow)      * K + aCol);
    la1 = *(const float4*)(A + (size_t)(rowBase + aRow + 64) * K + aCol);
    if (TRANSB) {
        lb0 = *(const float4*)(Bg + (size_t)(colBase + bRowT)      * K + bColT);
        lb1 = *(const float4*)(Bg + (size_t)(colBase + bRowT + 64) * K + bColT);
    } else {
        lb0 = *(const float4*)(Bg + (size_t)(bRowN)     * N + colBase + bColN);
        lb1 = *(const float4*)(Bg + (size_t)(bRowN + 8) * N + colBase + bColN);
    }
    {
        float* p = &As[0][aRow][aCol];
        p[0]=tf32r(la0.x); p[1]=tf32r(la0.y); p[2]=tf32r(la0.z); p[3]=tf32r(la0.w);
        float* q = &As[0][aRow+64][aCol];
        q[0]=tf32r(la1.x); q[1]=tf32r(la1.y); q[2]=tf32r(la1.z); q[3]=tf32r(la1.w);
        if (TRANSB) {
            Bs[0][bColT+0][bRowT] = tf32r(lb0.x);
            Bs[0][bColT+1][bRowT] = tf32r(lb0.y);
            Bs[0][bColT+2][bRowT] = tf32r(lb0.z);
            Bs[0][bColT+3][bRowT] = tf32r(lb0.w);
            Bs[0][bColT+0][bRowT+64] = tf32r(lb1.x);
            Bs[0][bColT+1][bRowT+64] = tf32r(lb1.y);
            Bs[0][bColT+2][bRowT+64] = tf32r(lb1.z);
            Bs[0][bColT+3][bRowT+64] = tf32r(lb1.w);
        } else {
            float* r = &Bs[0][bRowN][bColN];
            r[0]=tf32r(lb0.x); r[1]=tf32r(lb0.y); r[2]=tf32r(lb0.z); r[3]=tf32r(lb0.w);
            float* s = &Bs[0][bRowN+8][bColN];
            s[0]=tf32r(lb1.x); s[1]=tf32r(lb1.y); s[2]=tf32r(lb1.z); s[3]=tf32r(lb1.w);
        }
    }
    __syncthreads();

    for (int i = 0; i < nk; i++) {
        const int cur = i & 1;
        const bool more = (i + 1 < nk);
        if (more) {
            const int k0 = (i + 1) * BK;
            la0 = *(const float4*)(A + (size_t)(rowBase + aRow)      * K + k0 + aCol);
            la1 = *(const float4*)(A + (size_t)(rowBase + aRow + 64) * K + k0 + aCol);
            if (TRANSB) {
                lb0 = *(const float4*)(Bg + (size_t)(colBase + bRowT)      * K + k0 + bColT);
                lb1 = *(const float4*)(Bg + (size_t)(colBase + bRowT + 64) * K + k0 + bColT);
            } else {
                lb0 = *(const float4*)(Bg + (size_t)(k0 + bRowN)     * N + colBase + bColN);
                lb1 = *(const float4*)(Bg + (size_t)(k0 + bRowN + 8) * N + colBase + bColN);
            }
        }

        const float* abase = &As[cur][0][0];
        const float* bbase = &Bs[cur][0][0];
        #pragma unroll
        for (int ks = 0; ks < 2; ks++) {
            unsigned af[4][4];
            unsigned bf[4][2];
            #pragma unroll
            for (int mt = 0; mt < 4; mt++) {
                const float* ap = abase + (size_t)(m0 + mt*16) * ASTR + ks*8;
                af[mt][0] = __float_as_uint(ap[(g    ) * ASTR + tg    ]);
                af[mt][1] = __float_as_uint(ap[(g + 8) * ASTR + tg    ]);
                af[mt][2] = __float_as_uint(ap[(g    ) * ASTR + tg + 4]);
                af[mt][3] = __float_as_uint(ap[(g + 8) * ASTR + tg + 4]);
            }
            #pragma unroll
            for (int nt = 0; nt < 4; nt++) {
                const float* bp = bbase + (size_t)(ks*8) * BSTR + n0 + nt*8;
                bf[nt][0] = __float_as_uint(bp[(tg    ) * BSTR + g]);
                bf[nt][1] = __float_as_uint(bp[(tg + 4) * BSTR + g]);
            }
            #pragma unroll
            for (int mt = 0; mt < 4; mt++)
                #pragma unroll
                for (int nt = 0; nt < 4; nt++)
                    mma_tf32(acc[mt][nt], af[mt], bf[nt]);
        }

        if (more) {
            const int nxt = (i + 1) & 1;
            float* p = &As[nxt][aRow][aCol];
            p[0]=tf32r(la0.x); p[1]=tf32r(la0.y); p[2]=tf32r(la0.z); p[3]=tf32r(la0.w);
            float* q = &As[nxt][aRow+64][aCol];
            q[0]=tf32r(la1.x); q[1]=tf32r(la1.y); q[2]=tf32r(la1.z); q[3]=tf32r(la1.w);
            if (TRANSB) {
                Bs[nxt][bColT+0][bRowT] = tf32r(lb0.x);
                Bs[nxt][bColT+1][bRowT] = tf32r(lb0.y);
                Bs[nxt][bColT+2][bRowT] = tf32r(lb0.z);
                Bs[nxt][bColT+3][bRowT] = tf32r(lb0.w);
                Bs[nxt][bColT+0][bRowT+64] = tf32r(lb1.x);
                Bs[nxt][bColT+1][bRowT+64] = tf32r(lb1.y);
                Bs[nxt][bColT+2][bRowT+64] = tf32r(lb1.z);
                Bs[nxt][bColT+3][bRowT+64] = tf32r(lb1.w);
            } else {
                float* r = &Bs[nxt][bRowN][bColN];
                r[0]=tf32r(lb0.x); r[1]=tf32r(lb0.y); r[2]=tf32r(lb0.z); r[3]=tf32r(lb0.w);
                float* s = &Bs[nxt][bRowN+8][bColN];
                s[0]=tf32r(lb1.x); s[1]=tf32r(lb1.y); s[2]=tf32r(lb1.z); s[3]=tf32r(lb1.w);
            }
            __syncthreads();
        }
    }

    // ---- epilogue ----
    const float scale = 0.044194173824159216f;   // 1/sqrt(512)
    #pragma unroll
    for (int mt = 0; mt < 4; mt++) {
        #pragma unroll
        for (int nt = 0; nt < 4; nt++) {
            const float* c = acc[mt][nt];
            int r0 = rowBase + m0 + mt*16 + g;
            int cb = colBase + n0 + nt*8 + tg*2;
            #pragma unroll
            for (int half = 0; half < 2; half++) {
                int r = r0 + half*8;
                float v0 = c[half*2 + 0];
                float v1 = c[half*2 + 1];
                if (EPI == 0 || EPI == 1 || EPI == 2) {
                    v0 += bias[cb];
                    v1 += bias[cb + 1];
                    if (EPI == 1) { v0 = fmaxf(v0, 0.f); v1 = fmaxf(v1, 0.f); }
                    if (EPI == 2) {
                        v0 += resid[(size_t)r * N + cb];
                        v1 += resid[(size_t)r * N + cb + 1];
                    }
                } else if (EPI == 3) {
                    v0 = v0 * scale + table[abs(r - cb)];
                    v1 = v1 * scale + table[abs(r - cb - 1)];
                }
                *(float2*)(C + (size_t)r * N + cb) = make_float2(v0, v1);
            }
        }
    }
}

// ---------------- cosine bias table -----------------------------------------
__global__ void bias_table_kernel(const float* __restrict__ beta, float* __restrict__ bt) {
    int i = blockIdx.x * blockDim.x + threadIdx.x;
    if (i >= NL * S) return;
    int l = i / S;
    float d = (float)(i % S);
    bt[i] = beta[l*2 + 0] * cosf(6.283185307179586f * d / 24.0f)
          + beta[l*2 + 1] * cosf(6.283185307179586f * d / 720.0f);
}

// ---------------- encoder: cat(z,c)@W^T + b + posenc ------------------------
__global__ void encoder_kernel(const float* __restrict__ z, const float* __restrict__ c,
                               const float* __restrict__ ew, const float* __restrict__ eb,
                               float* __restrict__ x) {
    int i = blockIdx.x * blockDim.x + threadIdx.x;
    if (i >= ROWS * D) return;
    int d  = i % D;
    int bs = i / D;
    int s  = bs % S;
    float val = z[bs] * ew[d*2+0] + c[bs] * ew[d*2+1] + eb[d];
    int k2 = d & ~1;
    float div = expf(-(float)k2 * (logf(10000.0f) / (float)D));
    float ang = (float)s * div;
    val += (d & 1) ? cosf(ang) : sinf(ang);
    x[i] = val;
}

// ---------------- layernorm (optional residual), row length D=512 -----------
__global__ void ln_kernel(const float* __restrict__ in, const float* __restrict__ res,
                          const float* __restrict__ w, const float* __restrict__ b,
                          float* __restrict__ out) {
    int row = blockIdx.x;
    const float* ip = in + (size_t)row * D;
    int t = threadIdx.x;
    float v0 = ip[t];
    float v1 = ip[t + 256];
    if (res) {
        const float* rp = res + (size_t)row * D;
        v0 += rp[t];
        v1 += rp[t + 256];
    }
    float s = v0 + v1, ss = v0*v0 + v1*v1;
    #pragma unroll
    for (int o = 16; o; o >>= 1) {
        s  += __shfl_xor_sync(0xffffffffu, s,  o);
        ss += __shfl_xor_sync(0xffffffffu, ss, o);
    }
    __shared__ float sh_s[8], sh_ss[8];
    int wid = t >> 5, lid = t & 31;
    if (lid == 0) { sh_s[wid] = s; sh_ss[wid] = ss; }
    __syncthreads();
    float ts = 0.f, tss = 0.f;
    #pragma unroll
    for (int i = 0; i < 8; i++) { ts += sh_s[i]; tss += sh_ss[i]; }
    float mean = ts * (1.0f / D);
    float var  = tss * (1.0f / D) - mean * mean;
    float rstd = rsqrtf(var + 1e-5f);
    float* op = out + (size_t)row * D;
    op[t]       = (v0 - mean) * rstd * w[t]       + b[t];
    op[t + 256] = (v1 - mean) * rstd * w[t + 256] + b[t + 256];
}

// ---------------- softmax over rows of length S ------------------------------
__global__ void softmax_kernel(float* __restrict__ Sc) {
    int row = blockIdx.x;
    float* p = Sc + (size_t)row * S;
    int t = threadIdx.x;
    float v[8];
    float m = -1e30f;
    #pragma unroll
    for (int i = 0; i < 8; i++) { v[i] = p[t + i*256]; m = fmaxf(m, v[i]); }
    #pragma unroll
    for (int o = 16; o; o >>= 1) m = fmaxf(m, __shfl_xor_sync(0xffffffffu, m, o));
    __shared__ float shm[8], shs[8];
    int wid = t >> 5, lid = t & 31;
    if (lid == 0) shm[wid] = m;
    __syncthreads();
    float mm = -1e30f;
    #pragma unroll
    for (int i = 0; i < 8; i++) mm = fmaxf(mm, shm[i]);
    float s = 0.f;
    #pragma unroll
    for (int i = 0; i < 8; i++) { v[i] = __expf(v[i] - mm); s += v[i]; }
    #pragma unroll
    for (int o = 16; o; o >>= 1) s += __shfl_xor_sync(0xffffffffu, s, o);
    if (lid == 0) shs[wid] = s;
    __syncthreads();
    float ts = 0.f;
    #pragma unroll
    for (int i = 0; i < 8; i++) ts += shs[i];
    float inv = 1.0f / ts;
    #pragma unroll
    for (int i = 0; i < 8; i++) p[t + i*256] = v[i] * inv;
}

// ---------------- final projection D -> 1 ------------------------------------
__global__ void out_kernel(const float* __restrict__ x, const float* __restrict__ ow,
                           const float* __restrict__ ob, float* __restrict__ out) {
    int row = blockIdx.x;
    const float* p = x + (size_t)row * D;
    int t = threadIdx.x;
    float s = p[t] * ow[t] + p[t + 256] * ow[t + 256];
    #pragma unroll
    for (int o = 16; o; o >>= 1) s += __shfl_xor_sync(0xffffffffu, s, o);
    __shared__ float sh[8];
    int wid = t >> 5, lid = t & 31;
    if (lid == 0) sh[wid] = s;
    __syncthreads();
    if (t == 0) {
        float ts = 0.f;
        #pragma unroll
        for (int i = 0; i < 8; i++) ts += sh[i];
        out[row] = ts + ob[0];
    }
}

// ---------------------------------------------------------------------------
extern "C" void kernel_launch(void* const* d_in, const int* in_sizes, int n_in,
                              void* d_out, int out_size) {
    const float* z     = (const float*)d_in[0];
    const float* c     = (const float*)d_in[1];
    const float* enc_w = (const float*)d_in[2];
    const float* enc_b = (const float*)d_in[3];
    const float* beta  = (const float*)d_in[4];
    const float* wq    = (const float*)d_in[5];
    const float* bq    = (const float*)d_in[6];
    const float* wk    = (const float*)d_in[7];
    const float* bk    = (const float*)d_in[8];
    const float* wv    = (const float*)d_in[9];
    const float* bv    = (const float*)d_in[10];
    const float* ln1w  = (const float*)d_in[11];
    const float* ln1b  = (const float*)d_in[12];
    const float* ln2w  = (const float*)d_in[13];
    const float* ln2b  = (const float*)d_in[14];
    const float* ff1w  = (const float*)d_in[15];
    const float* ff1b  = (const float*)d_in[16];
    const float* ff2w  = (const float*)d_in[17];
    const float* ff2b  = (const float*)d_in[18];
    const float* outw  = (const float*)d_in[19];
    const float* outb  = (const float*)d_in[20];
    float* out = (float*)d_out;

    float *px, *pxn, *pq, *pk, *pv, *patt, *psc, *ph, *pbt;
    cudaGetSymbolAddress((void**)&px,   g_x);
    cudaGetSymbolAddress((void**)&pxn,  g_xn);
    cudaGetSymbolAddress((void**)&pq,   g_q);
    cudaGetSymbolAddress((void**)&pk,   g_k);
    cudaGetSymbolAddress((void**)&pv,   g_v);
    cudaGetSymbolAddress((void**)&patt, g_att);
    cudaGetSymbolAddress((void**)&psc,  g_sc);
    cudaGetSymbolAddress((void**)&ph,   g_h);
    cudaGetSymbolAddress((void**)&pbt,  g_bt);

    bias_table_kernel<<<(NL*S + 255)/256, 256>>>(beta, pbt);
    encoder_kernel<<<(ROWS*D + 255)/256, 256>>>(z, c, enc_w, enc_b, px);

    for (int l = 0; l < NL; l++) {
        const float* l1w = ln1w + l * D;
        const float* l1b = ln1b + l * D;
        const float* l2w = ln2w + l * D;
        const float* l2b = ln2b + l * D;

        // pre-norm
        ln_kernel<<<ROWS, 256>>>(px, nullptr, l1w, l1b, pxn);

        // QKV projections (tensor core, NT)
        dim3 gqkv(D / BN, ROWS / BM);
        mma_gemm<0, true><<<gqkv, 256>>>(pxn, wq + (size_t)l*D*D, bq + l*D, nullptr,
                                         pq, ROWS, D, D, 0, 0, 0, nullptr);
        mma_gemm<0, true><<<gqkv, 256>>>(pxn, wk + (size_t)l*D*D, bk + l*D, nullptr,
                                         pk, ROWS, D, D, 0, 0, 0, nullptr);
        mma_gemm<0, true><<<gqkv, 256>>>(pxn, wv + (size_t)l*D*D, bv + l*D, nullptr,
                                         pv, ROWS, D, D, 0, 0, 0, nullptr);

        // attention scores + cosine bias (batched NT)
        dim3 gsc(S / BN, S / BM, B);
        mma_gemm<3, true><<<gsc, 256>>>(pq, pk, nullptr, nullptr, psc,
                                        S, S, D,
                                        (size_t)S*D, (size_t)S*D, (size_t)S*S,
                                        pbt + (size_t)l*S);

        // softmax
        softmax_kernel<<<B * S, 256>>>(psc);

        // P @ V (batched NN)
        dim3 gpv(D / BN, S / BM, B);
        mma_gemm<4, false><<<gpv, 256>>>(psc, pv, nullptr, nullptr, patt,
                                         S, D, S,
                                         (size_t)S*S, (size_t)S*D, (size_t)S*D,
                                         nullptr);

        // x = LN(x + att_out) with ln1
        ln_kernel<<<ROWS, 256>>>(px, patt, l1w, l1b, px);
        // xn2 = LN(x) with ln2
        ln_kernel<<<ROWS, 256>>>(px, nullptr, l2w, l2b, pxn);

        // FF1 + relu
        dim3 gff1(FF / BN, ROWS / BM);
        mma_gemm<1, true><<<gff1, 256>>>(pxn, ff1w + (size_t)l*FF*D, ff1b + l*FF, nullptr,
                                         ph, ROWS, FF, D, 0, 0, 0, nullptr);

        // FF2 + residual (in-place on x)
        dim3 gff2(D / BN, ROWS / BM);
        mma_gemm<2, true><<<gff2, 256>>>(ph, ff2w + (size_t)l*D*FF, ff2b + l*D, px,
                                         px, ROWS, D, FF, 0, 0, 0, nullptr);
    }

    out_kernel<<<ROWS, 256>>>(px, outw, outb, out);
}

// round 6
// speedup vs baseline: 3.5053x; 1.2386x over previous
#include <cuda_runtime.h>
#include <math.h>
#include <stdint.h>

#define NL 6
#define D 512
#define S 2048
#define B 8
#define FF 2048
#define ROWS 16384

// GEMM tiling
#define BM 128
#define BN 256
#define BK 16
#define RSTR 20                       // row stride in floats (conflict-free, 80B = 16B-aligned)
#define A_FLOATS (BM*RSTR)            // 2560
#define B_FLOATS (BN*RSTR)            // 5120
#define STAGE_FLOATS (A_FLOATS+B_FLOATS)  // 7680
#define NSTAGE 3
#define DYN_SMEM (NSTAGE*STAGE_FLOATS*4)  // 92160 bytes

// ---------------- scratch (device globals: allocation-free) ----------------
__device__ float g_x  [ROWS*(size_t)D];
__device__ float g_xn [ROWS*(size_t)D];
__device__ float g_q  [ROWS*(size_t)D];
__device__ float g_k  [ROWS*(size_t)D];
__device__ float g_v  [ROWS*(size_t)D];
__device__ float g_vt [ROWS*(size_t)D];
__device__ float g_att[ROWS*(size_t)D];
__device__ float g_sc [(size_t)B*S*S];
__device__ float g_h  [ROWS*(size_t)FF];
__device__ float g_bt [NL*S];
__device__ float g_wr [17301504];    // rounded weights: wq|wk|wv|ff1|ff2

// ---------------- helpers ---------------------------------------------------
__device__ __forceinline__ uint32_t smem_u32(const void* p) {
    uint32_t a;
    asm("{ .reg .u64 t; cvta.to.shared.u64 t, %1; cvt.u32.u64 %0, t; }"
        : "=r"(a) : "l"(p));
    return a;
}

__device__ __forceinline__ float tf32r(float x) {
    unsigned u;
    asm("cvt.rna.tf32.f32 %0, %1;" : "=r"(u) : "f"(x));
    return __uint_as_float(u);
}

__device__ __forceinline__ void mma_tf32(float* c, const unsigned* a, const unsigned* b) {
    asm volatile(
        "mma.sync.aligned.m16n8k8.row.col.f32.tf32.tf32.f32 "
        "{%0,%1,%2,%3}, {%4,%5,%6,%7}, {%8,%9}, {%0,%1,%2,%3};\n"
        : "+f"(c[0]), "+f"(c[1]), "+f"(c[2]), "+f"(c[3])
        : "r"(a[0]), "r"(a[1]), "r"(a[2]), "r"(a[3]), "r"(b[0]), "r"(b[1]));
}

__device__ __forceinline__ void cp16(uint32_t dst, const float* src) {
    asm volatile("cp.async.cg.shared.global [%0], [%1], 16;"
        :: "r"(dst), "l"(__cvta_generic_to_global((const void*)src)) : "memory");
}

// Load one BK=16 chunk (A: 128 rows, B: 256 rows, both K-major) into stage.
__device__ __forceinline__ void load_chunk(const float* __restrict__ Ag,
                                           const float* __restrict__ Bg, int K,
                                           int j, uint32_t smbase, int tid) {
    const uint32_t st = smbase + (uint32_t)(j % NSTAGE) * (STAGE_FLOATS * 4);
    const float* asrc = Ag + (size_t)j * BK;
    #pragma unroll
    for (int u = 0; u < 2; u++) {
        int idx = tid + u * 256;          // 0..511
        int row = idx >> 2, c4 = idx & 3; // row 0..127, 4-float group
        cp16(st + row * (RSTR*4) + c4 * 16, asrc + (size_t)row * K + c4 * 4);
    }
    const float* bsrc = Bg + (size_t)j * BK;
    const uint32_t stb = st + A_FLOATS * 4;
    #pragma unroll
    for (int u = 0; u < 4; u++) {
        int idx = tid + u * 256;          // 0..1023
        int row = idx >> 2, c4 = idx & 3; // row 0..255
        cp16(stb + row * (RSTR*4) + c4 * 16, bsrc + (size_t)row * K + c4 * 4);
    }
    asm volatile("cp.async.commit_group;" ::: "memory");
}

// ---------------- tensor-core GEMM (mma.sync tf32) ---------------------------
// C[M,N] = A[M,K] @ Bm[N,K]^T   (both operands K-major, pre-rounded to tf32)
// EPI: 0=bias  1=bias+relu  2=bias+resid  3=scores(scale+table)  4=plain
template<int EPI, bool RND>
__global__ void __launch_bounds__(256, 1) mma_gemm(
    const float* __restrict__ A, const float* __restrict__ Bm,
    const float* __restrict__ bias, const float* __restrict__ resid,
    float* __restrict__ C, int N, int K,
    size_t sA, size_t sB, size_t sC, const float* __restrict__ table)
{
    extern __shared__ float sm[];
    const uint32_t smbase = smem_u32(sm);

    const int tid  = threadIdx.x;
    const int wid  = tid >> 5;
    const int lane = tid & 31;
    const int g    = lane >> 2;   // 0..7
    const int tg   = lane & 3;    // 0..3
    const int wm   = wid >> 2;    // 0..1  : 64-row slab
    const int wn   = wid & 3;     // 0..3  : 64-col slab
    const int m0   = wm * 64;
    const int n0   = wn * 64;

    A  += (size_t)blockIdx.z * sA;
    Bm += (size_t)blockIdx.z * sB;
    C  += (size_t)blockIdx.z * sC;
    const int rowBase = blockIdx.y * BM;
    const int colBase = blockIdx.x * BN;
    const float* Ag = A  + (size_t)rowBase * K;
    const float* Bg = Bm + (size_t)colBase * K;

    float acc[4][8][4] = {};

    const int nc = K / BK;

    // prologue: 2 chunks in flight
    load_chunk(Ag, Bg, K, 0, smbase, tid);
    load_chunk(Ag, Bg, K, 1, smbase, tid);

    for (int i = 0; i < nc; i++) {
        // chunk i must be complete before compute
        if (i < nc - 1) {
            asm volatile("cp.async.wait_group 1;" ::: "memory");
        } else {
            asm volatile("cp.async.wait_group 0;" ::: "memory");
        }
        __syncthreads();   // all warps past compute of chunk i-1; chunk i visible CTA-wide

        // prefetch chunk i+2 into stage (i+2)%3 (== (i-1)%3, consumed last iter)
        if (i + 2 < nc) load_chunk(Ag, Bg, K, i + 2, smbase, tid);

        const float* sa = sm + (size_t)(i % NSTAGE) * STAGE_FLOATS;
        const float* sb = sa + A_FLOATS;
        #pragma unroll
        for (int ks = 0; ks < 2; ks++) {
            unsigned af[4][4];
            unsigned bf[8][2];
            #pragma unroll
            for (int mt = 0; mt < 4; mt++) {
                const float* ap = sa + (m0 + mt*16) * RSTR + ks*8;
                af[mt][0] = __float_as_uint(ap[(g    ) * RSTR + tg    ]);
                af[mt][1] = __float_as_uint(ap[(g + 8) * RSTR + tg    ]);
                af[mt][2] = __float_as_uint(ap[(g    ) * RSTR + tg + 4]);
                af[mt][3] = __float_as_uint(ap[(g + 8) * RSTR + tg + 4]);
            }
            #pragma unroll
            for (int nt = 0; nt < 8; nt++) {
                const float* bp = sb + (n0 + nt*8) * RSTR + ks*8;
                bf[nt][0] = __float_as_uint(bp[g * RSTR + tg    ]);
                bf[nt][1] = __float_as_uint(bp[g * RSTR + tg + 4]);
            }
            #pragma unroll
            for (int mt = 0; mt < 4; mt++)
                #pragma unroll
                for (int nt = 0; nt < 8; nt++)
                    mma_tf32(acc[mt][nt], af[mt], bf[nt]);
        }
    }

    // ---- epilogue ----
    const float scale = 0.044194173824159216f;   // 1/sqrt(512)
    #pragma unroll
    for (int mt = 0; mt < 4; mt++) {
        #pragma unroll
        for (int nt = 0; nt < 8; nt++) {
            const float* c = acc[mt][nt];
            const int r0 = rowBase + m0 + mt*16 + g;
            const int cb = colBase + n0 + nt*8 + tg*2;
            #pragma unroll
            for (int half = 0; half < 2; half++) {
                const int r = r0 + half*8;
                float v0 = c[half*2 + 0];
                float v1 = c[half*2 + 1];
                if (EPI == 0 || EPI == 1 || EPI == 2) {
                    v0 += bias[cb];
                    v1 += bias[cb + 1];
                    if (EPI == 1) { v0 = fmaxf(v0, 0.f); v1 = fmaxf(v1, 0.f); }
                    if (EPI == 2) {
                        v0 += resid[(size_t)r * N + cb];
                        v1 += resid[(size_t)r * N + cb + 1];
                    }
                } else if (EPI == 3) {
                    v0 = v0 * scale + table[abs(r - cb)];
                    v1 = v1 * scale + table[abs(r - cb - 1)];
                }
                if (RND) { v0 = tf32r(v0); v1 = tf32r(v1); }
                *(float2*)(C + (size_t)r * N + cb) = make_float2(v0, v1);
            }
        }
    }
}

// ---------------- aux kernels ------------------------------------------------
__global__ void round4_kernel(const float4* __restrict__ in, float4* __restrict__ out, int n4) {
    int i = blockIdx.x * blockDim.x + threadIdx.x;
    if (i >= n4) return;
    float4 a = in[i];
    out[i] = make_float4(tf32r(a.x), tf32r(a.y), tf32r(a.z), tf32r(a.w));
}

__global__ void bias_table_kernel(const float* __restrict__ beta, float* __restrict__ bt) {
    int i = blockIdx.x * blockDim.x + threadIdx.x;
    if (i >= NL * S) return;
    int l = i / S;
    float d = (float)(i % S);
    bt[i] = beta[l*2 + 0] * cosf(6.283185307179586f * d / 24.0f)
          + beta[l*2 + 1] * cosf(6.283185307179586f * d / 720.0f);
}

__global__ void encoder_kernel(const float* __restrict__ z, const float* __restrict__ c,
                               const float* __restrict__ ew, const float* __restrict__ eb,
                               float* __restrict__ x) {
    int i = blockIdx.x * blockDim.x + threadIdx.x;
    if (i >= ROWS * D) return;
    int d  = i % D;
    int bs = i / D;
    int s  = bs % S;
    float val = z[bs] * ew[d*2+0] + c[bs] * ew[d*2+1] + eb[d];
    int k2 = d & ~1;
    float div = expf(-(float)k2 * (logf(10000.0f) / (float)D));
    float ang = (float)s * div;
    val += (d & 1) ? cosf(ang) : sinf(ang);
    x[i] = val;
}

template<bool RND>
__global__ void ln_kernel(const float* __restrict__ in, const float* __restrict__ res,
                          const float* __restrict__ w, const float* __restrict__ b,
                          float* __restrict__ out) {
    int row = blockIdx.x;
    const float* ip = in + (size_t)row * D;
    int t = threadIdx.x;
    float v0 = ip[t];
    float v1 = ip[t + 256];
    if (res) {
        const float* rp = res + (size_t)row * D;
        v0 += rp[t];
        v1 += rp[t + 256];
    }
    float s = v0 + v1, ss = v0*v0 + v1*v1;
    #pragma unroll
    for (int o = 16; o; o >>= 1) {
        s  += __shfl_xor_sync(0xffffffffu, s,  o);
        ss += __shfl_xor_sync(0xffffffffu, ss, o);
    }
    __shared__ float sh_s[8], sh_ss[8];
    int wid = t >> 5, lid = t & 31;
    if (lid == 0) { sh_s[wid] = s; sh_ss[wid] = ss; }
    __syncthreads();
    float ts = 0.f, tss = 0.f;
    #pragma unroll
    for (int i = 0; i < 8; i++) { ts += sh_s[i]; tss += sh_ss[i]; }
    float mean = ts * (1.0f / D);
    float var  = tss * (1.0f / D) - mean * mean;
    float rstd = rsqrtf(var + 1e-5f);
    float* op = out + (size_t)row * D;
    float o0 = (v0 - mean) * rstd * w[t]       + b[t];
    float o1 = (v1 - mean) * rstd * w[t + 256] + b[t + 256];
    if (RND) { o0 = tf32r(o0); o1 = tf32r(o1); }
    op[t]       = o0;
    op[t + 256] = o1;
}

__global__ void softmax_kernel(float* __restrict__ Sc) {
    int row = blockIdx.x;
    float* p = Sc + (size_t)row * S;
    int t = threadIdx.x;
    float v[8];
    float m = -1e30f;
    #pragma unroll
    for (int i = 0; i < 8; i++) { v[i] = p[t + i*256]; m = fmaxf(m, v[i]); }
    #pragma unroll
    for (int o = 16; o; o >>= 1) m = fmaxf(m, __shfl_xor_sync(0xffffffffu, m, o));
    __shared__ float shm[8], shs[8];
    int wid = t >> 5, lid = t & 31;
    if (lid == 0) shm[wid] = m;
    __syncthreads();
    float mm = -1e30f;
    #pragma unroll
    for (int i = 0; i < 8; i++) mm = fmaxf(mm, shm[i]);
    float s = 0.f;
    #pragma unroll
    for (int i = 0; i < 8; i++) { v[i] = __expf(v[i] - mm); s += v[i]; }
    #pragma unroll
    for (int o = 16; o; o >>= 1) s += __shfl_xor_sync(0xffffffffu, s, o);
    if (lid == 0) shs[wid] = s;
    __syncthreads();
    float ts = 0.f;
    #pragma unroll
    for (int i = 0; i < 8; i++) ts += shs[i];
    float inv = 1.0f / ts;
    #pragma unroll
    for (int i = 0; i < 8; i++) p[t + i*256] = tf32r(v[i] * inv);
}

// transpose per batch: vt[b][d][s] = v[b][s][d]
__global__ void transpose_kernel(const float* __restrict__ v, float* __restrict__ vt) {
    __shared__ float tile[32][33];
    int b = blockIdx.z;
    int s0 = blockIdx.x * 32, d0 = blockIdx.y * 32;
    int tx = threadIdx.x, ty = threadIdx.y;
    const float* src = v + (size_t)b * S * D;
    #pragma unroll
    for (int k = 0; k < 4; k++)
        tile[ty + k*8][tx] = src[(size_t)(s0 + ty + k*8) * D + d0 + tx];
    __syncthreads();
    float* dst = vt + (size_t)b * D * S;
    #pragma unroll
    for (int k = 0; k < 4; k++)
        dst[(size_t)(d0 + ty + k*8) * S + s0 + tx] = tile[tx][ty + k*8];
}

__global__ void out_kernel(const float* __restrict__ x, const float* __restrict__ ow,
                           const float* __restrict__ ob, float* __restrict__ out) {
    int row = blockIdx.x;
    const float* p = x + (size_t)row * D;
    int t = threadIdx.x;
    float s = p[t] * ow[t] + p[t + 256] * ow[t + 256];
    #pragma unroll
    for (int o = 16; o; o >>= 1) s += __shfl_xor_sync(0xffffffffu, s, o);
    __shared__ float sh[8];
    int wid = t >> 5, lid = t & 31;
    if (lid == 0) sh[wid] = s;
    __syncthreads();
    if (t == 0) {
        float ts = 0.f;
        #pragma unroll
        for (int i = 0; i < 8; i++) ts += sh[i];
        out[row] = ts + ob[0];
    }
}

// ---------------------------------------------------------------------------
extern "C" void kernel_launch(void* const* d_in, const int* in_sizes, int n_in,
                              void* d_out, int out_size) {
    const float* z     = (const float*)d_in[0];
    const float* c     = (const float*)d_in[1];
    const float* enc_w = (const float*)d_in[2];
    const float* enc_b = (const float*)d_in[3];
    const float* beta  = (const float*)d_in[4];
    const float* wq    = (const float*)d_in[5];
    const float* bq    = (const float*)d_in[6];
    const float* wk    = (const float*)d_in[7];
    const float* bk    = (const float*)d_in[8];
    const float* wv    = (const float*)d_in[9];
    const float* bv    = (const float*)d_in[10];
    const float* ln1w  = (const float*)d_in[11];
    const float* ln1b  = (const float*)d_in[12];
    const float* ln2w  = (const float*)d_in[13];
    const float* ln2b  = (const float*)d_in[14];
    const float* ff1w  = (const float*)d_in[15];
    const float* ff1b  = (const float*)d_in[16];
    const float* ff2w  = (const float*)d_in[17];
    const float* ff2b  = (const float*)d_in[18];
    const float* outw  = (const float*)d_in[19];
    const float* outb  = (const float*)d_in[20];
    float* out = (float*)d_out;

    float *px, *pxn, *pq, *pk, *pv, *pvt, *patt, *psc, *ph, *pbt, *pwr;
    cudaGetSymbolAddress((void**)&px,   g_x);
    cudaGetSymbolAddress((void**)&pxn,  g_xn);
    cudaGetSymbolAddress((void**)&pq,   g_q);
    cudaGetSymbolAddress((void**)&pk,   g_k);
    cudaGetSymbolAddress((void**)&pv,   g_v);
    cudaGetSymbolAddress((void**)&pvt,  g_vt);
    cudaGetSymbolAddress((void**)&patt, g_att);
    cudaGetSymbolAddress((void**)&psc,  g_sc);
    cudaGetSymbolAddress((void**)&ph,   g_h);
    cudaGetSymbolAddress((void**)&pbt,  g_bt);
    cudaGetSymbolAddress((void**)&pwr,  g_wr);

    cudaFuncSetAttribute((const void*)mma_gemm<0,true>,  cudaFuncAttributeMaxDynamicSharedMemorySize, DYN_SMEM);
    cudaFuncSetAttribute((const void*)mma_gemm<1,true>,  cudaFuncAttributeMaxDynamicSharedMemorySize, DYN_SMEM);
    cudaFuncSetAttribute((const void*)mma_gemm<2,false>, cudaFuncAttributeMaxDynamicSharedMemorySize, DYN_SMEM);
    cudaFuncSetAttribute((const void*)mma_gemm<3,false>, cudaFuncAttributeMaxDynamicSharedMemorySize, DYN_SMEM);
    cudaFuncSetAttribute((const void*)mma_gemm<4,false>, cudaFuncAttributeMaxDynamicSharedMemorySize, DYN_SMEM);

    // rounded weight copies (valid-tf32 inputs for mma.sync)
    const size_t nqkv = (size_t)NL * D * D;
    const size_t nff  = (size_t)NL * FF * D;
    float* wq_r  = pwr;
    float* wk_r  = wq_r + nqkv;
    float* wv_r  = wk_r + nqkv;
    float* ff1_r = wv_r + nqkv;
    float* ff2_r = ff1_r + nff;
    round4_kernel<<<(int)((nqkv/4 + 255)/256), 256>>>((const float4*)wq,  (float4*)wq_r,  (int)(nqkv/4));
    round4_kernel<<<(int)((nqkv/4 + 255)/256), 256>>>((const float4*)wk,  (float4*)wk_r,  (int)(nqkv/4));
    round4_kernel<<<(int)((nqkv/4 + 255)/256), 256>>>((const float4*)wv,  (float4*)wv_r,  (int)(nqkv/4));
    round4_kernel<<<(int)((nff/4  + 255)/256), 256>>>((const float4*)ff1w,(float4*)ff1_r, (int)(nff/4));
    round4_kernel<<<(int)((nff/4  + 255)/256), 256>>>((const float4*)ff2w,(float4*)ff2_r, (int)(nff/4));

    bias_table_kernel<<<(NL*S + 255)/256, 256>>>(beta, pbt);
    encoder_kernel<<<(ROWS*D + 255)/256, 256>>>(z, c, enc_w, enc_b, px);

    for (int l = 0; l < NL; l++) {
        const float* l1w = ln1w + l * D;
        const float* l1b = ln1b + l * D;
        const float* l2w = ln2w + l * D;
        const float* l2b = ln2b + l * D;

        // pre-norm (tf32-rounded output feeds GEMMs)
        ln_kernel<true><<<ROWS, 256>>>(px, nullptr, l1w, l1b, pxn);

        // QKV projections (RND outputs: they feed the attention GEMMs)
        dim3 gqkv(D / BN, ROWS / BM);
        mma_gemm<0,true><<<gqkv, 256, DYN_SMEM>>>(pxn, wq_r + (size_t)l*D*D, bq + l*D, nullptr,
                                                  pq, D, D, 0, 0, 0, nullptr);
        mma_gemm<0,true><<<gqkv, 256, DYN_SMEM>>>(pxn, wk_r + (size_t)l*D*D, bk + l*D, nullptr,
                                                  pk, D, D, 0, 0, 0, nullptr);
        mma_gemm<0,true><<<gqkv, 256, DYN_SMEM>>>(pxn, wv_r + (size_t)l*D*D, bv + l*D, nullptr,
                                                  pv, D, D, 0, 0, 0, nullptr);

        // attention scores + cosine bias (batched NT)
        dim3 gsc(S / BN, S / BM, B);
        mma_gemm<3,false><<<gsc, 256, DYN_SMEM>>>(pq, pk, nullptr, nullptr, psc,
                                                  S, D, (size_t)S*D, (size_t)S*D, (size_t)S*S,
                                                  pbt + (size_t)l*S);

        softmax_kernel<<<B * S, 256>>>(psc);

        // transpose V -> Vt (K-major operand for PV-as-NT)
        dim3 gtr(S/32, D/32, B);
        transpose_kernel<<<gtr, dim3(32,8)>>>(pv, pvt);

        // att_out = P @ Vt^T (batched NT)
        dim3 gpv(D / BN, S / BM, B);
        mma_gemm<4,false><<<gpv, 256, DYN_SMEM>>>(psc, pvt, nullptr, nullptr, patt,
                                                  D, S, (size_t)S*S, (size_t)D*S, (size_t)S*D,
                                                  nullptr);

        // x = LN(x + att_out) with ln1 ; xn2 = LN(x) with ln2 (rounded)
        ln_kernel<false><<<ROWS, 256>>>(px, patt, l1w, l1b, px);
        ln_kernel<true><<<ROWS, 256>>>(px, nullptr, l2w, l2b, pxn);

        // FF1 + relu (rounded: feeds FF2)
        dim3 gff1(FF / BN, ROWS / BM);
        mma_gemm<1,true><<<gff1, 256, DYN_SMEM>>>(pxn, ff1_r + (size_t)l*FF*D, ff1b + l*FF, nullptr,
                                                  ph, FF, D, 0, 0, 0, nullptr);

        // FF2 + residual (in-place on x)
        dim3 gff2(D / BN, ROWS / BM);
        mma_gemm<2,false><<<gff2, 256, DYN_SMEM>>>(ph, ff2_r + (size_t)l*D*FF, ff2b + l*D, px,
                                                   px, D, FF, 0, 0, 0, nullptr);
    }

    out_kernel<<<ROWS, 256>>>(px, outw, outb, out);
}

// round 7
// speedup vs baseline: 3.8874x; 1.1090x over previous
#include <cuda_runtime.h>
#include <math.h>
#include <stdint.h>

#define NL 6
#define D 512
#define S 2048
#define B 8
#define FF 2048
#define ROWS 16384

// GEMM tiling: 128x128 CTA tile, 4 warps x (64x64), 2 CTAs/SM
#define BM 128
#define BN 128
#define BK 16
#define RSTR 20                            // conflict-free row stride (floats)
#define A_FLOATS (BM*RSTR)                 // 2560
#define B_FLOATS (BN*RSTR)                 // 2560
#define STAGE_FLOATS (A_FLOATS+B_FLOATS)   // 5120
#define NSTAGE 4
#define DYN_SMEM (NSTAGE*STAGE_FLOATS*4)   // 81920 bytes -> 2 CTAs/SM

// ---------------- scratch (device globals: allocation-free) ----------------
__device__ float g_x  [ROWS*(size_t)D];
__device__ float g_xn [ROWS*(size_t)D];
__device__ float g_q  [ROWS*(size_t)D];
__device__ float g_k  [ROWS*(size_t)D];
__device__ float g_v  [ROWS*(size_t)D];
__device__ float g_vt [ROWS*(size_t)D];
__device__ float g_att[ROWS*(size_t)D];
__device__ float g_sc [(size_t)B*S*S];
__device__ float g_h  [ROWS*(size_t)FF];
__device__ float g_bt [NL*S];
__device__ float g_wr [17301504];      // rounded weights: wqkv(concat) | ff1 | ff2
__device__ float g_bq [NL*1536];       // concat qkv bias

// ---------------- helpers ---------------------------------------------------
__device__ __forceinline__ float tf32r(float x) {
    unsigned u;
    asm("cvt.rna.tf32.f32 %0, %1;" : "=r"(u) : "f"(x));
    return __uint_as_float(u);
}

__device__ __forceinline__ void mma_tf32(float* c, const unsigned* a, const unsigned* b) {
    asm volatile(
        "mma.sync.aligned.m16n8k8.row.col.f32.tf32.tf32.f32 "
        "{%0,%1,%2,%3}, {%4,%5,%6,%7}, {%8,%9}, {%0,%1,%2,%3};\n"
        : "+f"(c[0]), "+f"(c[1]), "+f"(c[2]), "+f"(c[3])
        : "r"(a[0]), "r"(a[1]), "r"(a[2]), "r"(a[3]), "r"(b[0]), "r"(b[1]));
}

__device__ __forceinline__ uint32_t smem_u32(const void* p) {
    uint32_t a;
    asm("{ .reg .u64 t; cvta.to.shared.u64 t, %1; cvt.u32.u64 %0, t; }"
        : "=r"(a) : "l"(p));
    return a;
}

__device__ __forceinline__ void cp16(uint32_t dst, const float* src) {
    asm volatile("cp.async.cg.shared.global [%0], [%1], 16;"
        :: "r"(dst), "l"(__cvta_generic_to_global((const void*)src)) : "memory");
}

// Load one BK=16 chunk (A: 128 rows, B: 128 rows, both K-major) into a stage.
__device__ __forceinline__ void load_chunk(const float* __restrict__ Ag,
                                           const float* __restrict__ Bg, int K,
                                           int j, uint32_t smbase, int tid) {
    const uint32_t st = smbase + (uint32_t)(j & (NSTAGE-1)) * (STAGE_FLOATS * 4);
    const float* asrc = Ag + (size_t)j * BK;
    #pragma unroll
    for (int u = 0; u < 4; u++) {
        int idx = tid + u * 128;           // 0..511
        int row = idx >> 2, c4 = idx & 3;  // row 0..127
        cp16(st + row * (RSTR*4) + c4 * 16, asrc + (size_t)row * K + c4 * 4);
    }
    const float* bsrc = Bg + (size_t)j * BK;
    const uint32_t stb = st + A_FLOATS * 4;
    #pragma unroll
    for (int u = 0; u < 4; u++) {
        int idx = tid + u * 128;
        int row = idx >> 2, c4 = idx & 3;
        cp16(stb + row * (RSTR*4) + c4 * 16, bsrc + (size_t)row * K + c4 * 4);
    }
    asm volatile("cp.async.commit_group;" ::: "memory");
}

// ---------------- tensor-core GEMM (mma.sync tf32) ---------------------------
// C[M,N] = A[M,K] @ Bm[N,K]^T   (both K-major, pre-rounded tf32)
// EPI: 0=bias 1=bias+relu 2=bias+resid 3=scores(scale+table) 4=plain 5=bias+qkv-split
template<int EPI, bool RND>
__global__ void __launch_bounds__(128, 2) mma_gemm(
    const float* __restrict__ A, const float* __restrict__ Bm,
    const float* __restrict__ bias, const float* __restrict__ resid,
    float* __restrict__ C, float* __restrict__ C2, float* __restrict__ C3,
    int N, int K, size_t sA, size_t sB, size_t sC,
    const float* __restrict__ table)
{
    extern __shared__ float sm[];
    const uint32_t smbase = smem_u32(sm);

    const int tid  = threadIdx.x;
    const int wid  = tid >> 5;
    const int lane = tid & 31;
    const int g    = lane >> 2;   // 0..7
    const int tg   = lane & 3;    // 0..3
    const int m0   = (wid >> 1) * 64;
    const int n0   = (wid & 1) * 64;

    A  += (size_t)blockIdx.z * sA;
    Bm += (size_t)blockIdx.z * sB;
    C  += (size_t)blockIdx.z * sC;
    const int rowBase = blockIdx.y * BM;
    const int colBase = blockIdx.x * BN;
    const float* Ag = A  + (size_t)rowBase * K;
    const float* Bg = Bm + (size_t)colBase * K;

    float acc[4][8][4] = {};

    const int nc = K / BK;

    // prologue: 3 chunks in flight
    load_chunk(Ag, Bg, K, 0, smbase, tid);
    load_chunk(Ag, Bg, K, 1, smbase, tid);
    load_chunk(Ag, Bg, K, 2, smbase, tid);

    for (int i = 0; i < nc; i++) {
        // committed groups so far: min(nc, i+3). Newer-than-i groups:
        // 2 normally, 1 at i==nc-2, 0 at i==nc-1 -> wait accordingly.
        if (i < nc - 2)       asm volatile("cp.async.wait_group 2;" ::: "memory");
        else if (i == nc - 2) asm volatile("cp.async.wait_group 1;" ::: "memory");
        else                  asm volatile("cp.async.wait_group 0;" ::: "memory");
        __syncthreads();   // chunk i visible; all warps done with stage (i+3)%4

        if (i + 3 < nc) load_chunk(Ag, Bg, K, i + 3, smbase, tid);

        const float* sa = sm + (size_t)(i & (NSTAGE-1)) * STAGE_FLOATS;
        const float* sb = sa + A_FLOATS;
        #pragma unroll
        for (int ks = 0; ks < 2; ks++) {
            unsigned af[4][4];
            unsigned bf[8][2];
            #pragma unroll
            for (int mt = 0; mt < 4; mt++) {
                const float* ap = sa + (m0 + mt*16) * RSTR + ks*8;
                af[mt][0] = __float_as_uint(ap[(g    ) * RSTR + tg    ]);
                af[mt][1] = __float_as_uint(ap[(g + 8) * RSTR + tg    ]);
                af[mt][2] = __float_as_uint(ap[(g    ) * RSTR + tg + 4]);
                af[mt][3] = __float_as_uint(ap[(g + 8) * RSTR + tg + 4]);
            }
            #pragma unroll
            for (int nt = 0; nt < 8; nt++) {
                const float* bp = sb + (n0 + nt*8) * RSTR + ks*8;
                bf[nt][0] = __float_as_uint(bp[g * RSTR + tg    ]);
                bf[nt][1] = __float_as_uint(bp[g * RSTR + tg + 4]);
            }
            #pragma unroll
            for (int mt = 0; mt < 4; mt++)
                #pragma unroll
                for (int nt = 0; nt < 8; nt++)
                    mma_tf32(acc[mt][nt], af[mt], bf[nt]);
        }
    }

    // ---- epilogue ----
    float* Cout = C;
    int Nout = N;
    int colDelta = 0;
    if (EPI == 5) {
        const int sec = colBase >> 9;          // 128-col tile lies in one section
        Cout = (sec == 0) ? C : (sec == 1 ? C2 : C3);
        colDelta = sec << 9;
        Nout = 512;
    }
    const float scale = 0.044194173824159216f;   // 1/sqrt(512)
    #pragma unroll
    for (int mt = 0; mt < 4; mt++) {
        #pragma unroll
        for (int nt = 0; nt < 8; nt++) {
            const float* c = acc[mt][nt];
            const int r0 = rowBase + m0 + mt*16 + g;
            const int cb = colBase + n0 + nt*8 + tg*2;
            #pragma unroll
            for (int half = 0; half < 2; half++) {
                const int r = r0 + half*8;
                float v0 = c[half*2 + 0];
                float v1 = c[half*2 + 1];
                if (EPI == 0 || EPI == 1 || EPI == 2 || EPI == 5) {
                    v0 += bias[cb];
                    v1 += bias[cb + 1];
                    if (EPI == 1) { v0 = fmaxf(v0, 0.f); v1 = fmaxf(v1, 0.f); }
                    if (EPI == 2) {
                        v0 += resid[(size_t)r * N + cb];
                        v1 += resid[(size_t)r * N + cb + 1];
                    }
                } else if (EPI == 3) {
                    v0 = v0 * scale + table[abs(r - cb)];
                    v1 = v1 * scale + table[abs(r - cb - 1)];
                }
                if (RND) { v0 = tf32r(v0); v1 = tf32r(v1); }
                *(float2*)(Cout + (size_t)r * Nout + (cb - colDelta)) = make_float2(v0, v1);
            }
        }
    }
}

// ---------------- prep kernels -----------------------------------------------
__global__ void round4_kernel(const float4* __restrict__ in, float4* __restrict__ out, int n4) {
    int i = blockIdx.x * blockDim.x + threadIdx.x;
    if (i >= n4) return;
    float4 a = in[i];
    out[i] = make_float4(tf32r(a.x), tf32r(a.y), tf32r(a.z), tf32r(a.w));
}

// concat+round per layer: dst[l][sec*512 + r][0:512] = round(src[l][r][0:512])
__global__ void concat_round_kernel(const float4* __restrict__ src, float4* __restrict__ dst, int sec) {
    const int per = 512 * 128;                 // float4s per layer-section
    int i = blockIdx.x * blockDim.x + threadIdx.x;
    if (i >= NL * per) return;
    int l = i / per, j = i % per;
    float4 a = src[(size_t)l * per + j];
    dst[(size_t)l * (3 * per) + (size_t)sec * per + j] =
        make_float4(tf32r(a.x), tf32r(a.y), tf32r(a.z), tf32r(a.w));
}

__global__ void concat_bias_kernel(const float* __restrict__ bq, const float* __restrict__ bk,
                                   const float* __restrict__ bv, float* __restrict__ dst) {
    int i = blockIdx.x * blockDim.x + threadIdx.x;
    if (i >= NL * 1536) return;
    int l = i / 1536, j = i % 1536;
    const float* src = (j < 512) ? bq : (j < 1024 ? bk : bv);
    dst[i] = src[l * 512 + (j & 511)];
}

__global__ void bias_table_kernel(const float* __restrict__ beta, float* __restrict__ bt) {
    int i = blockIdx.x * blockDim.x + threadIdx.x;
    if (i >= NL * S) return;
    int l = i / S;
    float d = (float)(i % S);
    bt[i] = beta[l*2 + 0] * cosf(6.283185307179586f * d / 24.0f)
          + beta[l*2 + 1] * cosf(6.283185307179586f * d / 720.0f);
}

__global__ void encoder_kernel(const float* __restrict__ z, const float* __restrict__ c,
                               const float* __restrict__ ew, const float* __restrict__ eb,
                               float* __restrict__ x) {
    int i = blockIdx.x * blockDim.x + threadIdx.x;
    if (i >= ROWS * D) return;
    int d  = i % D;
    int bs = i / D;
    int s  = bs % S;
    float val = z[bs] * ew[d*2+0] + c[bs] * ew[d*2+1] + eb[d];
    int k2 = d & ~1;
    float div = expf(-(float)k2 * (logf(10000.0f) / (float)D));
    float ang = (float)s * div;
    val += (d & 1) ? cosf(ang) : sinf(ang);
    x[i] = val;
}

template<bool RND>
__global__ void ln_kernel(const float* __restrict__ in, const float* __restrict__ res,
                          const float* __restrict__ w, const float* __restrict__ b,
                          float* __restrict__ out) {
    int row = blockIdx.x;
    const float* ip = in + (size_t)row * D;
    int t = threadIdx.x;
    float v0 = ip[t];
    float v1 = ip[t + 256];
    if (res) {
        const float* rp = res + (size_t)row * D;
        v0 += rp[t];
        v1 += rp[t + 256];
    }
    float s = v0 + v1, ss = v0*v0 + v1*v1;
    #pragma unroll
    for (int o = 16; o; o >>= 1) {
        s  += __shfl_xor_sync(0xffffffffu, s,  o);
        ss += __shfl_xor_sync(0xffffffffu, ss, o);
    }
    __shared__ float sh_s[8], sh_ss[8];
    int wid = t >> 5, lid = t & 31;
    if (lid == 0) { sh_s[wid] = s; sh_ss[wid] = ss; }
    __syncthreads();
    float ts = 0.f, tss = 0.f;
    #pragma unroll
    for (int i = 0; i < 8; i++) { ts += sh_s[i]; tss += sh_ss[i]; }
    float mean = ts * (1.0f / D);
    float var  = tss * (1.0f / D) - mean * mean;
    float rstd = rsqrtf(var + 1e-5f);
    float* op = out + (size_t)row * D;
    float o0 = (v0 - mean) * rstd * w[t]       + b[t];
    float o1 = (v1 - mean) * rstd * w[t + 256] + b[t + 256];
    if (RND) { o0 = tf32r(o0); o1 = tf32r(o1); }
    op[t]       = o0;
    op[t + 256] = o1;
}

__global__ void softmax_kernel(float* __restrict__ Sc) {
    int row = blockIdx.x;
    float* p = Sc + (size_t)row * S;
    int t = threadIdx.x;
    float v[8];
    float m = -1e30f;
    #pragma unroll
    for (int i = 0; i < 8; i++) { v[i] = p[t + i*256]; m = fmaxf(m, v[i]); }
    #pragma unroll
    for (int o = 16; o; o >>= 1) m = fmaxf(m, __shfl_xor_sync(0xffffffffu, m, o));
    __shared__ float shm[8], shs[8];
    int wid = t >> 5, lid = t & 31;
    if (lid == 0) shm[wid] = m;
    __syncthreads();
    float mm = -1e30f;
    #pragma unroll
    for (int i = 0; i < 8; i++) mm = fmaxf(mm, shm[i]);
    float s = 0.f;
    #pragma unroll
    for (int i = 0; i < 8; i++) { v[i] = __expf(v[i] - mm); s += v[i]; }
    #pragma unroll
    for (int o = 16; o; o >>= 1) s += __shfl_xor_sync(0xffffffffu, s, o);
    if (lid == 0) shs[wid] = s;
    __syncthreads();
    float ts = 0.f;
    #pragma unroll
    for (int i = 0; i < 8; i++) ts += shs[i];
    float inv = 1.0f / ts;
    #pragma unroll
    for (int i = 0; i < 8; i++) p[t + i*256] = tf32r(v[i] * inv);
}

// transpose per batch: vt[b][d][s] = v[b][s][d]
__global__ void transpose_kernel(const float* __restrict__ v, float* __restrict__ vt) {
    __shared__ float tile[32][33];
    int b = blockIdx.z;
    int s0 = blockIdx.x * 32, d0 = blockIdx.y * 32;
    int tx = threadIdx.x, ty = threadIdx.y;
    const float* src = v + (size_t)b * S * D;
    #pragma unroll
    for (int k = 0; k < 4; k++)
        tile[ty + k*8][tx] = src[(size_t)(s0 + ty + k*8) * D + d0 + tx];
    __syncthreads();
    float* dst = vt + (size_t)b * D * S;
    #pragma unroll
    for (int k = 0; k < 4; k++)
        dst[(size_t)(d0 + ty + k*8) * S + s0 + tx] = tile[tx][ty + k*8];
}

__global__ void out_kernel(const float* __restrict__ x, const float* __restrict__ ow,
                           const float* __restrict__ ob, float* __restrict__ out) {
    int row = blockIdx.x;
    const float* p = x + (size_t)row * D;
    int t = threadIdx.x;
    float s = p[t] * ow[t] + p[t + 256] * ow[t + 256];
    #pragma unroll
    for (int o = 16; o; o >>= 1) s += __shfl_xor_sync(0xffffffffu, s, o);
    __shared__ float sh[8];
    int wid = t >> 5, lid = t & 31;
    if (lid == 0) sh[wid] = s;
    __syncthreads();
    if (t == 0) {
        float ts = 0.f;
        #pragma unroll
        for (int i = 0; i < 8; i++) ts += sh[i];
        out[row] = ts + ob[0];
    }
}

// ---------------------------------------------------------------------------
extern "C" void kernel_launch(void* const* d_in, const int* in_sizes, int n_in,
                              void* d_out, int out_size) {
    const float* z     = (const float*)d_in[0];
    const float* c     = (const float*)d_in[1];
    const float* enc_w = (const float*)d_in[2];
    const float* enc_b = (const float*)d_in[3];
    const float* beta  = (const float*)d_in[4];
    const float* wq    = (const float*)d_in[5];
    const float* bq    = (const float*)d_in[6];
    const float* wk    = (const float*)d_in[7];
    const float* bk    = (const float*)d_in[8];
    const float* wv    = (const float*)d_in[9];
    const float* bv    = (const float*)d_in[10];
    const float* ln1w  = (const float*)d_in[11];
    const float* ln1b  = (const float*)d_in[12];
    const float* ln2w  = (const float*)d_in[13];
    const float* ln2b  = (const float*)d_in[14];
    const float* ff1w  = (const float*)d_in[15];
    const float* ff1b  = (const float*)d_in[16];
    const float* ff2w  = (const float*)d_in[17];
    const float* ff2b  = (const float*)d_in[18];
    const float* outw  = (const float*)d_in[19];
    const float* outb  = (const float*)d_in[20];
    float* out = (float*)d_out;

    float *px, *pxn, *pq, *pk, *pv, *pvt, *patt, *psc, *ph, *pbt, *pwr, *pbq;
    cudaGetSymbolAddress((void**)&px,   g_x);
    cudaGetSymbolAddress((void**)&pxn,  g_xn);
    cudaGetSymbolAddress((void**)&pq,   g_q);
    cudaGetSymbolAddress((void**)&pk,   g_k);
    cudaGetSymbolAddress((void**)&pv,   g_v);
    cudaGetSymbolAddress((void**)&pvt,  g_vt);
    cudaGetSymbolAddress((void**)&patt, g_att);
    cudaGetSymbolAddress((void**)&psc,  g_sc);
    cudaGetSymbolAddress((void**)&ph,   g_h);
    cudaGetSymbolAddress((void**)&pbt,  g_bt);
    cudaGetSymbolAddress((void**)&pwr,  g_wr);
    cudaGetSymbolAddress((void**)&pbq,  g_bq);

    cudaFuncSetAttribute((const void*)mma_gemm<5,true>,  cudaFuncAttributeMaxDynamicSharedMemorySize, DYN_SMEM);
    cudaFuncSetAttribute((const void*)mma_gemm<1,true>,  cudaFuncAttributeMaxDynamicSharedMemorySize, DYN_SMEM);
    cudaFuncSetAttribute((const void*)mma_gemm<2,false>, cudaFuncAttributeMaxDynamicSharedMemorySize, DYN_SMEM);
    cudaFuncSetAttribute((const void*)mma_gemm<3,false>, cudaFuncAttributeMaxDynamicSharedMemorySize, DYN_SMEM);
    cudaFuncSetAttribute((const void*)mma_gemm<4,false>, cudaFuncAttributeMaxDynamicSharedMemorySize, DYN_SMEM);

    // rounded/concatenated weight copies
    const size_t nqkv = (size_t)NL * 1536 * 512;   // 4718592
    const size_t nff  = (size_t)NL * FF * D;       // 6291456
    float* wqkv_r = pwr;
    float* ff1_r  = wqkv_r + nqkv;
    float* ff2_r  = ff1_r + nff;
    {
        int n4 = NL * 512 * 128;
        concat_round_kernel<<<(n4 + 255)/256, 256>>>((const float4*)wq, (float4*)wqkv_r, 0);
        concat_round_kernel<<<(n4 + 255)/256, 256>>>((const float4*)wk, (float4*)wqkv_r, 1);
        concat_round_kernel<<<(n4 + 255)/256, 256>>>((const float4*)wv, (float4*)wqkv_r, 2);
        concat_bias_kernel<<<(NL*1536 + 255)/256, 256>>>(bq, bk, bv, pbq);
        round4_kernel<<<(int)((nff/4 + 255)/256), 256>>>((const float4*)ff1w, (float4*)ff1_r, (int)(nff/4));
        round4_kernel<<<(int)((nff/4 + 255)/256), 256>>>((const float4*)ff2w, (float4*)ff2_r, (int)(nff/4));
    }

    bias_table_kernel<<<(NL*S + 255)/256, 256>>>(beta, pbt);
    encoder_kernel<<<(ROWS*D + 255)/256, 256>>>(z, c, enc_w, enc_b, px);

    for (int l = 0; l < NL; l++) {
        const float* l1w = ln1w + l * D;
        const float* l1b = ln1b + l * D;
        const float* l2w = ln2w + l * D;
        const float* l2b = ln2b + l * D;

        // pre-norm (tf32-rounded output feeds GEMMs)
        ln_kernel<true><<<ROWS, 256>>>(px, nullptr, l1w, l1b, pxn);

        // fused QKV projection (split epilogue, rounded outputs)
        dim3 gqkv(1536 / BN, ROWS / BM);
        mma_gemm<5,true><<<gqkv, 128, DYN_SMEM>>>(pxn, wqkv_r + (size_t)l*1536*512,
                                                  pbq + (size_t)l*1536, nullptr,
                                                  pq, pk, pv, 1536, 512, 0, 0, 0, nullptr);

        // attention scores + cosine bias (batched NT)
        dim3 gsc(S / BN, S / BM, B);
        mma_gemm<3,false><<<gsc, 128, DYN_SMEM>>>(pq, pk, nullptr, nullptr, psc, nullptr, nullptr,
                                                  S, D, (size_t)S*D, (size_t)S*D, (size_t)S*S,
                                                  pbt + (size_t)l*S);

        softmax_kernel<<<B * S, 256>>>(psc);

        // transpose V -> Vt (K-major operand for PV-as-NT)
        dim3 gtr(S/32, D/32, B);
        transpose_kernel<<<gtr, dim3(32,8)>>>(pv, pvt);

        // att_out = P @ Vt^T (batched NT)
        dim3 gpv(D / BN, S / BM, B);
        mma_gemm<4,false><<<gpv, 128, DYN_SMEM>>>(psc, pvt, nullptr, nullptr, patt, nullptr, nullptr,
                                                  D, S, (size_t)S*S, (size_t)D*S, (size_t)S*D,
                                                  nullptr);

        // x = LN(x + att_out) with ln1 ; xn2 = LN(x) with ln2 (rounded)
        ln_kernel<false><<<ROWS, 256>>>(px, patt, l1w, l1b, px);
        ln_kernel<true><<<ROWS, 256>>>(px, nullptr, l2w, l2b, pxn);

        // FF1 + relu (rounded: feeds FF2)
        dim3 gff1(FF / BN, ROWS / BM);
        mma_gemm<1,true><<<gff1, 128, DYN_SMEM>>>(pxn, ff1_r + (size_t)l*FF*D, ff1b + l*FF, nullptr,
                                                  ph, nullptr, nullptr, FF, D, 0, 0, 0, nullptr);

        // FF2 + residual (in-place on x)
        dim3 gff2(D / BN, ROWS / BM);
        mma_gemm<2,false><<<gff2, 128, DYN_SMEM>>>(ph, ff2_r + (size_t)l*D*FF, ff2b + l*D, px,
                                                   px, nullptr, nullptr, D, FF, 0, 0, 0, nullptr);
    }

    out_kernel<<<ROWS, 256>>>(px, outw, outb, out);
}

// round 8
// speedup vs baseline: 6.7384x; 1.7334x over previous
#include <cuda_runtime.h>
#include <cuda_fp16.h>
#include <math.h>
#include <stdint.h>

#define NL 6
#define D 512
#define S 2048
#define B 8
#define FF 2048
#define ROWS 16384

// GEMM tiling: 128x128 CTA tile, 4 warps x (64x64), fp16 operands, 2 CTAs/SM
#define BM 128
#define BN 128
#define BK 32                              // halves per chunk (64B per row)
#define RSTR 40                            // halves per smem row (32 + 8 pad) = 80B
#define A_BYTES (BM*RSTR*2)                // 10240
#define STAGE_BYTES (2*A_BYTES)            // 20480
#define NSTAGE 4
#define DYN_SMEM (NSTAGE*STAGE_BYTES)      // 81920 -> 2 CTAs/SM

// ---------------- scratch (device globals: allocation-free) ----------------
__device__ float  g_x  [ROWS*(size_t)D];
__device__ float  g_att[ROWS*(size_t)D];
__device__ float  g_sc [(size_t)B*S*S];     // fp32 logits (precision-critical)
__device__ float  g_bt [NL*S];
__device__ float  g_bq [NL*1536];
__device__ __half h_xn [ROWS*(size_t)D];
__device__ __half h_q  [ROWS*(size_t)D];
__device__ __half h_k  [ROWS*(size_t)D];
__device__ __half h_v  [ROWS*(size_t)D];
__device__ __half h_vt [ROWS*(size_t)D];
__device__ __half h_p  [(size_t)B*S*S];     // half probs
__device__ __half h_h  [ROWS*(size_t)FF];
__device__ __half g_wh [17301504];          // half weights: wqkv(concat) | ff1 | ff2

// ---------------- helpers ---------------------------------------------------
__device__ __forceinline__ uint32_t smem_u32(const void* p) {
    uint32_t a;
    asm("{ .reg .u64 t; cvta.to.shared.u64 t, %1; cvt.u32.u64 %0, t; }"
        : "=r"(a) : "l"(p));
    return a;
}

__device__ __forceinline__ void mma_f16(float* c, const unsigned* a, const unsigned* b) {
    asm volatile(
        "mma.sync.aligned.m16n8k16.row.col.f32.f16.f16.f32 "
        "{%0,%1,%2,%3}, {%4,%5,%6,%7}, {%8,%9}, {%0,%1,%2,%3};\n"
        : "+f"(c[0]), "+f"(c[1]), "+f"(c[2]), "+f"(c[3])
        : "r"(a[0]), "r"(a[1]), "r"(a[2]), "r"(a[3]), "r"(b[0]), "r"(b[1]));
}

__device__ __forceinline__ void cp16(uint32_t dst, const void* src) {
    asm volatile("cp.async.cg.shared.global [%0], [%1], 16;"
        :: "r"(dst), "l"(__cvta_generic_to_global(src)) : "memory");
}

// Load one BK=32-half chunk (A: 128 rows, B: 128 rows, both K-major halves).
__device__ __forceinline__ void load_chunk(const __half* __restrict__ Ag,
                                           const __half* __restrict__ Bg, int K,
                                           int j, uint32_t smbase, int tid) {
    const uint32_t st = smbase + (uint32_t)(j & (NSTAGE-1)) * STAGE_BYTES;
    const __half* asrc = Ag + (size_t)j * BK;
    #pragma unroll
    for (int u = 0; u < 4; u++) {
        int idx = tid + u * 128;           // 0..511
        int row = idx >> 2, c4 = idx & 3;  // row 0..127, 16B group 0..3
        cp16(st + row * 80 + c4 * 16, asrc + (size_t)row * K + c4 * 8);
    }
    const __half* bsrc = Bg + (size_t)j * BK;
    const uint32_t stb = st + A_BYTES;
    #pragma unroll
    for (int u = 0; u < 4; u++) {
        int idx = tid + u * 128;
        int row = idx >> 2, c4 = idx & 3;
        cp16(stb + row * 80 + c4 * 16, bsrc + (size_t)row * K + c4 * 8);
    }
    asm volatile("cp.async.commit_group;" ::: "memory");
}

// ---------------- tensor-core GEMM (mma.sync fp16 -> fp32 acc) ---------------
// C[M,N] = A[M,K] @ Bm[N,K]^T   (half operands, K-major)
// EPI: 1=bias+relu 2=bias+resid 3=scores(scale+table) 4=plain 5=bias+qkv-split
// OUTH: store half (rounded) vs fp32
template<int EPI, bool OUTH>
__global__ void __launch_bounds__(128, 2) mma_gemm(
    const __half* __restrict__ A, const __half* __restrict__ Bm,
    const float* __restrict__ bias, const float* __restrict__ resid,
    void* __restrict__ Cv, void* __restrict__ C2v, void* __restrict__ C3v,
    int N, int K, size_t sA, size_t sB, size_t sC,
    const float* __restrict__ table)
{
    extern __shared__ __half smh[];
    const uint32_t smbase = smem_u32(smh);

    const int tid  = threadIdx.x;
    const int wid  = tid >> 5;
    const int lane = tid & 31;
    const int g    = lane >> 2;   // 0..7
    const int tg   = lane & 3;    // 0..3
    const int m0   = (wid >> 1) * 64;
    const int n0   = (wid & 1) * 64;

    A  += (size_t)blockIdx.z * sA;
    Bm += (size_t)blockIdx.z * sB;
    const int rowBase = blockIdx.y * BM;
    const int colBase = blockIdx.x * BN;
    const __half* Ag = A  + (size_t)rowBase * K;
    const __half* Bg = Bm + (size_t)colBase * K;

    float acc[4][8][4] = {};

    const int nc = K / BK;

    load_chunk(Ag, Bg, K, 0, smbase, tid);
    load_chunk(Ag, Bg, K, 1, smbase, tid);
    load_chunk(Ag, Bg, K, 2, smbase, tid);

    for (int i = 0; i < nc; i++) {
        if (i < nc - 2)       asm volatile("cp.async.wait_group 2;" ::: "memory");
        else if (i == nc - 2) asm volatile("cp.async.wait_group 1;" ::: "memory");
        else                  asm volatile("cp.async.wait_group 0;" ::: "memory");
        __syncthreads();

        if (i + 3 < nc) load_chunk(Ag, Bg, K, i + 3, smbase, tid);

        const __half* sa = smh + (size_t)(i & (NSTAGE-1)) * (STAGE_BYTES/2);
        const __half* sb = sa + BM * RSTR;
        #pragma unroll
        for (int ks = 0; ks < 2; ks++) {      // two k16 steps per chunk
            unsigned af[4][4];
            unsigned bf[8][2];
            #pragma unroll
            for (int mt = 0; mt < 4; mt++) {
                const __half* ap = sa + (m0 + mt*16) * RSTR + 2*tg + ks*16;
                af[mt][0] = *(const unsigned*)(ap + (g    ) * RSTR);
                af[mt][1] = *(const unsigned*)(ap + (g + 8) * RSTR);
                af[mt][2] = *(const unsigned*)(ap + (g    ) * RSTR + 8);
                af[mt][3] = *(const unsigned*)(ap + (g + 8) * RSTR + 8);
            }
            #pragma unroll
            for (int nt = 0; nt < 8; nt++) {
                const __half* bp = sb + (n0 + nt*8 + g) * RSTR + 2*tg + ks*16;
                bf[nt][0] = *(const unsigned*)(bp);
                bf[nt][1] = *(const unsigned*)(bp + 8);
            }
            #pragma unroll
            for (int mt = 0; mt < 4; mt++)
                #pragma unroll
                for (int nt = 0; nt < 8; nt++)
                    mma_f16(acc[mt][nt], af[mt], bf[nt]);
        }
    }

    // ---- epilogue ----
    void* Cout = Cv;
    int Nout = N;
    int colDelta = 0;
    if (EPI == 5) {
        const int sec = colBase >> 9;      // 128-col tile lies wholly in one section
        Cout = (sec == 0) ? Cv : (sec == 1 ? C2v : C3v);
        colDelta = sec << 9;
        Nout = 512;
    }
    const size_t cBatch = (size_t)blockIdx.z * sC;
    const float scale = 0.044194173824159216f;   // 1/sqrt(512)
    #pragma unroll
    for (int mt = 0; mt < 4; mt++) {
        #pragma unroll
        for (int nt = 0; nt < 8; nt++) {
            const float* c = acc[mt][nt];
            const int r0 = rowBase + m0 + mt*16 + g;
            const int cb = colBase + n0 + nt*8 + tg*2;
            #pragma unroll
            for (int half_ = 0; half_ < 2; half_++) {
                const int r = r0 + half_*8;
                float v0 = c[half_*2 + 0];
                float v1 = c[half_*2 + 1];
                if (EPI == 1 || EPI == 2 || EPI == 5) {
                    v0 += bias[cb];
                    v1 += bias[cb + 1];
                    if (EPI == 1) { v0 = fmaxf(v0, 0.f); v1 = fmaxf(v1, 0.f); }
                    if (EPI == 2) {
                        v0 += resid[cBatch + (size_t)r * N + cb];
                        v1 += resid[cBatch + (size_t)r * N + cb + 1];
                    }
                } else if (EPI == 3) {
                    v0 = v0 * scale + table[abs(r - cb)];
                    v1 = v1 * scale + table[abs(r - cb - 1)];
                }
                const size_t off = cBatch + (size_t)r * Nout + (cb - colDelta);
                if (OUTH) {
                    *(__half2*)((__half*)Cout + off) = __floats2half2_rn(v0, v1);
                } else {
                    *(float2*)((float*)Cout + off) = make_float2(v0, v1);
                }
            }
        }
    }
}

// ---------------- prep kernels -----------------------------------------------
__global__ void f2h4_kernel(const float4* __restrict__ in, __half* __restrict__ out, int n4) {
    int i = blockIdx.x * blockDim.x + threadIdx.x;
    if (i >= n4) return;
    float4 a = in[i];
    __half2 h01 = __floats2half2_rn(a.x, a.y);
    __half2 h23 = __floats2half2_rn(a.z, a.w);
    *(__half2*)(out + (size_t)i*4)     = h01;
    *(__half2*)(out + (size_t)i*4 + 2) = h23;
}

// concat per layer into [1536,512] half: dst row block sec*512
__global__ void concat_h_kernel(const float4* __restrict__ src, __half* __restrict__ dst, int sec) {
    const int per = 512 * 128;                 // float4s per layer-section
    int i = blockIdx.x * blockDim.x + threadIdx.x;
    if (i >= NL * per) return;
    int l = i / per, j = i % per;
    float4 a = src[(size_t)l * per + j];
    __half* d = dst + ((size_t)l * 3 + sec) * (512*512) + (size_t)j * 4;
    *(__half2*)(d)     = __floats2half2_rn(a.x, a.y);
    *(__half2*)(d + 2) = __floats2half2_rn(a.z, a.w);
}

__global__ void concat_bias_kernel(const float* __restrict__ bq, const float* __restrict__ bk,
                                   const float* __restrict__ bv, float* __restrict__ dst) {
    int i = blockIdx.x * blockDim.x + threadIdx.x;
    if (i >= NL * 1536) return;
    int l = i / 1536, j = i % 1536;
    const float* src = (j < 512) ? bq : (j < 1024 ? bk : bv);
    dst[i] = src[l * 512 + (j & 511)];
}

__global__ void bias_table_kernel(const float* __restrict__ beta, float* __restrict__ bt) {
    int i = blockIdx.x * blockDim.x + threadIdx.x;
    if (i >= NL * S) return;
    int l = i / S;
    float d = (float)(i % S);
    bt[i] = beta[l*2 + 0] * cosf(6.283185307179586f * d / 24.0f)
          + beta[l*2 + 1] * cosf(6.283185307179586f * d / 720.0f);
}

__global__ void encoder_kernel(const float* __restrict__ z, const float* __restrict__ c,
                               const float* __restrict__ ew, const float* __restrict__ eb,
                               float* __restrict__ x) {
    int i = blockIdx.x * blockDim.x + threadIdx.x;
    if (i >= ROWS * D) return;
    int d  = i % D;
    int bs = i / D;
    int s  = bs % S;
    float val = z[bs] * ew[d*2+0] + c[bs] * ew[d*2+1] + eb[d];
    int k2 = d & ~1;
    float div = expf(-(float)k2 * (logf(10000.0f) / (float)D));
    float ang = (float)s * div;
    val += (d & 1) ? cosf(ang) : sinf(ang);
    x[i] = val;
}

// layernorm; OUTH selects half (GEMM operand) vs fp32 output
template<bool OUTH>
__global__ void ln_kernel(const float* __restrict__ in, const float* __restrict__ res,
                          const float* __restrict__ w, const float* __restrict__ b,
                          void* __restrict__ outv) {
    int row = blockIdx.x;
    const float* ip = in + (size_t)row * D;
    int t = threadIdx.x;
    float v0 = ip[t];
    float v1 = ip[t + 256];
    if (res) {
        const float* rp = res + (size_t)row * D;
        v0 += rp[t];
        v1 += rp[t + 256];
    }
    float s = v0 + v1, ss = v0*v0 + v1*v1;
    #pragma unroll
    for (int o = 16; o; o >>= 1) {
        s  += __shfl_xor_sync(0xffffffffu, s,  o);
        ss += __shfl_xor_sync(0xffffffffu, ss, o);
    }
    __shared__ float sh_s[8], sh_ss[8];
    int wid = t >> 5, lid = t & 31;
    if (lid == 0) { sh_s[wid] = s; sh_ss[wid] = ss; }
    __syncthreads();
    float ts = 0.f, tss = 0.f;
    #pragma unroll
    for (int i = 0; i < 8; i++) { ts += sh_s[i]; tss += sh_ss[i]; }
    float mean = ts * (1.0f / D);
    float var  = tss * (1.0f / D) - mean * mean;
    float rstd = rsqrtf(var + 1e-5f);
    float o0 = (v0 - mean) * rstd * w[t]       + b[t];
    float o1 = (v1 - mean) * rstd * w[t + 256] + b[t + 256];
    if (OUTH) {
        __half* op = (__half*)outv + (size_t)row * D;
        op[t]       = __float2half_rn(o0);
        op[t + 256] = __float2half_rn(o1);
    } else {
        float* op = (float*)outv + (size_t)row * D;
        op[t]       = o0;
        op[t + 256] = o1;
    }
}

// softmax: fp32 logits in, half probs out
__global__ void softmax_kernel(const float* __restrict__ Sc, __half* __restrict__ P) {
    int row = blockIdx.x;
    const float* p = Sc + (size_t)row * S;
    __half* q = P + (size_t)row * S;
    int t = threadIdx.x;
    float v[8];
    float m = -1e30f;
    #pragma unroll
    for (int i = 0; i < 8; i++) { v[i] = p[t + i*256]; m = fmaxf(m, v[i]); }
    #pragma unroll
    for (int o = 16; o; o >>= 1) m = fmaxf(m, __shfl_xor_sync(0xffffffffu, m, o));
    __shared__ float shm[8], shs[8];
    int wid = t >> 5, lid = t & 31;
    if (lid == 0) shm[wid] = m;
    __syncthreads();
    float mm = -1e30f;
    #pragma unroll
    for (int i = 0; i < 8; i++) mm = fmaxf(mm, shm[i]);
    float s = 0.f;
    #pragma unroll
    for (int i = 0; i < 8; i++) { v[i] = __expf(v[i] - mm); s += v[i]; }
    #pragma unroll
    for (int o = 16; o; o >>= 1) s += __shfl_xor_sync(0xffffffffu, s, o);
    if (lid == 0) shs[wid] = s;
    __syncthreads();
    float ts = 0.f;
    #pragma unroll
    for (int i = 0; i < 8; i++) ts += shs[i];
    float inv = 1.0f / ts;
    #pragma unroll
    for (int i = 0; i < 8; i++) q[t + i*256] = __float2half_rn(v[i] * inv);
}

// transpose per batch: vt[b][d][s] = v[b][s][d]  (half)
__global__ void transpose_kernel(const __half* __restrict__ v, __half* __restrict__ vt) {
    __shared__ __half tile[32][34];
    int b = blockIdx.z;
    int s0 = blockIdx.x * 32, d0 = blockIdx.y * 32;
    int tx = threadIdx.x, ty = threadIdx.y;
    const __half* src = v + (size_t)b * S * D;
    #pragma unroll
    for (int k = 0; k < 4; k++)
        tile[ty + k*8][tx] = src[(size_t)(s0 + ty + k*8) * D + d0 + tx];
    __syncthreads();
    __half* dst = vt + (size_t)b * D * S;
    #pragma unroll
    for (int k = 0; k < 4; k++)
        dst[(size_t)(d0 + ty + k*8) * S + s0 + tx] = tile[tx][ty + k*8];
}

__global__ void out_kernel(const float* __restrict__ x, const float* __restrict__ ow,
                           const float* __restrict__ ob, float* __restrict__ out) {
    int row = blockIdx.x;
    const float* p = x + (size_t)row * D;
    int t = threadIdx.x;
    float s = p[t] * ow[t] + p[t + 256] * ow[t + 256];
    #pragma unroll
    for (int o = 16; o; o >>= 1) s += __shfl_xor_sync(0xffffffffu, s, o);
    __shared__ float sh[8];
    int wid = t >> 5, lid = t & 31;
    if (lid == 0) sh[wid] = s;
    __syncthreads();
    if (t == 0) {
        float ts = 0.f;
        #pragma unroll
        for (int i = 0; i < 8; i++) ts += sh[i];
        out[row] = ts + ob[0];
    }
}

// ---------------------------------------------------------------------------
extern "C" void kernel_launch(void* const* d_in, const int* in_sizes, int n_in,
                              void* d_out, int out_size) {
    const float* z     = (const float*)d_in[0];
    const float* c     = (const float*)d_in[1];
    const float* enc_w = (const float*)d_in[2];
    const float* enc_b = (const float*)d_in[3];
    const float* beta  = (const float*)d_in[4];
    const float* wq    = (const float*)d_in[5];
    const float* bq    = (const float*)d_in[6];
    const float* wk    = (const float*)d_in[7];
    const float* bk    = (const float*)d_in[8];
    const float* wv    = (const float*)d_in[9];
    const float* bv    = (const float*)d_in[10];
    const float* ln1w  = (const float*)d_in[11];
    const float* ln1b  = (const float*)d_in[12];
    const float* ln2w  = (const float*)d_in[13];
    const float* ln2b  = (const float*)d_in[14];
    const float* ff1w  = (const float*)d_in[15];
    const float* ff1b  = (const float*)d_in[16];
    const float* ff2w  = (const float*)d_in[17];
    const float* ff2b  = (const float*)d_in[18];
    const float* outw  = (const float*)d_in[19];
    const float* outb  = (const float*)d_in[20];
    float* out = (float*)d_out;

    float *px, *patt, *psc, *pbt, *pbq;
    __half *pxn, *pq, *pk, *pv, *pvt, *pp, *ph, *pwh;
    cudaGetSymbolAddress((void**)&px,   g_x);
    cudaGetSymbolAddress((void**)&patt, g_att);
    cudaGetSymbolAddress((void**)&psc,  g_sc);
    cudaGetSymbolAddress((void**)&pbt,  g_bt);
    cudaGetSymbolAddress((void**)&pbq,  g_bq);
    cudaGetSymbolAddress((void**)&pxn,  h_xn);
    cudaGetSymbolAddress((void**)&pq,   h_q);
    cudaGetSymbolAddress((void**)&pk,   h_k);
    cudaGetSymbolAddress((void**)&pv,   h_v);
    cudaGetSymbolAddress((void**)&pvt,  h_vt);
    cudaGetSymbolAddress((void**)&pp,   h_p);
    cudaGetSymbolAddress((void**)&ph,   h_h);
    cudaGetSymbolAddress((void**)&pwh,  g_wh);

    cudaFuncSetAttribute((const void*)mma_gemm<5,true>,  cudaFuncAttributeMaxDynamicSharedMemorySize, DYN_SMEM);
    cudaFuncSetAttribute((const void*)mma_gemm<1,true>,  cudaFuncAttributeMaxDynamicSharedMemorySize, DYN_SMEM);
    cudaFuncSetAttribute((const void*)mma_gemm<2,false>, cudaFuncAttributeMaxDynamicSharedMemorySize, DYN_SMEM);
    cudaFuncSetAttribute((const void*)mma_gemm<3,false>, cudaFuncAttributeMaxDynamicSharedMemorySize, DYN_SMEM);
    cudaFuncSetAttribute((const void*)mma_gemm<4,false>, cudaFuncAttributeMaxDynamicSharedMemorySize, DYN_SMEM);

    // half weights: concat-qkv | ff1 | ff2
    const size_t nqkv = (size_t)NL * 1536 * 512;
    const size_t nff  = (size_t)NL * FF * D;
    __half* wqkv_h = pwh;
    __half* ff1_h  = wqkv_h + nqkv;
    __half* ff2_h  = ff1_h + nff;
    {
        int n4 = NL * 512 * 128;
        concat_h_kernel<<<(n4 + 255)/256, 256>>>((const float4*)wq, wqkv_h, 0);
        concat_h_kernel<<<(n4 + 255)/256, 256>>>((const float4*)wk, wqkv_h, 1);
        concat_h_kernel<<<(n4 + 255)/256, 256>>>((const float4*)wv, wqkv_h, 2);
        concat_bias_kernel<<<(NL*1536 + 255)/256, 256>>>(bq, bk, bv, pbq);
        f2h4_kernel<<<(int)((nff/4 + 255)/256), 256>>>((const float4*)ff1w, ff1_h, (int)(nff/4));
        f2h4_kernel<<<(int)((nff/4 + 255)/256), 256>>>((const float4*)ff2w, ff2_h, (int)(nff/4));
    }

    bias_table_kernel<<<(NL*S + 255)/256, 256>>>(beta, pbt);
    encoder_kernel<<<(ROWS*D + 255)/256, 256>>>(z, c, enc_w, enc_b, px);

    for (int l = 0; l < NL; l++) {
        const float* l1w = ln1w + l * D;
        const float* l1b = ln1b + l * D;
        const float* l2w = ln2w + l * D;
        const float* l2b = ln2b + l * D;

        // pre-norm -> half operand
        ln_kernel<true><<<ROWS, 256>>>(px, nullptr, l1w, l1b, pxn);

        // fused QKV projection (split epilogue, half outputs)
        dim3 gqkv(1536 / BN, ROWS / BM);
        mma_gemm<5,true><<<gqkv, 128, DYN_SMEM>>>(pxn, wqkv_h + (size_t)l*1536*512,
                                                  pbq + (size_t)l*1536, nullptr,
                                                  pq, pk, pv, 1536, 512, 0, 0, 0, nullptr);

        // attention logits + cosine bias -> fp32 (precision-critical)
        dim3 gsc(S / BN, S / BM, B);
        mma_gemm<3,false><<<gsc, 128, DYN_SMEM>>>(pq, pk, nullptr, nullptr, psc, nullptr, nullptr,
                                                  S, D, (size_t)S*D, (size_t)S*D, (size_t)S*S,
                                                  pbt + (size_t)l*S);

        // softmax fp32 -> half probs
        softmax_kernel<<<B * S, 256>>>(psc, pp);

        // transpose V -> Vt (half, K-major operand for PV-as-NT)
        dim3 gtr(S/32, D/32, B);
        transpose_kernel<<<gtr, dim3(32,8)>>>(pv, pvt);

        // att_out = P @ Vt^T -> fp32
        dim3 gpv(D / BN, S / BM, B);
        mma_gemm<4,false><<<gpv, 128, DYN_SMEM>>>(pp, pvt, nullptr, nullptr, patt, nullptr, nullptr,
                                                  D, S, (size_t)S*S, (size_t)D*S, (size_t)S*D,
                                                  nullptr);

        // x = LN(x + att_out) with ln1 (fp32) ; xn2 = LN(x) with ln2 (half)
        ln_kernel<false><<<ROWS, 256>>>(px, patt, l1w, l1b, px);
        ln_kernel<true><<<ROWS, 256>>>(px, nullptr, l2w, l2b, pxn);

        // FF1 + relu -> half
        dim3 gff1(FF / BN, ROWS / BM);
        mma_gemm<1,true><<<gff1, 128, DYN_SMEM>>>(pxn, ff1_h + (size_t)l*FF*D, ff1b + l*FF, nullptr,
                                                  ph, nullptr, nullptr, FF, D, 0, 0, 0, nullptr);

        // FF2 + residual -> fp32 x (in place)
        dim3 gff2(D / BN, ROWS / BM);
        mma_gemm<2,false><<<gff2, 128, DYN_SMEM>>>(ph, ff2_h + (size_t)l*D*FF, ff2b + l*D, px,
                                                   px, nullptr, nullptr, D, FF, 0, 0, 0, nullptr);
    }

    out_kernel<<<ROWS, 256>>>(px, outw, outb, out);
}

// round 9
// speedup vs baseline: 7.8290x; 1.1618x over previous
#include <cuda_runtime.h>
#include <cuda_fp16.h>
#include <math.h>
#include <stdint.h>

#define NL 6
#define D 512
#define S 2048
#define B 8
#define FF 2048
#define ROWS 16384

// GEMM tiling: 128x128 CTA tile, 4 warps x (64x64), fp16 operands, 2 CTAs/SM
#define BM 128
#define BN 128
#define BK 32                              // halves per chunk (64B per row)
#define RSTR 40                            // halves per smem row (32 + 8 pad) = 80B
#define A_BYTES (BM*RSTR*2)                // 10240
#define STAGE_BYTES (2*A_BYTES)            // 20480
#define NSTAGE 4
#define DYN_SMEM (NSTAGE*STAGE_BYTES)      // 81920 -> 2 CTAs/SM

// ---------------- scratch (device globals: allocation-free) ----------------
__device__ float  g_x  [ROWS*(size_t)D];
__device__ float  g_att[ROWS*(size_t)D];
__device__ float  g_sc [(size_t)B*S*S];     // fp32 logits (precision-critical)
__device__ float  g_bt [NL*S];
__device__ float  g_bq [NL*1536];
__device__ __half h_xn [ROWS*(size_t)D];
__device__ __half h_q  [ROWS*(size_t)D];
__device__ __half h_k  [ROWS*(size_t)D];
__device__ __half h_v  [ROWS*(size_t)D];
__device__ __half h_vt [ROWS*(size_t)D];
__device__ __half h_p  [(size_t)B*S*S];     // half probs
__device__ __half h_h  [ROWS*(size_t)FF];
__device__ __half g_wh [17301504];          // half weights: wqkv(concat) | ff1 | ff2

// ---------------- helpers ---------------------------------------------------
__device__ __forceinline__ uint32_t smem_u32(const void* p) {
    uint32_t a;
    asm("{ .reg .u64 t; cvta.to.shared.u64 t, %1; cvt.u32.u64 %0, t; }"
        : "=r"(a) : "l"(p));
    return a;
}

__device__ __forceinline__ void mma_f16(float* c, const unsigned* a, const unsigned* b) {
    asm volatile(
        "mma.sync.aligned.m16n8k16.row.col.f32.f16.f16.f32 "
        "{%0,%1,%2,%3}, {%4,%5,%6,%7}, {%8,%9}, {%0,%1,%2,%3};\n"
        : "+f"(c[0]), "+f"(c[1]), "+f"(c[2]), "+f"(c[3])
        : "r"(a[0]), "r"(a[1]), "r"(a[2]), "r"(a[3]), "r"(b[0]), "r"(b[1]));
}

__device__ __forceinline__ void ldsm_x4(unsigned* r, uint32_t addr) {
    asm volatile("ldmatrix.sync.aligned.m8n8.x4.shared.b16 {%0,%1,%2,%3}, [%4];"
        : "=r"(r[0]), "=r"(r[1]), "=r"(r[2]), "=r"(r[3]) : "r"(addr));
}

__device__ __forceinline__ void cp16(uint32_t dst, const void* src) {
    asm volatile("cp.async.cg.shared.global [%0], [%1], 16;"
        :: "r"(dst), "l"(__cvta_generic_to_global(src)) : "memory");
}

// Load one BK=32-half chunk (A: 128 rows, B: 128 rows, both K-major halves).
__device__ __forceinline__ void load_chunk(const __half* __restrict__ Ag,
                                           const __half* __restrict__ Bg, int K,
                                           int j, uint32_t smbase, int tid) {
    const uint32_t st = smbase + (uint32_t)(j & (NSTAGE-1)) * STAGE_BYTES;
    const __half* asrc = Ag + (size_t)j * BK;
    #pragma unroll
    for (int u = 0; u < 4; u++) {
        int idx = tid + u * 128;           // 0..511
        int row = idx >> 2, c4 = idx & 3;  // row 0..127, 16B group 0..3
        cp16(st + row * 80 + c4 * 16, asrc + (size_t)row * K + c4 * 8);
    }
    const __half* bsrc = Bg + (size_t)j * BK;
    const uint32_t stb = st + A_BYTES;
    #pragma unroll
    for (int u = 0; u < 4; u++) {
        int idx = tid + u * 128;
        int row = idx >> 2, c4 = idx & 3;
        cp16(stb + row * 80 + c4 * 16, bsrc + (size_t)row * K + c4 * 8);
    }
    asm volatile("cp.async.commit_group;" ::: "memory");
}

// ---------------- tensor-core GEMM (mma.sync fp16 -> fp32 acc, ldmatrix) -----
// C[M,N] = A[M,K] @ Bm[N,K]^T   (half operands, K-major)
// EPI: 1=bias+relu 2=bias+resid 3=scores(scale+table) 4=plain 5=bias+qkv-split
// OUTH: store half vs fp32
template<int EPI, bool OUTH>
__global__ void __launch_bounds__(128, 2) mma_gemm(
    const __half* __restrict__ A, const __half* __restrict__ Bm,
    const float* __restrict__ bias, const float* __restrict__ resid,
    void* __restrict__ Cv, void* __restrict__ C2v, void* __restrict__ C3v,
    int N, int K, size_t sA, size_t sB, size_t sC,
    const float* __restrict__ table)
{
    extern __shared__ __half smh[];
    const uint32_t smbase = smem_u32(smh);

    const int tid  = threadIdx.x;
    const int wid  = tid >> 5;
    const int lane = tid & 31;
    const int g    = lane >> 2;   // 0..7
    const int tg   = lane & 3;    // 0..3
    const int m0   = (wid >> 1) * 64;
    const int n0   = (wid & 1) * 64;

    // ldmatrix per-lane half-offsets (verified against m16n8k16 frag layouts):
    // A x4: lanes 0-7: rows r..r+7 @k+0 | 8-15: rows+8 @k+0 | 16-23: rows @k+8 | 24-31: rows+8 @k+8
    const uint32_t aoff = (uint32_t)(((lane & 7) + ((lane >> 3) & 1) * 8) * RSTR + (lane >> 4) * 8);
    // B x4 (covers two n8 tiles): 0-7: rows n..n+7 @k | 8-15: same rows @k+8 | 16-23: rows+8 @k | 24-31: rows+8 @k+8
    const uint32_t boff = (uint32_t)(((lane & 7) + ((lane >> 4) & 1) * 8) * RSTR + ((lane >> 3) & 1) * 8);

    A  += (size_t)blockIdx.z * sA;
    Bm += (size_t)blockIdx.z * sB;
    const int rowBase = blockIdx.y * BM;
    const int colBase = blockIdx.x * BN;
    const __half* Ag = A  + (size_t)rowBase * K;
    const __half* Bg = Bm + (size_t)colBase * K;

    float acc[4][8][4] = {};

    const int nc = K / BK;

    load_chunk(Ag, Bg, K, 0, smbase, tid);
    load_chunk(Ag, Bg, K, 1, smbase, tid);
    load_chunk(Ag, Bg, K, 2, smbase, tid);

    for (int i = 0; i < nc; i++) {
        if (i < nc - 2)       asm volatile("cp.async.wait_group 2;" ::: "memory");
        else if (i == nc - 2) asm volatile("cp.async.wait_group 1;" ::: "memory");
        else                  asm volatile("cp.async.wait_group 0;" ::: "memory");
        __syncthreads();

        if (i + 3 < nc) load_chunk(Ag, Bg, K, i + 3, smbase, tid);

        const uint32_t sa = smbase + (uint32_t)(i & (NSTAGE-1)) * STAGE_BYTES;
        const uint32_t sb = sa + A_BYTES;
        #pragma unroll
        for (int ks = 0; ks < 2; ks++) {      // two k16 steps per chunk
            unsigned af[4][4];
            unsigned bq[4][4];                // bq[j] = {b0(2j), b1(2j), b0(2j+1), b1(2j+1)}
            #pragma unroll
            for (int mt = 0; mt < 4; mt++)
                ldsm_x4(af[mt], sa + 2u * (aoff + (uint32_t)((m0 + mt*16) * RSTR + ks*16)));
            #pragma unroll
            for (int j = 0; j < 4; j++)
                ldsm_x4(bq[j], sb + 2u * (boff + (uint32_t)((n0 + j*16) * RSTR + ks*16)));
            #pragma unroll
            for (int mt = 0; mt < 4; mt++)
                #pragma unroll
                for (int j = 0; j < 4; j++) {
                    mma_f16(acc[mt][2*j    ], af[mt], &bq[j][0]);
                    mma_f16(acc[mt][2*j + 1], af[mt], &bq[j][2]);
                }
        }
    }

    // ---- epilogue ----
    void* Cout = Cv;
    int Nout = N;
    int colDelta = 0;
    if (EPI == 5) {
        const int sec = colBase >> 9;      // 128-col tile lies wholly in one section
        Cout = (sec == 0) ? Cv : (sec == 1 ? C2v : C3v);
        colDelta = sec << 9;
        Nout = 512;
    }
    const size_t cBatch = (size_t)blockIdx.z * sC;
    const float scale = 0.044194173824159216f;   // 1/sqrt(512)
    #pragma unroll
    for (int mt = 0; mt < 4; mt++) {
        #pragma unroll
        for (int nt = 0; nt < 8; nt++) {
            const float* c = acc[mt][nt];
            const int r0 = rowBase + m0 + mt*16 + g;
            const int cb = colBase + n0 + nt*8 + tg*2;
            #pragma unroll
            for (int half_ = 0; half_ < 2; half_++) {
                const int r = r0 + half_*8;
                float v0 = c[half_*2 + 0];
                float v1 = c[half_*2 + 1];
                if (EPI == 1 || EPI == 2 || EPI == 5) {
                    v0 += bias[cb];
                    v1 += bias[cb + 1];
                    if (EPI == 1) { v0 = fmaxf(v0, 0.f); v1 = fmaxf(v1, 0.f); }
                    if (EPI == 2) {
                        v0 += resid[cBatch + (size_t)r * N + cb];
                        v1 += resid[cBatch + (size_t)r * N + cb + 1];
                    }
                } else if (EPI == 3) {
                    v0 = v0 * scale + table[abs(r - cb)];
                    v1 = v1 * scale + table[abs(r - cb - 1)];
                }
                const size_t off = cBatch + (size_t)r * Nout + (cb - colDelta);
                if (OUTH) {
                    *(__half2*)((__half*)Cout + off) = __floats2half2_rn(v0, v1);
                } else {
                    *(float2*)((float*)Cout + off) = make_float2(v0, v1);
                }
            }
        }
    }
}

// ---------------- prep kernels -----------------------------------------------
__global__ void f2h4_kernel(const float4* __restrict__ in, __half* __restrict__ out, int n4) {
    int i = blockIdx.x * blockDim.x + threadIdx.x;
    if (i >= n4) return;
    float4 a = in[i];
    *(__half2*)(out + (size_t)i*4)     = __floats2half2_rn(a.x, a.y);
    *(__half2*)(out + (size_t)i*4 + 2) = __floats2half2_rn(a.z, a.w);
}

__global__ void concat_h_kernel(const float4* __restrict__ src, __half* __restrict__ dst, int sec) {
    const int per = 512 * 128;                 // float4s per layer-section
    int i = blockIdx.x * blockDim.x + threadIdx.x;
    if (i >= NL * per) return;
    int l = i / per, j = i % per;
    float4 a = src[(size_t)l * per + j];
    __half* d = dst + ((size_t)l * 3 + sec) * (512*512) + (size_t)j * 4;
    *(__half2*)(d)     = __floats2half2_rn(a.x, a.y);
    *(__half2*)(d + 2) = __floats2half2_rn(a.z, a.w);
}

__global__ void concat_bias_kernel(const float* __restrict__ bq, const float* __restrict__ bk,
                                   const float* __restrict__ bv, float* __restrict__ dst) {
    int i = blockIdx.x * blockDim.x + threadIdx.x;
    if (i >= NL * 1536) return;
    int l = i / 1536, j = i % 1536;
    const float* src = (j < 512) ? bq : (j < 1024 ? bk : bv);
    dst[i] = src[l * 512 + (j & 511)];
}

__global__ void bias_table_kernel(const float* __restrict__ beta, float* __restrict__ bt) {
    int i = blockIdx.x * blockDim.x + threadIdx.x;
    if (i >= NL * S) return;
    int l = i / S;
    float d = (float)(i % S);
    bt[i] = beta[l*2 + 0] * cosf(6.283185307179586f * d / 24.0f)
          + beta[l*2 + 1] * cosf(6.283185307179586f * d / 720.0f);
}

__global__ void encoder_kernel(const float* __restrict__ z, const float* __restrict__ c,
                               const float* __restrict__ ew, const float* __restrict__ eb,
                               float* __restrict__ x) {
    int i = blockIdx.x * blockDim.x + threadIdx.x;
    if (i >= ROWS * D) return;
    int d  = i % D;
    int bs = i / D;
    int s  = bs % S;
    float val = z[bs] * ew[d*2+0] + c[bs] * ew[d*2+1] + eb[d];
    int k2 = d & ~1;
    float div = expf(-(float)k2 * (logf(10000.0f) / (float)D));
    float ang = (float)s * div;
    val += (d & 1) ? cosf(ang) : sinf(ang);
    x[i] = val;
}

// single layernorm; OUTH selects half (GEMM operand) vs fp32 output
template<bool OUTH>
__global__ void ln_kernel(const float* __restrict__ in, const float* __restrict__ res,
                          const float* __restrict__ w, const float* __restrict__ b,
                          void* __restrict__ outv) {
    int row = blockIdx.x;
    const float* ip = in + (size_t)row * D;
    int t = threadIdx.x;
    float v0 = ip[t];
    float v1 = ip[t + 256];
    if (res) {
        const float* rp = res + (size_t)row * D;
        v0 += rp[t];
        v1 += rp[t + 256];
    }
    float s = v0 + v1, ss = v0*v0 + v1*v1;
    #pragma unroll
    for (int o = 16; o; o >>= 1) {
        s  += __shfl_xor_sync(0xffffffffu, s,  o);
        ss += __shfl_xor_sync(0xffffffffu, ss, o);
    }
    __shared__ float sh_s[8], sh_ss[8];
    int wid = t >> 5, lid = t & 31;
    if (lid == 0) { sh_s[wid] = s; sh_ss[wid] = ss; }
    __syncthreads();
    float ts = 0.f, tss = 0.f;
    #pragma unroll
    for (int i = 0; i < 8; i++) { ts += sh_s[i]; tss += sh_ss[i]; }
    float mean = ts * (1.0f / D);
    float var  = tss * (1.0f / D) - mean * mean;
    float rstd = rsqrtf(var + 1e-5f);
    float o0 = (v0 - mean) * rstd * w[t]       + b[t];
    float o1 = (v1 - mean) * rstd * w[t + 256] + b[t + 256];
    if (OUTH) {
        __half* op = (__half*)outv + (size_t)row * D;
        op[t]       = __float2half_rn(o0);
        op[t + 256] = __float2half_rn(o1);
    } else {
        float* op = (float*)outv + (size_t)row * D;
        op[t]       = o0;
        op[t + 256] = o1;
    }
}

// fused pair: x' = LN1(x + att) -> out1 (fp32); LN2(x') -> out2 (half)
__global__ void ln_pair_kernel(const float* __restrict__ in, const float* __restrict__ res,
                               const float* __restrict__ w1, const float* __restrict__ b1,
                               const float* __restrict__ w2, const float* __restrict__ b2,
                               float* __restrict__ out1, __half* __restrict__ out2) {
    int row = blockIdx.x;
    int t = threadIdx.x;
    const float* ip = in  + (size_t)row * D;
    const float* rp = res + (size_t)row * D;
    float v0 = ip[t]       + rp[t];
    float v1 = ip[t + 256] + rp[t + 256];

    __shared__ float sh_s[8], sh_ss[8];
    int wid = t >> 5, lid = t & 31;

    // --- LN1 ---
    float s = v0 + v1, ss = v0*v0 + v1*v1;
    #pragma unroll
    for (int o = 16; o; o >>= 1) {
        s  += __shfl_xor_sync(0xffffffffu, s,  o);
        ss += __shfl_xor_sync(0xffffffffu, ss, o);
    }
    if (lid == 0) { sh_s[wid] = s; sh_ss[wid] = ss; }
    __syncthreads();
    float ts = 0.f, tss = 0.f;
    #pragma unroll
    for (int i = 0; i < 8; i++) { ts += sh_s[i]; tss += sh_ss[i]; }
    float mean = ts * (1.0f / D);
    float var  = tss * (1.0f / D) - mean * mean;
    float rstd = rsqrtf(var + 1e-5f);
    float o0 = (v0 - mean) * rstd * w1[t]       + b1[t];
    float o1 = (v1 - mean) * rstd * w1[t + 256] + b1[t + 256];
    float* op1 = out1 + (size_t)row * D;
    op1[t]       = o0;
    op1[t + 256] = o1;
    __syncthreads();    // done reading sh_* before reuse

    // --- LN2 on (o0, o1) ---
    s = o0 + o1; ss = o0*o0 + o1*o1;
    #pragma unroll
    for (int o = 16; o; o >>= 1) {
        s  += __shfl_xor_sync(0xffffffffu, s,  o);
        ss += __shfl_xor_sync(0xffffffffu, ss, o);
    }
    if (lid == 0) { sh_s[wid] = s; sh_ss[wid] = ss; }
    __syncthreads();
    ts = 0.f; tss = 0.f;
    #pragma unroll
    for (int i = 0; i < 8; i++) { ts += sh_s[i]; tss += sh_ss[i]; }
    mean = ts * (1.0f / D);
    var  = tss * (1.0f / D) - mean * mean;
    rstd = rsqrtf(var + 1e-5f);
    __half* op2 = out2 + (size_t)row * D;
    op2[t]       = __float2half_rn((o0 - mean) * rstd * w2[t]       + b2[t]);
    op2[t + 256] = __float2half_rn((o1 - mean) * rstd * w2[t + 256] + b2[t + 256]);
}

// softmax: fp32 logits in, half probs out
__global__ void softmax_kernel(const float* __restrict__ Sc, __half* __restrict__ P) {
    int row = blockIdx.x;
    const float* p = Sc + (size_t)row * S;
    __half* q = P + (size_t)row * S;
    int t = threadIdx.x;
    float v[8];
    float m = -1e30f;
    #pragma unroll
    for (int i = 0; i < 8; i++) { v[i] = p[t + i*256]; m = fmaxf(m, v[i]); }
    #pragma unroll
    for (int o = 16; o; o >>= 1) m = fmaxf(m, __shfl_xor_sync(0xffffffffu, m, o));
    __shared__ float shm[8], shs[8];
    int wid = t >> 5, lid = t & 31;
    if (lid == 0) shm[wid] = m;
    __syncthreads();
    float mm = -1e30f;
    #pragma unroll
    for (int i = 0; i < 8; i++) mm = fmaxf(mm, shm[i]);
    float s = 0.f;
    #pragma unroll
    for (int i = 0; i < 8; i++) { v[i] = __expf(v[i] - mm); s += v[i]; }
    #pragma unroll
    for (int o = 16; o; o >>= 1) s += __shfl_xor_sync(0xffffffffu, s, o);
    if (lid == 0) shs[wid] = s;
    __syncthreads();
    float ts = 0.f;
    #pragma unroll
    for (int i = 0; i < 8; i++) ts += shs[i];
    float inv = 1.0f / ts;
    #pragma unroll
    for (int i = 0; i < 8; i++) q[t + i*256] = __float2half_rn(v[i] * inv);
}

// transpose per batch: vt[b][d][s] = v[b][s][d]  (half)
__global__ void transpose_kernel(const __half* __restrict__ v, __half* __restrict__ vt) {
    __shared__ __half tile[32][34];
    int b = blockIdx.z;
    int s0 = blockIdx.x * 32, d0 = blockIdx.y * 32;
    int tx = threadIdx.x, ty = threadIdx.y;
    const __half* src = v + (size_t)b * S * D;
    #pragma unroll
    for (int k = 0; k < 4; k++)
        tile[ty + k*8][tx] = src[(size_t)(s0 + ty + k*8) * D + d0 + tx];
    __syncthreads();
    __half* dst = vt + (size_t)b * D * S;
    #pragma unroll
    for (int k = 0; k < 4; k++)
        dst[(size_t)(d0 + ty + k*8) * S + s0 + tx] = tile[tx][ty + k*8];
}

__global__ void out_kernel(const float* __restrict__ x, const float* __restrict__ ow,
                           const float* __restrict__ ob, float* __restrict__ out) {
    int row = blockIdx.x;
    const float* p = x + (size_t)row * D;
    int t = threadIdx.x;
    float s = p[t] * ow[t] + p[t + 256] * ow[t + 256];
    #pragma unroll
    for (int o = 16; o; o >>= 1) s += __shfl_xor_sync(0xffffffffu, s, o);
    __shared__ float sh[8];
    int wid = t >> 5, lid = t & 31;
    if (lid == 0) sh[wid] = s;
    __syncthreads();
    if (t == 0) {
        float ts = 0.f;
        #pragma unroll
        for (int i = 0; i < 8; i++) ts += sh[i];
        out[row] = ts + ob[0];
    }
}

// ---------------------------------------------------------------------------
extern "C" void kernel_launch(void* const* d_in, const int* in_sizes, int n_in,
                              void* d_out, int out_size) {
    const float* z     = (const float*)d_in[0];
    const float* c     = (const float*)d_in[1];
    const float* enc_w = (const float*)d_in[2];
    const float* enc_b = (const float*)d_in[3];
    const float* beta  = (const float*)d_in[4];
    const float* wq    = (const float*)d_in[5];
    const float* bq    = (const float*)d_in[6];
    const float* wk    = (const float*)d_in[7];
    const float* bk    = (const float*)d_in[8];
    const float* wv    = (const float*)d_in[9];
    const float* bv    = (const float*)d_in[10];
    const float* ln1w  = (const float*)d_in[11];
    const float* ln1b  = (const float*)d_in[12];
    const float* ln2w  = (const float*)d_in[13];
    const float* ln2b  = (const float*)d_in[14];
    const float* ff1w  = (const float*)d_in[15];
    const float* ff1b  = (const float*)d_in[16];
    const float* ff2w  = (const float*)d_in[17];
    const float* ff2b  = (const float*)d_in[18];
    const float* outw  = (const float*)d_in[19];
    const float* outb  = (const float*)d_in[20];
    float* out = (float*)d_out;

    float *px, *patt, *psc, *pbt, *pbq;
    __half *pxn, *pq, *pk, *pv, *pvt, *pp, *ph, *pwh;
    cudaGetSymbolAddress((void**)&px,   g_x);
    cudaGetSymbolAddress((void**)&patt, g_att);
    cudaGetSymbolAddress((void**)&psc,  g_sc);
    cudaGetSymbolAddress((void**)&pbt,  g_bt);
    cudaGetSymbolAddress((void**)&pbq,  g_bq);
    cudaGetSymbolAddress((void**)&pxn,  h_xn);
    cudaGetSymbolAddress((void**)&pq,   h_q);
    cudaGetSymbolAddress((void**)&pk,   h_k);
    cudaGetSymbolAddress((void**)&pv,   h_v);
    cudaGetSymbolAddress((void**)&pvt,  h_vt);
    cudaGetSymbolAddress((void**)&pp,   h_p);
    cudaGetSymbolAddress((void**)&ph,   h_h);
    cudaGetSymbolAddress((void**)&pwh,  g_wh);

    cudaFuncSetAttribute((const void*)mma_gemm<5,true>,  cudaFuncAttributeMaxDynamicSharedMemorySize, DYN_SMEM);
    cudaFuncSetAttribute((const void*)mma_gemm<1,true>,  cudaFuncAttributeMaxDynamicSharedMemorySize, DYN_SMEM);
    cudaFuncSetAttribute((const void*)mma_gemm<2,false>, cudaFuncAttributeMaxDynamicSharedMemorySize, DYN_SMEM);
    cudaFuncSetAttribute((const void*)mma_gemm<3,false>, cudaFuncAttributeMaxDynamicSharedMemorySize, DYN_SMEM);
    cudaFuncSetAttribute((const void*)mma_gemm<4,false>, cudaFuncAttributeMaxDynamicSharedMemorySize, DYN_SMEM);

    // half weights: concat-qkv | ff1 | ff2
    const size_t nqkv = (size_t)NL * 1536 * 512;
    const size_t nff  = (size_t)NL * FF * D;
    __half* wqkv_h = pwh;
    __half* ff1_h  = wqkv_h + nqkv;
    __half* ff2_h  = ff1_h + nff;
    {
        int n4 = NL * 512 * 128;
        concat_h_kernel<<<(n4 + 255)/256, 256>>>((const float4*)wq, wqkv_h, 0);
        concat_h_kernel<<<(n4 + 255)/256, 256>>>((const float4*)wk, wqkv_h, 1);
        concat_h_kernel<<<(n4 + 255)/256, 256>>>((const float4*)wv, wqkv_h, 2);
        concat_bias_kernel<<<(NL*1536 + 255)/256, 256>>>(bq, bk, bv, pbq);
        f2h4_kernel<<<(int)((nff/4 + 255)/256), 256>>>((const float4*)ff1w, ff1_h, (int)(nff/4));
        f2h4_kernel<<<(int)((nff/4 + 255)/256), 256>>>((const float4*)ff2w, ff2_h, (int)(nff/4));
    }

    bias_table_kernel<<<(NL*S + 255)/256, 256>>>(beta, pbt);
    encoder_kernel<<<(ROWS*D + 255)/256, 256>>>(z, c, enc_w, enc_b, px);

    for (int l = 0; l < NL; l++) {
        const float* l1w = ln1w + l * D;
        const float* l1b = ln1b + l * D;
        const float* l2w = ln2w + l * D;
        const float* l2b = ln2b + l * D;

        // pre-norm -> half operand
        ln_kernel<true><<<ROWS, 256>>>(px, nullptr, l1w, l1b, pxn);

        // fused QKV projection (split epilogue, half outputs)
        dim3 gqkv(1536 / BN, ROWS / BM);
        mma_gemm<5,true><<<gqkv, 128, DYN_SMEM>>>(pxn, wqkv_h + (size_t)l*1536*512,
                                                  pbq + (size_t)l*1536, nullptr,
                                                  pq, pk, pv, 1536, 512, 0, 0, 0, nullptr);

        // attention logits + cosine bias -> fp32 (precision-critical)
        dim3 gsc(S / BN, S / BM, B);
        mma_gemm<3,false><<<gsc, 128, DYN_SMEM>>>(pq, pk, nullptr, nullptr, psc, nullptr, nullptr,
                                                  S, D, (size_t)S*D, (size_t)S*D, (size_t)S*S,
                                                  pbt + (size_t)l*S);

        // softmax fp32 -> half probs
        softmax_kernel<<<B * S, 256>>>(psc, pp);

        // transpose V -> Vt (half, K-major operand for PV-as-NT)
        dim3 gtr(S/32, D/32, B);
        transpose_kernel<<<gtr, dim3(32,8)>>>(pv, pvt);

        // att_out = P @ Vt^T -> fp32
        dim3 gpv(D / BN, S / BM, B);
        mma_gemm<4,false><<<gpv, 128, DYN_SMEM>>>(pp, pvt, nullptr, nullptr, patt, nullptr, nullptr,
                                                  D, S, (size_t)S*S, (size_t)D*S, (size_t)S*D,
                                                  nullptr);

        // fused: x = LN1(x + att) ; xn = LN2(x) (half)
        ln_pair_kernel<<<ROWS, 256>>>(px, patt, l1w, l1b, l2w, l2b, px, pxn);

        // FF1 + relu -> half
        dim3 gff1(FF / BN, ROWS / BM);
        mma_gemm<1,true><<<gff1, 128, DYN_SMEM>>>(pxn, ff1_h + (size_t)l*FF*D, ff1b + l*FF, nullptr,
                                                  ph, nullptr, nullptr, FF, D, 0, 0, 0, nullptr);

        // FF2 + residual -> fp32 x (in place)
        dim3 gff2(D / BN, ROWS / BM);
        mma_gemm<2,false><<<gff2, 128, DYN_SMEM>>>(ph, ff2_h + (size_t)l*D*FF, ff2b + l*D, px,
                                                   px, nullptr, nullptr, D, FF, 0, 0, 0, nullptr);
    }

    out_kernel<<<ROWS, 256>>>(px, outw, outb, out);
}

// round 10
// speedup vs baseline: 8.0609x; 1.0296x over previous
#include <cuda_runtime.h>
#include <cuda_fp16.h>
#include <math.h>
#include <stdint.h>

#define NL 6
#define D 512
#define S 2048
#define B 8
#define FF 2048
#define ROWS 16384

// GEMM tiling: 128x128 CTA tile, 4 warps x (64x64), fp16 operands, 2 CTAs/SM
#define BM 128
#define BN 128
#define BK 32                              // halves per chunk
#define RSTR 40                            // NT row stride in halves (80 B)
#define NNROWB 272                         // NN B-tile row stride in bytes (256+16)
#define A_BYTES (BM*RSTR*2)                // 10240
#define NSTAGE 5

// ---------------- scratch (device globals: allocation-free) ----------------
__device__ float  g_x  [ROWS*(size_t)D];
__device__ float  g_att[ROWS*(size_t)D];
__device__ float  g_sc [(size_t)B*S*S];     // fp32 logits (precision-critical)
__device__ float  g_bt [NL*S];
__device__ float  g_bq [NL*1536];
__device__ __half h_xn [ROWS*(size_t)D];
__device__ __half h_q  [ROWS*(size_t)D];
__device__ __half h_k  [ROWS*(size_t)D];
__device__ __half h_v  [ROWS*(size_t)D];
__device__ __half h_p  [(size_t)B*S*S];     // half probs
__device__ __half h_h  [ROWS*(size_t)FF];
__device__ __half g_wh [17301504];          // half weights: wqkv(concat) | ff1 | ff2

// ---------------- helpers ---------------------------------------------------
__device__ __forceinline__ uint32_t smem_u32(const void* p) {
    uint32_t a;
    asm("{ .reg .u64 t; cvta.to.shared.u64 t, %1; cvt.u32.u64 %0, t; }"
        : "=r"(a) : "l"(p));
    return a;
}

__device__ __forceinline__ void mma_f16(float* c, const unsigned* a, const unsigned* b) {
    asm volatile(
        "mma.sync.aligned.m16n8k16.row.col.f32.f16.f16.f32 "
        "{%0,%1,%2,%3}, {%4,%5,%6,%7}, {%8,%9}, {%0,%1,%2,%3};\n"
        : "+f"(c[0]), "+f"(c[1]), "+f"(c[2]), "+f"(c[3])
        : "r"(a[0]), "r"(a[1]), "r"(a[2]), "r"(a[3]), "r"(b[0]), "r"(b[1]));
}

__device__ __forceinline__ void ldsm_x4(unsigned* r, uint32_t addr) {
    asm volatile("ldmatrix.sync.aligned.m8n8.x4.shared.b16 {%0,%1,%2,%3}, [%4];"
        : "=r"(r[0]), "=r"(r[1]), "=r"(r[2]), "=r"(r[3]) : "r"(addr));
}

__device__ __forceinline__ void ldsm_x4_t(unsigned* r, uint32_t addr) {
    asm volatile("ldmatrix.sync.aligned.m8n8.x4.trans.shared.b16 {%0,%1,%2,%3}, [%4];"
        : "=r"(r[0]), "=r"(r[1]), "=r"(r[2]), "=r"(r[3]) : "r"(addr));
}

__device__ __forceinline__ void cp16(uint32_t dst, const void* src) {
    asm volatile("cp.async.cg.shared.global [%0], [%1], 16;"
        :: "r"(dst), "l"(__cvta_generic_to_global(src)) : "memory");
}

// ---------------- tensor-core GEMM (mma.sync fp16 -> fp32 acc, ldmatrix) -----
// TRB=true : C = A[M,K] @ Bm[N,K]^T  (NT; both K-major)
// TRB=false: C = A[M,K] @ Bm[K,N]    (NN; B k-row-major, trans ldmatrix)
// EPI: 1=bias+relu 2=bias+resid 3=scores(scale+table) 4=plain 5=bias+qkv-split
template<int EPI, bool OUTH, bool TRB>
__global__ void __launch_bounds__(128, 2) mma_gemm(
    const __half* __restrict__ A, const __half* __restrict__ Bm,
    const float* __restrict__ bias, const float* __restrict__ resid,
    void* __restrict__ Cv, void* __restrict__ C2v, void* __restrict__ C3v,
    int N, int K, size_t sA, size_t sB, size_t sC,
    const float* __restrict__ table)
{
    constexpr int BTB = TRB ? (BN*RSTR*2) : (BK*NNROWB);   // B tile bytes
    constexpr int STB = A_BYTES + BTB;                      // stage bytes

    extern __shared__ __half smh[];
    const uint32_t smbase = smem_u32(smh);

    const int tid  = threadIdx.x;
    const int wid  = tid >> 5;
    const int lane = tid & 31;
    const int g    = lane >> 2;
    const int tg   = lane & 3;
    const int m0   = (wid >> 1) * 64;
    const int n0   = (wid & 1) * 64;

    // ldmatrix per-lane offsets
    // A x4 (16x16): lanes 0-7 rows r..r+7 @k0 | 8-15 rows+8 @k0 | 16-23 rows @k+8 | 24-31 rows+8 @k+8
    const uint32_t aoff = (uint32_t)(((lane & 7) + ((lane >> 3) & 1) * 8) * RSTR + (lane >> 4) * 8);
    // NT B x4: same pattern as A but per 16-row (n) group
    const uint32_t boff = (uint32_t)(((lane & 7) + ((lane >> 4) & 1) * 8) * RSTR + ((lane >> 3) & 1) * 8);
    // NN B x4 trans (bytes): m0=(k0-7,n0-7) m1=(k8-15,n0-7) m2=(k0-7,n8-15) m3=(k8-15,n8-15)
    const uint32_t btoff = (uint32_t)(((lane & 7) + ((lane >> 3) & 1) * 8) * NNROWB + ((lane >> 4) & 1) * 16);

    A  += (size_t)blockIdx.z * sA;
    Bm += (size_t)blockIdx.z * sB;
    const int rowBase = blockIdx.y * BM;
    const int colBase = blockIdx.x * BN;
    const __half* Ag = A + (size_t)rowBase * K;
    const __half* Bg = TRB ? (Bm + (size_t)colBase * K)   // NT: row (n) offset
                           : (Bm + colBase);              // NN: col offset

    float acc[4][8][4] = {};

    const int nc = K / BK;

    // ---- chunk loader (lambda-free inline) ----
    auto load_chunk = [&](int j, int stage) {
        const uint32_t st = smbase + (uint32_t)stage * STB;
        const __half* asrc = Ag + (size_t)j * BK;
        #pragma unroll
        for (int u = 0; u < 4; u++) {
            int idx = tid + u * 128;
            int row = idx >> 2, c4 = idx & 3;
            cp16(st + row * 80 + c4 * 16, asrc + (size_t)row * K + c4 * 8);
        }
        const uint32_t stb = st + A_BYTES;
        if (TRB) {
            const __half* bsrc = Bg + (size_t)j * BK;
            #pragma unroll
            for (int u = 0; u < 4; u++) {
                int idx = tid + u * 128;
                int row = idx >> 2, c4 = idx & 3;
                cp16(stb + row * 80 + c4 * 16, bsrc + (size_t)row * K + c4 * 8);
            }
        } else {
            const __half* bsrc = Bg + (size_t)j * BK * N;
            #pragma unroll
            for (int u = 0; u < 4; u++) {
                int idx = tid + u * 128;
                int row = idx >> 4, c16 = idx & 15;     // 32 k-rows x 16 groups
                cp16(stb + row * NNROWB + c16 * 16, bsrc + (size_t)row * N + c16 * 8);
            }
        }
        asm volatile("cp.async.commit_group;" ::: "memory");
    };

    // prologue: 4 chunks in flight
    load_chunk(0, 0);
    load_chunk(1, 1);
    load_chunk(2, 2);
    load_chunk(3, 3);

    int cs = 0;              // compute stage
    int ps = 4 % NSTAGE;     // next prefetch stage
    for (int i = 0; i < nc; i++) {
        if (i < nc - 3)       asm volatile("cp.async.wait_group 3;" ::: "memory");
        else if (i == nc - 3) asm volatile("cp.async.wait_group 2;" ::: "memory");
        else if (i == nc - 2) asm volatile("cp.async.wait_group 1;" ::: "memory");
        else                  asm volatile("cp.async.wait_group 0;" ::: "memory");
        __syncthreads();

        if (i + 4 < nc) {
            load_chunk(i + 4, ps);
            if (++ps == NSTAGE) ps = 0;
        }

        const uint32_t sa = smbase + (uint32_t)cs * STB;
        const uint32_t sb = sa + A_BYTES;
        if (++cs == NSTAGE) cs = 0;

        #pragma unroll
        for (int ks = 0; ks < 2; ks++) {      // two k16 steps per chunk
            unsigned af[4][4];
            unsigned bq[4][4];
            #pragma unroll
            for (int mt = 0; mt < 4; mt++)
                ldsm_x4(af[mt], sa + 2u * (aoff + (uint32_t)((m0 + mt*16) * RSTR + ks*16)));
            #pragma unroll
            for (int j = 0; j < 4; j++) {
                if (TRB)
                    ldsm_x4(bq[j], sb + 2u * (boff + (uint32_t)((n0 + j*16) * RSTR + ks*16)));
                else
                    ldsm_x4_t(bq[j], sb + btoff + (uint32_t)((n0 + j*16) * 2 + ks*16*NNROWB));
            }
            #pragma unroll
            for (int mt = 0; mt < 4; mt++)
                #pragma unroll
                for (int j = 0; j < 4; j++) {
                    mma_f16(acc[mt][2*j    ], af[mt], &bq[j][0]);
                    mma_f16(acc[mt][2*j + 1], af[mt], &bq[j][2]);
                }
        }
    }

    // ---- epilogue ----
    void* Cout = Cv;
    int Nout = N;
    int colDelta = 0;
    if (EPI == 5) {
        const int sec = colBase >> 9;
        Cout = (sec == 0) ? Cv : (sec == 1 ? C2v : C3v);
        colDelta = sec << 9;
        Nout = 512;
    }
    const size_t cBatch = (size_t)blockIdx.z * sC;
    const float scale = 0.044194173824159216f;   // 1/sqrt(512)
    #pragma unroll
    for (int mt = 0; mt < 4; mt++) {
        #pragma unroll
        for (int nt = 0; nt < 8; nt++) {
            const float* c = acc[mt][nt];
            const int r0 = rowBase + m0 + mt*16 + g;
            const int cb = colBase + n0 + nt*8 + tg*2;
            #pragma unroll
            for (int half_ = 0; half_ < 2; half_++) {
                const int r = r0 + half_*8;
                float v0 = c[half_*2 + 0];
                float v1 = c[half_*2 + 1];
                if (EPI == 1 || EPI == 2 || EPI == 5) {
                    v0 += bias[cb];
                    v1 += bias[cb + 1];
                    if (EPI == 1) { v0 = fmaxf(v0, 0.f); v1 = fmaxf(v1, 0.f); }
                    if (EPI == 2) {
                        v0 += resid[cBatch + (size_t)r * N + cb];
                        v1 += resid[cBatch + (size_t)r * N + cb + 1];
                    }
                } else if (EPI == 3) {
                    v0 = v0 * scale + table[abs(r - cb)];
                    v1 = v1 * scale + table[abs(r - cb - 1)];
                }
                const size_t off = cBatch + (size_t)r * Nout + (cb - colDelta);
                if (OUTH) {
                    *(__half2*)((__half*)Cout + off) = __floats2half2_rn(v0, v1);
                } else {
                    *(float2*)((float*)Cout + off) = make_float2(v0, v1);
                }
            }
        }
    }
}

// ---------------- prep kernels -----------------------------------------------
__global__ void f2h4_kernel(const float4* __restrict__ in, __half* __restrict__ out, int n4) {
    int i = blockIdx.x * blockDim.x + threadIdx.x;
    if (i >= n4) return;
    float4 a = in[i];
    *(__half2*)(out + (size_t)i*4)     = __floats2half2_rn(a.x, a.y);
    *(__half2*)(out + (size_t)i*4 + 2) = __floats2half2_rn(a.z, a.w);
}

__global__ void concat_h_kernel(const float4* __restrict__ src, __half* __restrict__ dst, int sec) {
    const int per = 512 * 128;
    int i = blockIdx.x * blockDim.x + threadIdx.x;
    if (i >= NL * per) return;
    int l = i / per, j = i % per;
    float4 a = src[(size_t)l * per + j];
    __half* d = dst + ((size_t)l * 3 + sec) * (512*512) + (size_t)j * 4;
    *(__half2*)(d)     = __floats2half2_rn(a.x, a.y);
    *(__half2*)(d + 2) = __floats2half2_rn(a.z, a.w);
}

__global__ void concat_bias_kernel(const float* __restrict__ bq, const float* __restrict__ bk,
                                   const float* __restrict__ bv, float* __restrict__ dst) {
    int i = blockIdx.x * blockDim.x + threadIdx.x;
    if (i >= NL * 1536) return;
    int l = i / 1536, j = i % 1536;
    const float* src = (j < 512) ? bq : (j < 1024 ? bk : bv);
    dst[i] = src[l * 512 + (j & 511)];
}

__global__ void bias_table_kernel(const float* __restrict__ beta, float* __restrict__ bt) {
    int i = blockIdx.x * blockDim.x + threadIdx.x;
    if (i >= NL * S) return;
    int l = i / S;
    float d = (float)(i % S);
    bt[i] = beta[l*2 + 0] * cosf(6.283185307179586f * d / 24.0f)
          + beta[l*2 + 1] * cosf(6.283185307179586f * d / 720.0f);
}

__global__ void encoder_kernel(const float* __restrict__ z, const float* __restrict__ c,
                               const float* __restrict__ ew, const float* __restrict__ eb,
                               float* __restrict__ x) {
    int i = blockIdx.x * blockDim.x + threadIdx.x;
    if (i >= ROWS * D) return;
    int d  = i % D;
    int bs = i / D;
    int s  = bs % S;
    float val = z[bs] * ew[d*2+0] + c[bs] * ew[d*2+1] + eb[d];
    int k2 = d & ~1;
    float div = expf(-(float)k2 * (logf(10000.0f) / (float)D));
    float ang = (float)s * div;
    val += (d & 1) ? cosf(ang) : sinf(ang);
    x[i] = val;
}

// single layernorm; OUTH selects half vs fp32 output
template<bool OUTH>
__global__ void ln_kernel(const float* __restrict__ in, const float* __restrict__ res,
                          const float* __restrict__ w, const float* __restrict__ b,
                          void* __restrict__ outv) {
    int row = blockIdx.x;
    const float* ip = in + (size_t)row * D;
    int t = threadIdx.x;
    float v0 = ip[t];
    float v1 = ip[t + 256];
    if (res) {
        const float* rp = res + (size_t)row * D;
        v0 += rp[t];
        v1 += rp[t + 256];
    }
    float s = v0 + v1, ss = v0*v0 + v1*v1;
    #pragma unroll
    for (int o = 16; o; o >>= 1) {
        s  += __shfl_xor_sync(0xffffffffu, s,  o);
        ss += __shfl_xor_sync(0xffffffffu, ss, o);
    }
    __shared__ float sh_s[8], sh_ss[8];
    int wid = t >> 5, lid = t & 31;
    if (lid == 0) { sh_s[wid] = s; sh_ss[wid] = ss; }
    __syncthreads();
    float ts = 0.f, tss = 0.f;
    #pragma unroll
    for (int i = 0; i < 8; i++) { ts += sh_s[i]; tss += sh_ss[i]; }
    float mean = ts * (1.0f / D);
    float var  = tss * (1.0f / D) - mean * mean;
    float rstd = rsqrtf(var + 1e-5f);
    float o0 = (v0 - mean) * rstd * w[t]       + b[t];
    float o1 = (v1 - mean) * rstd * w[t + 256] + b[t + 256];
    if (OUTH) {
        __half* op = (__half*)outv + (size_t)row * D;
        op[t]       = __float2half_rn(o0);
        op[t + 256] = __float2half_rn(o1);
    } else {
        float* op = (float*)outv + (size_t)row * D;
        op[t]       = o0;
        op[t + 256] = o1;
    }
}

// fused pair: x' = LN1(x + att) -> out1 (fp32); LN2(x') -> out2 (half)
__global__ void ln_pair_kernel(const float* __restrict__ in, const float* __restrict__ res,
                               const float* __restrict__ w1, const float* __restrict__ b1,
                               const float* __restrict__ w2, const float* __restrict__ b2,
                               float* __restrict__ out1, __half* __restrict__ out2) {
    int row = blockIdx.x;
    int t = threadIdx.x;
    const float* ip = in  + (size_t)row * D;
    const float* rp = res + (size_t)row * D;
    float v0 = ip[t]       + rp[t];
    float v1 = ip[t + 256] + rp[t + 256];

    __shared__ float sh_s[8], sh_ss[8];
    int wid = t >> 5, lid = t & 31;

    float s = v0 + v1, ss = v0*v0 + v1*v1;
    #pragma unroll
    for (int o = 16; o; o >>= 1) {
        s  += __shfl_xor_sync(0xffffffffu, s,  o);
        ss += __shfl_xor_sync(0xffffffffu, ss, o);
    }
    if (lid == 0) { sh_s[wid] = s; sh_ss[wid] = ss; }
    __syncthreads();
    float ts = 0.f, tss = 0.f;
    #pragma unroll
    for (int i = 0; i < 8; i++) { ts += sh_s[i]; tss += sh_ss[i]; }
    float mean = ts * (1.0f / D);
    float var  = tss * (1.0f / D) - mean * mean;
    float rstd = rsqrtf(var + 1e-5f);
    float o0 = (v0 - mean) * rstd * w1[t]       + b1[t];
    float o1 = (v1 - mean) * rstd * w1[t + 256] + b1[t + 256];
    float* op1 = out1 + (size_t)row * D;
    op1[t]       = o0;
    op1[t + 256] = o1;
    __syncthreads();

    s = o0 + o1; ss = o0*o0 + o1*o1;
    #pragma unroll
    for (int o = 16; o; o >>= 1) {
        s  += __shfl_xor_sync(0xffffffffu, s,  o);
        ss += __shfl_xor_sync(0xffffffffu, ss, o);
    }
    if (lid == 0) { sh_s[wid] = s; sh_ss[wid] = ss; }
    __syncthreads();
    ts = 0.f; tss = 0.f;
    #pragma unroll
    for (int i = 0; i < 8; i++) { ts += sh_s[i]; tss += sh_ss[i]; }
    mean = ts * (1.0f / D);
    var  = tss * (1.0f / D) - mean * mean;
    rstd = rsqrtf(var + 1e-5f);
    __half* op2 = out2 + (size_t)row * D;
    op2[t]       = __float2half_rn((o0 - mean) * rstd * w2[t]       + b2[t]);
    op2[t + 256] = __float2half_rn((o1 - mean) * rstd * w2[t + 256] + b2[t + 256]);
}

// softmax: fp32 logits in, half probs out
__global__ void softmax_kernel(const float* __restrict__ Sc, __half* __restrict__ P) {
    int row = blockIdx.x;
    const float* p = Sc + (size_t)row * S;
    __half* q = P + (size_t)row * S;
    int t = threadIdx.x;
    float v[8];
    float m = -1e30f;
    #pragma unroll
    for (int i = 0; i < 8; i++) { v[i] = p[t + i*256]; m = fmaxf(m, v[i]); }
    #pragma unroll
    for (int o = 16; o; o >>= 1) m = fmaxf(m, __shfl_xor_sync(0xffffffffu, m, o));
    __shared__ float shm[8], shs[8];
    int wid = t >> 5, lid = t & 31;
    if (lid == 0) shm[wid] = m;
    __syncthreads();
    float mm = -1e30f;
    #pragma unroll
    for (int i = 0; i < 8; i++) mm = fmaxf(mm, shm[i]);
    float s = 0.f;
    #pragma unroll
    for (int i = 0; i < 8; i++) { v[i] = __expf(v[i] - mm); s += v[i]; }
    #pragma unroll
    for (int o = 16; o; o >>= 1) s += __shfl_xor_sync(0xffffffffu, s, o);
    if (lid == 0) shs[wid] = s;
    __syncthreads();
    float ts = 0.f;
    #pragma unroll
    for (int i = 0; i < 8; i++) ts += shs[i];
    float inv = 1.0f / ts;
    #pragma unroll
    for (int i = 0; i < 8; i++) q[t + i*256] = __float2half_rn(v[i] * inv);
}

__global__ void out_kernel(const float* __restrict__ x, const float* __restrict__ ow,
                           const float* __restrict__ ob, float* __restrict__ out) {
    int row = blockIdx.x;
    const float* p = x + (size_t)row * D;
    int t = threadIdx.x;
    float s = p[t] * ow[t] + p[t + 256] * ow[t + 256];
    #pragma unroll
    for (int o = 16; o; o >>= 1) s += __shfl_xor_sync(0xffffffffu, s, o);
    __shared__ float sh[8];
    int wid = t >> 5, lid = t & 31;
    if (lid == 0) sh[wid] = s;
    __syncthreads();
    if (t == 0) {
        float ts = 0.f;
        #pragma unroll
        for (int i = 0; i < 8; i++) ts += sh[i];
        out[row] = ts + ob[0];
    }
}

// ---------------------------------------------------------------------------
extern "C" void kernel_launch(void* const* d_in, const int* in_sizes, int n_in,
                              void* d_out, int out_size) {
    const float* z     = (const float*)d_in[0];
    const float* c     = (const float*)d_in[1];
    const float* enc_w = (const float*)d_in[2];
    const float* enc_b = (const float*)d_in[3];
    const float* beta  = (const float*)d_in[4];
    const float* wq    = (const float*)d_in[5];
    const float* bq    = (const float*)d_in[6];
    const float* wk    = (const float*)d_in[7];
    const float* bk    = (const float*)d_in[8];
    const float* wv    = (const float*)d_in[9];
    const float* bv    = (const float*)d_in[10];
    const float* ln1w  = (const float*)d_in[11];
    const float* ln1b  = (const float*)d_in[12];
    const float* ln2w  = (const float*)d_in[13];
    const float* ln2b  = (const float*)d_in[14];
    const float* ff1w  = (const float*)d_in[15];
    const float* ff1b  = (const float*)d_in[16];
    const float* ff2w  = (const float*)d_in[17];
    const float* ff2b  = (const float*)d_in[18];
    const float* outw  = (const float*)d_in[19];
    const float* outb  = (const float*)d_in[20];
    float* out = (float*)d_out;

    float *px, *patt, *psc, *pbt, *pbq;
    __half *pxn, *pq, *pk, *pv, *pp, *ph, *pwh;
    cudaGetSymbolAddress((void**)&px,   g_x);
    cudaGetSymbolAddress((void**)&patt, g_att);
    cudaGetSymbolAddress((void**)&psc,  g_sc);
    cudaGetSymbolAddress((void**)&pbt,  g_bt);
    cudaGetSymbolAddress((void**)&pbq,  g_bq);
    cudaGetSymbolAddress((void**)&pxn,  h_xn);
    cudaGetSymbolAddress((void**)&pq,   h_q);
    cudaGetSymbolAddress((void**)&pk,   h_k);
    cudaGetSymbolAddress((void**)&pv,   h_v);
    cudaGetSymbolAddress((void**)&pp,   h_p);
    cudaGetSymbolAddress((void**)&ph,   h_h);
    cudaGetSymbolAddress((void**)&pwh,  g_wh);

    const int SMEM_NT = NSTAGE * (A_BYTES + BN*RSTR*2);    // 102400
    const int SMEM_NN = NSTAGE * (A_BYTES + BK*NNROWB);    // 94720

    cudaFuncSetAttribute((const void*)mma_gemm<5,true ,true >, cudaFuncAttributeMaxDynamicSharedMemorySize, SMEM_NT);
    cudaFuncSetAttribute((const void*)mma_gemm<1,true ,true >, cudaFuncAttributeMaxDynamicSharedMemorySize, SMEM_NT);
    cudaFuncSetAttribute((const void*)mma_gemm<2,false,true >, cudaFuncAttributeMaxDynamicSharedMemorySize, SMEM_NT);
    cudaFuncSetAttribute((const void*)mma_gemm<3,false,true >, cudaFuncAttributeMaxDynamicSharedMemorySize, SMEM_NT);
    cudaFuncSetAttribute((const void*)mma_gemm<4,false,false>, cudaFuncAttributeMaxDynamicSharedMemorySize, SMEM_NN);

    // half weights: concat-qkv | ff1 | ff2
    const size_t nqkv = (size_t)NL * 1536 * 512;
    const size_t nff  = (size_t)NL * FF * D;
    __half* wqkv_h = pwh;
    __half* ff1_h  = wqkv_h + nqkv;
    __half* ff2_h  = ff1_h + nff;
    {
        int n4 = NL * 512 * 128;
        concat_h_kernel<<<(n4 + 255)/256, 256>>>((const float4*)wq, wqkv_h, 0);
        concat_h_kernel<<<(n4 + 255)/256, 256>>>((const float4*)wk, wqkv_h, 1);
        concat_h_kernel<<<(n4 + 255)/256, 256>>>((const float4*)wv, wqkv_h, 2);
        concat_bias_kernel<<<(NL*1536 + 255)/256, 256>>>(bq, bk, bv, pbq);
        f2h4_kernel<<<(int)((nff/4 + 255)/256), 256>>>((const float4*)ff1w, ff1_h, (int)(nff/4));
        f2h4_kernel<<<(int)((nff/4 + 255)/256), 256>>>((const float4*)ff2w, ff2_h, (int)(nff/4));
    }

    bias_table_kernel<<<(NL*S + 255)/256, 256>>>(beta, pbt);
    encoder_kernel<<<(ROWS*D + 255)/256, 256>>>(z, c, enc_w, enc_b, px);

    for (int l = 0; l < NL; l++) {
        const float* l1w = ln1w + l * D;
        const float* l1b = ln1b + l * D;
        const float* l2w = ln2w + l * D;
        const float* l2b = ln2b + l * D;

        // pre-norm -> half operand
        ln_kernel<true><<<ROWS, 256>>>(px, nullptr, l1w, l1b, pxn);

        // fused QKV projection (split epilogue, half outputs)
        dim3 gqkv(1536 / BN, ROWS / BM);
        mma_gemm<5,true,true><<<gqkv, 128, SMEM_NT>>>(pxn, wqkv_h + (size_t)l*1536*512,
                                                      pbq + (size_t)l*1536, nullptr,
                                                      pq, pk, pv, 1536, 512, 0, 0, 0, nullptr);

        // attention logits + cosine bias -> fp32 (precision-critical)
        dim3 gsc(S / BN, S / BM, B);
        mma_gemm<3,false,true><<<gsc, 128, SMEM_NT>>>(pq, pk, nullptr, nullptr, psc, nullptr, nullptr,
                                                      S, D, (size_t)S*D, (size_t)S*D, (size_t)S*S,
                                                      pbt + (size_t)l*S);

        // softmax fp32 -> half probs
        softmax_kernel<<<B * S, 256>>>(psc, pp);

        // att_out = P @ V (NN, trans-ldmatrix B; no transpose kernel) -> fp32
        dim3 gpv(D / BN, S / BM, B);
        mma_gemm<4,false,false><<<gpv, 128, SMEM_NN>>>(pp, pv, nullptr, nullptr, patt, nullptr, nullptr,
                                                       D, S, (size_t)S*S, (size_t)S*D, (size_t)S*D,
                                                       nullptr);

        // fused: x = LN1(x + att) ; xn = LN2(x) (half)
        ln_pair_kernel<<<ROWS, 256>>>(px, patt, l1w, l1b, l2w, l2b, px, pxn);

        // FF1 + relu -> half
        dim3 gff1(FF / BN, ROWS / BM);
        mma_gemm<1,true,true><<<gff1, 128, SMEM_NT>>>(pxn, ff1_h + (size_t)l*FF*D, ff1b + l*FF, nullptr,
                                                      ph, nullptr, nullptr, FF, D, 0, 0, 0, nullptr);

        // FF2 + residual -> fp32 x (in place)
        dim3 gff2(D / BN, ROWS / BM);
        mma_gemm<2,false,true><<<gff2, 128, SMEM_NT>>>(ph, ff2_h + (size_t)l*D*FF, ff2b + l*D, px,
                                                       px, nullptr, nullptr, D, FF, 0, 0, 0, nullptr);
    }

    out_kernel<<<ROWS, 256>>>(px, outw, outb, out);
}

// round 11
// speedup vs baseline: 8.3930x; 1.0412x over previous
#include <cuda_runtime.h>
#include <cuda_fp16.h>
#include <math.h>
#include <stdint.h>

#define NL 6
#define D 512
#define S 2048
#define B 8
#define FF 2048
#define ROWS 16384

// GEMM tiling: 128x128 CTA tile, 4 warps x (64x64), fp16 operands, 2 CTAs/SM
#define BM 128
#define BN 128
#define BK 32                              // halves per chunk
#define RSTR 40                            // NT row stride in halves (80 B)
#define NNROWB 272                         // NN B-tile row stride in bytes (256+16)
#define A_BYTES (BM*RSTR*2)                // 10240
#define NSTAGE 5

// ---------------- scratch (device globals: allocation-free) ----------------
__device__ float  g_x  [ROWS*(size_t)D];
__device__ float  g_att[ROWS*(size_t)D];
__device__ float  g_bt [NL*S];
__device__ float  g_bq [NL*1536];
__device__ float  g_rs [B*S];               // per-row sum of unnormalized probs
__device__ __half h_xn [ROWS*(size_t)D];
__device__ __half h_q  [ROWS*(size_t)D];
__device__ __half h_k  [ROWS*(size_t)D];
__device__ __half h_v  [ROWS*(size_t)D];
__device__ __half h_p  [(size_t)B*S*S];     // half unnormalized probs
__device__ __half h_h  [ROWS*(size_t)FF];
__device__ __half g_wh [17301504];          // half weights: wqkv(concat) | ff1 | ff2

// ---------------- helpers ---------------------------------------------------
__device__ __forceinline__ uint32_t smem_u32(const void* p) {
    uint32_t a;
    asm("{ .reg .u64 t; cvta.to.shared.u64 t, %1; cvt.u32.u64 %0, t; }"
        : "=r"(a) : "l"(p));
    return a;
}

__device__ __forceinline__ void mma_f16(float* c, const unsigned* a, const unsigned* b) {
    asm volatile(
        "mma.sync.aligned.m16n8k16.row.col.f32.f16.f16.f32 "
        "{%0,%1,%2,%3}, {%4,%5,%6,%7}, {%8,%9}, {%0,%1,%2,%3};\n"
        : "+f"(c[0]), "+f"(c[1]), "+f"(c[2]), "+f"(c[3])
        : "r"(a[0]), "r"(a[1]), "r"(a[2]), "r"(a[3]), "r"(b[0]), "r"(b[1]));
}

__device__ __forceinline__ void ldsm_x4(unsigned* r, uint32_t addr) {
    asm volatile("ldmatrix.sync.aligned.m8n8.x4.shared.b16 {%0,%1,%2,%3}, [%4];"
        : "=r"(r[0]), "=r"(r[1]), "=r"(r[2]), "=r"(r[3]) : "r"(addr));
}

__device__ __forceinline__ void ldsm_x4_t(unsigned* r, uint32_t addr) {
    asm volatile("ldmatrix.sync.aligned.m8n8.x4.trans.shared.b16 {%0,%1,%2,%3}, [%4];"
        : "=r"(r[0]), "=r"(r[1]), "=r"(r[2]), "=r"(r[3]) : "r"(addr));
}

__device__ __forceinline__ void cp16(uint32_t dst, const void* src) {
    asm volatile("cp.async.cg.shared.global [%0], [%1], 16;"
        :: "r"(dst), "l"(__cvta_generic_to_global(src)) : "memory");
}

// ---------------- tensor-core GEMM (mma.sync fp16 -> fp32 acc, ldmatrix) -----
// TRB=true : C = A[M,K] @ Bm[N,K]^T  (NT; both K-major)
// TRB=false: C = A[M,K] @ Bm[K,N]    (NN; B k-row-major, trans ldmatrix)
// EPI: 1=bias+relu 2=bias+resid 5=bias+qkv-split
//      6=scores: p=exp(v*scale+table)->half, rowsum atomics into rsum
//      7=pv-normalize: v /= rsum[row] (rsum passed via table)
template<int EPI, bool OUTH, bool TRB>
__global__ void __launch_bounds__(128, 2) mma_gemm(
    const __half* __restrict__ A, const __half* __restrict__ Bm,
    const float* __restrict__ bias, const float* __restrict__ resid,
    void* __restrict__ Cv, void* __restrict__ C2v, void* __restrict__ C3v,
    int N, int K, size_t sA, size_t sB, size_t sC,
    const float* __restrict__ table, float* __restrict__ rsum)
{
    constexpr int BTB = TRB ? (BN*RSTR*2) : (BK*NNROWB);   // B tile bytes
    constexpr int STB = A_BYTES + BTB;                      // stage bytes

    extern __shared__ __half smh[];
    const uint32_t smbase = smem_u32(smh);

    const int tid  = threadIdx.x;
    const int wid  = tid >> 5;
    const int lane = tid & 31;
    const int g    = lane >> 2;
    const int tg   = lane & 3;
    const int m0   = (wid >> 1) * 64;
    const int n0   = (wid & 1) * 64;

    const uint32_t aoff = (uint32_t)(((lane & 7) + ((lane >> 3) & 1) * 8) * RSTR + (lane >> 4) * 8);
    const uint32_t boff = (uint32_t)(((lane & 7) + ((lane >> 4) & 1) * 8) * RSTR + ((lane >> 3) & 1) * 8);
    const uint32_t btoff = (uint32_t)(((lane & 7) + ((lane >> 3) & 1) * 8) * NNROWB + ((lane >> 4) & 1) * 16);

    A  += (size_t)blockIdx.z * sA;
    Bm += (size_t)blockIdx.z * sB;
    const int rowBase = blockIdx.y * BM;
    const int colBase = blockIdx.x * BN;
    const __half* Ag = A + (size_t)rowBase * K;
    const __half* Bg = TRB ? (Bm + (size_t)colBase * K) : (Bm + colBase);

    float acc[4][8][4] = {};

    const int nc = K / BK;

    auto load_chunk = [&](int j, int stage) {
        const uint32_t st = smbase + (uint32_t)stage * STB;
        const __half* asrc = Ag + (size_t)j * BK;
        #pragma unroll
        for (int u = 0; u < 4; u++) {
            int idx = tid + u * 128;
            int row = idx >> 2, c4 = idx & 3;
            cp16(st + row * 80 + c4 * 16, asrc + (size_t)row * K + c4 * 8);
        }
        const uint32_t stb = st + A_BYTES;
        if (TRB) {
            const __half* bsrc = Bg + (size_t)j * BK;
            #pragma unroll
            for (int u = 0; u < 4; u++) {
                int idx = tid + u * 128;
                int row = idx >> 2, c4 = idx & 3;
                cp16(stb + row * 80 + c4 * 16, bsrc + (size_t)row * K + c4 * 8);
            }
        } else {
            const __half* bsrc = Bg + (size_t)j * BK * N;
            #pragma unroll
            for (int u = 0; u < 4; u++) {
                int idx = tid + u * 128;
                int row = idx >> 4, c16 = idx & 15;
                cp16(stb + row * NNROWB + c16 * 16, bsrc + (size_t)row * N + c16 * 8);
            }
        }
        asm volatile("cp.async.commit_group;" ::: "memory");
    };

    load_chunk(0, 0);
    load_chunk(1, 1);
    load_chunk(2, 2);
    load_chunk(3, 3);

    int cs = 0;
    int ps = 4 % NSTAGE;
    for (int i = 0; i < nc; i++) {
        if (i < nc - 3)       asm volatile("cp.async.wait_group 3;" ::: "memory");
        else if (i == nc - 3) asm volatile("cp.async.wait_group 2;" ::: "memory");
        else if (i == nc - 2) asm volatile("cp.async.wait_group 1;" ::: "memory");
        else                  asm volatile("cp.async.wait_group 0;" ::: "memory");
        __syncthreads();

        if (i + 4 < nc) {
            load_chunk(i + 4, ps);
            if (++ps == NSTAGE) ps = 0;
        }

        const uint32_t sa = smbase + (uint32_t)cs * STB;
        const uint32_t sb = sa + A_BYTES;
        if (++cs == NSTAGE) cs = 0;

        #pragma unroll
        for (int ks = 0; ks < 2; ks++) {
            unsigned af[4][4];
            unsigned bq[4][4];
            #pragma unroll
            for (int mt = 0; mt < 4; mt++)
                ldsm_x4(af[mt], sa + 2u * (aoff + (uint32_t)((m0 + mt*16) * RSTR + ks*16)));
            #pragma unroll
            for (int j = 0; j < 4; j++) {
                if (TRB)
                    ldsm_x4(bq[j], sb + 2u * (boff + (uint32_t)((n0 + j*16) * RSTR + ks*16)));
                else
                    ldsm_x4_t(bq[j], sb + btoff + (uint32_t)((n0 + j*16) * 2 + ks*16*NNROWB));
            }
            #pragma unroll
            for (int mt = 0; mt < 4; mt++)
                #pragma unroll
                for (int j = 0; j < 4; j++) {
                    mma_f16(acc[mt][2*j    ], af[mt], &bq[j][0]);
                    mma_f16(acc[mt][2*j + 1], af[mt], &bq[j][2]);
                }
        }
    }

    // ---- epilogue ----
    const size_t cBatch = (size_t)blockIdx.z * sC;
    const float scale = 0.044194173824159216f;   // 1/sqrt(512)

    if (EPI == 6) {
        // scores: unnormalized exp-probs (half) + row-sum atomics
        __half* P = (__half*)Cv + cBatch;
        float* rsbase = rsum + (size_t)blockIdx.z * S;
        #pragma unroll
        for (int mt = 0; mt < 4; mt++) {
            #pragma unroll
            for (int half_ = 0; half_ < 2; half_++) {
                const int r = rowBase + m0 + mt*16 + g + half_*8;
                float rsumv = 0.f;
                #pragma unroll
                for (int nt = 0; nt < 8; nt++) {
                    const int cb = colBase + n0 + nt*8 + tg*2;
                    float v0 = __expf(acc[mt][nt][half_*2 + 0] * scale + table[abs(r - cb)]);
                    float v1 = __expf(acc[mt][nt][half_*2 + 1] * scale + table[abs(r - cb - 1)]);
                    __half hv0 = __float2half_rn(v0);
                    __half hv1 = __float2half_rn(v1);
                    *(__half2*)(P + (size_t)r * N + cb) = __halves2half2(hv0, hv1);
                    rsumv += __half2float(hv0) + __half2float(hv1);   // sum the rounded values
                }
                // reduce over tg quad (lanes differ in bits 0,1)
                rsumv += __shfl_xor_sync(0xffffffffu, rsumv, 1);
                rsumv += __shfl_xor_sync(0xffffffffu, rsumv, 2);
                if (tg == 0) atomicAdd(rsbase + r, rsumv);
            }
        }
        return;
    }

    void* Cout = Cv;
    int Nout = N;
    int colDelta = 0;
    if (EPI == 5) {
        const int sec = colBase >> 9;
        Cout = (sec == 0) ? Cv : (sec == 1 ? C2v : C3v);
        colDelta = sec << 9;
        Nout = 512;
    }
    #pragma unroll
    for (int mt = 0; mt < 4; mt++) {
        #pragma unroll
        for (int half_ = 0; half_ < 2; half_++) {
            const int r = rowBase + m0 + mt*16 + g + half_*8;
            float inv = 1.0f;
            if (EPI == 7) inv = 1.0f / table[(size_t)blockIdx.z * S + r];   // table = rowsum
            #pragma unroll
            for (int nt = 0; nt < 8; nt++) {
                const float* c = acc[mt][nt];
                const int cb = colBase + n0 + nt*8 + tg*2;
                float v0 = c[half_*2 + 0];
                float v1 = c[half_*2 + 1];
                if (EPI == 1 || EPI == 2 || EPI == 5) {
                    v0 += bias[cb];
                    v1 += bias[cb + 1];
                    if (EPI == 1) { v0 = fmaxf(v0, 0.f); v1 = fmaxf(v1, 0.f); }
                    if (EPI == 2) {
                        v0 += resid[cBatch + (size_t)r * N + cb];
                        v1 += resid[cBatch + (size_t)r * N + cb + 1];
                    }
                } else if (EPI == 7) {
                    v0 *= inv;
                    v1 *= inv;
                }
                const size_t off = cBatch + (size_t)r * Nout + (cb - colDelta);
                if (OUTH) {
                    *(__half2*)((__half*)Cout + off) = __floats2half2_rn(v0, v1);
                } else {
                    *(float2*)((float*)Cout + off) = make_float2(v0, v1);
                }
            }
        }
    }
}

// ---------------- prep kernels -----------------------------------------------
__global__ void f2h4_kernel(const float4* __restrict__ in, __half* __restrict__ out, int n4) {
    int i = blockIdx.x * blockDim.x + threadIdx.x;
    if (i >= n4) return;
    float4 a = in[i];
    *(__half2*)(out + (size_t)i*4)     = __floats2half2_rn(a.x, a.y);
    *(__half2*)(out + (size_t)i*4 + 2) = __floats2half2_rn(a.z, a.w);
}

__global__ void concat_h_kernel(const float4* __restrict__ src, __half* __restrict__ dst, int sec) {
    const int per = 512 * 128;
    int i = blockIdx.x * blockDim.x + threadIdx.x;
    if (i >= NL * per) return;
    int l = i / per, j = i % per;
    float4 a = src[(size_t)l * per + j];
    __half* d = dst + ((size_t)l * 3 + sec) * (512*512) + (size_t)j * 4;
    *(__half2*)(d)     = __floats2half2_rn(a.x, a.y);
    *(__half2*)(d + 2) = __floats2half2_rn(a.z, a.w);
}

__global__ void concat_bias_kernel(const float* __restrict__ bq, const float* __restrict__ bk,
                                   const float* __restrict__ bv, float* __restrict__ dst) {
    int i = blockIdx.x * blockDim.x + threadIdx.x;
    if (i >= NL * 1536) return;
    int l = i / 1536, j = i % 1536;
    const float* src = (j < 512) ? bq : (j < 1024 ? bk : bv);
    dst[i] = src[l * 512 + (j & 511)];
}

__global__ void bias_table_kernel(const float* __restrict__ beta, float* __restrict__ bt) {
    int i = blockIdx.x * blockDim.x + threadIdx.x;
    if (i >= NL * S) return;
    int l = i / S;
    float d = (float)(i % S);
    bt[i] = beta[l*2 + 0] * cosf(6.283185307179586f * d / 24.0f)
          + beta[l*2 + 1] * cosf(6.283185307179586f * d / 720.0f);
}

__global__ void encoder_kernel(const float* __restrict__ z, const float* __restrict__ c,
                               const float* __restrict__ ew, const float* __restrict__ eb,
                               float* __restrict__ x) {
    int i = blockIdx.x * blockDim.x + threadIdx.x;
    if (i >= ROWS * D) return;
    int d  = i % D;
    int bs = i / D;
    int s  = bs % S;
    float val = z[bs] * ew[d*2+0] + c[bs] * ew[d*2+1] + eb[d];
    int k2 = d & ~1;
    float div = expf(-(float)k2 * (logf(10000.0f) / (float)D));
    float ang = (float)s * div;
    val += (d & 1) ? cosf(ang) : sinf(ang);
    x[i] = val;
}

// single layernorm; OUTH selects half vs fp32 output
template<bool OUTH>
__global__ void ln_kernel(const float* __restrict__ in, const float* __restrict__ res,
                          const float* __restrict__ w, const float* __restrict__ b,
                          void* __restrict__ outv) {
    int row = blockIdx.x;
    const float* ip = in + (size_t)row * D;
    int t = threadIdx.x;
    float v0 = ip[t];
    float v1 = ip[t + 256];
    if (res) {
        const float* rp = res + (size_t)row * D;
        v0 += rp[t];
        v1 += rp[t + 256];
    }
    float s = v0 + v1, ss = v0*v0 + v1*v1;
    #pragma unroll
    for (int o = 16; o; o >>= 1) {
        s  += __shfl_xor_sync(0xffffffffu, s,  o);
        ss += __shfl_xor_sync(0xffffffffu, ss, o);
    }
    __shared__ float sh_s[8], sh_ss[8];
    int wid = t >> 5, lid = t & 31;
    if (lid == 0) { sh_s[wid] = s; sh_ss[wid] = ss; }
    __syncthreads();
    float ts = 0.f, tss = 0.f;
    #pragma unroll
    for (int i = 0; i < 8; i++) { ts += sh_s[i]; tss += sh_ss[i]; }
    float mean = ts * (1.0f / D);
    float var  = tss * (1.0f / D) - mean * mean;
    float rstd = rsqrtf(var + 1e-5f);
    float o0 = (v0 - mean) * rstd * w[t]       + b[t];
    float o1 = (v1 - mean) * rstd * w[t + 256] + b[t + 256];
    if (OUTH) {
        __half* op = (__half*)outv + (size_t)row * D;
        op[t]       = __float2half_rn(o0);
        op[t + 256] = __float2half_rn(o1);
    } else {
        float* op = (float*)outv + (size_t)row * D;
        op[t]       = o0;
        op[t + 256] = o1;
    }
}

// fused pair: x' = LN1(x + att) -> out1 (fp32); LN2(x') -> out2 (half)
__global__ void ln_pair_kernel(const float* __restrict__ in, const float* __restrict__ res,
                               const float* __restrict__ w1, const float* __restrict__ b1,
                               const float* __restrict__ w2, const float* __restrict__ b2,
                               float* __restrict__ out1, __half* __restrict__ out2) {
    int row = blockIdx.x;
    int t = threadIdx.x;
    const float* ip = in  + (size_t)row * D;
    const float* rp = res + (size_t)row * D;
    float v0 = ip[t]       + rp[t];
    float v1 = ip[t + 256] + rp[t + 256];

    __shared__ float sh_s[8], sh_ss[8];
    int wid = t >> 5, lid = t & 31;

    float s = v0 + v1, ss = v0*v0 + v1*v1;
    #pragma unroll
    for (int o = 16; o; o >>= 1) {
        s  += __shfl_xor_sync(0xffffffffu, s,  o);
        ss += __shfl_xor_sync(0xffffffffu, ss, o);
    }
    if (lid == 0) { sh_s[wid] = s; sh_ss[wid] = ss; }
    __syncthreads();
    float ts = 0.f, tss = 0.f;
    #pragma unroll
    for (int i = 0; i < 8; i++) { ts += sh_s[i]; tss += sh_ss[i]; }
    float mean = ts * (1.0f / D);
    float var  = tss * (1.0f / D) - mean * mean;
    float rstd = rsqrtf(var + 1e-5f);
    float o0 = (v0 - mean) * rstd * w1[t]       + b1[t];
    float o1 = (v1 - mean) * rstd * w1[t + 256] + b1[t + 256];
    float* op1 = out1 + (size_t)row * D;
    op1[t]       = o0;
    op1[t + 256] = o1;
    __syncthreads();

    s = o0 + o1; ss = o0*o0 + o1*o1;
    #pragma unroll
    for (int o = 16; o; o >>= 1) {
        s  += __shfl_xor_sync(0xffffffffu, s,  o);
        ss += __shfl_xor_sync(0xffffffffu, ss, o);
    }
    if (lid == 0) { sh_s[wid] = s; sh_ss[wid] = ss; }
    __syncthreads();
    ts = 0.f; tss = 0.f;
    #pragma unroll
    for (int i = 0; i < 8; i++) { ts += sh_s[i]; tss += sh_ss[i]; }
    mean = ts * (1.0f / D);
    var  = tss * (1.0f / D) - mean * mean;
    rstd = rsqrtf(var + 1e-5f);
    __half* op2 = out2 + (size_t)row * D;
    op2[t]       = __float2half_rn((o0 - mean) * rstd * w2[t]       + b2[t]);
    op2[t + 256] = __float2half_rn((o1 - mean) * rstd * w2[t + 256] + b2[t + 256]);
}

__global__ void out_kernel(const float* __restrict__ x, const float* __restrict__ ow,
                           const float* __restrict__ ob, float* __restrict__ out) {
    int row = blockIdx.x;
    const float* p = x + (size_t)row * D;
    int t = threadIdx.x;
    float s = p[t] * ow[t] + p[t + 256] * ow[t + 256];
    #pragma unroll
    for (int o = 16; o; o >>= 1) s += __shfl_xor_sync(0xffffffffu, s, o);
    __shared__ float sh[8];
    int wid = t >> 5, lid = t & 31;
    if (lid == 0) sh[wid] = s;
    __syncthreads();
    if (t == 0) {
        float ts = 0.f;
        #pragma unroll
        for (int i = 0; i < 8; i++) ts += sh[i];
        out[row] = ts + ob[0];
    }
}

// ---------------------------------------------------------------------------
extern "C" void kernel_launch(void* const* d_in, const int* in_sizes, int n_in,
                              void* d_out, int out_size) {
    const float* z     = (const float*)d_in[0];
    const float* c     = (const float*)d_in[1];
    const float* enc_w = (const float*)d_in[2];
    const float* enc_b = (const float*)d_in[3];
    const float* beta  = (const float*)d_in[4];
    const float* wq    = (const float*)d_in[5];
    const float* bq    = (const float*)d_in[6];
    const float* wk    = (const float*)d_in[7];
    const float* bk    = (const float*)d_in[8];
    const float* wv    = (const float*)d_in[9];
    const float* bv    = (const float*)d_in[10];
    const float* ln1w  = (const float*)d_in[11];
    const float* ln1b  = (const float*)d_in[12];
    const float* ln2w  = (const float*)d_in[13];
    const float* ln2b  = (const float*)d_in[14];
    const float* ff1w  = (const float*)d_in[15];
    const float* ff1b  = (const float*)d_in[16];
    const float* ff2w  = (const float*)d_in[17];
    const float* ff2b  = (const float*)d_in[18];
    const float* outw  = (const float*)d_in[19];
    const float* outb  = (const float*)d_in[20];
    float* out = (float*)d_out;

    float *px, *patt, *pbt, *pbq, *prs;
    __half *pxn, *pq, *pk, *pv, *pp, *ph, *pwh;
    cudaGetSymbolAddress((void**)&px,   g_x);
    cudaGetSymbolAddress((void**)&patt, g_att);
    cudaGetSymbolAddress((void**)&pbt,  g_bt);
    cudaGetSymbolAddress((void**)&pbq,  g_bq);
    cudaGetSymbolAddress((void**)&prs,  g_rs);
    cudaGetSymbolAddress((void**)&pxn,  h_xn);
    cudaGetSymbolAddress((void**)&pq,   h_q);
    cudaGetSymbolAddress((void**)&pk,   h_k);
    cudaGetSymbolAddress((void**)&pv,   h_v);
    cudaGetSymbolAddress((void**)&pp,   h_p);
    cudaGetSymbolAddress((void**)&ph,   h_h);
    cudaGetSymbolAddress((void**)&pwh,  g_wh);

    const int SMEM_NT = NSTAGE * (A_BYTES + BN*RSTR*2);    // 102400
    const int SMEM_NN = NSTAGE * (A_BYTES + BK*NNROWB);    // 94720

    cudaFuncSetAttribute((const void*)mma_gemm<5,true ,true >, cudaFuncAttributeMaxDynamicSharedMemorySize, SMEM_NT);
    cudaFuncSetAttribute((const void*)mma_gemm<1,true ,true >, cudaFuncAttributeMaxDynamicSharedMemorySize, SMEM_NT);
    cudaFuncSetAttribute((const void*)mma_gemm<2,false,true >, cudaFuncAttributeMaxDynamicSharedMemorySize, SMEM_NT);
    cudaFuncSetAttribute((const void*)mma_gemm<6,true ,true >, cudaFuncAttributeMaxDynamicSharedMemorySize, SMEM_NT);
    cudaFuncSetAttribute((const void*)mma_gemm<7,false,false>, cudaFuncAttributeMaxDynamicSharedMemorySize, SMEM_NN);

    // half weights: concat-qkv | ff1 | ff2
    const size_t nqkv = (size_t)NL * 1536 * 512;
    const size_t nff  = (size_t)NL * FF * D;
    __half* wqkv_h = pwh;
    __half* ff1_h  = wqkv_h + nqkv;
    __half* ff2_h  = ff1_h + nff;
    {
        int n4 = NL * 512 * 128;
        concat_h_kernel<<<(n4 + 255)/256, 256>>>((const float4*)wq, wqkv_h, 0);
        concat_h_kernel<<<(n4 + 255)/256, 256>>>((const float4*)wk, wqkv_h, 1);
        concat_h_kernel<<<(n4 + 255)/256, 256>>>((const float4*)wv, wqkv_h, 2);
        concat_bias_kernel<<<(NL*1536 + 255)/256, 256>>>(bq, bk, bv, pbq);
        f2h4_kernel<<<(int)((nff/4 + 255)/256), 256>>>((const float4*)ff1w, ff1_h, (int)(nff/4));
        f2h4_kernel<<<(int)((nff/4 + 255)/256), 256>>>((const float4*)ff2w, ff2_h, (int)(nff/4));
    }

    bias_table_kernel<<<(NL*S + 255)/256, 256>>>(beta, pbt);
    encoder_kernel<<<(ROWS*D + 255)/256, 256>>>(z, c, enc_w, enc_b, px);

    for (int l = 0; l < NL; l++) {
        const float* l1w = ln1w + l * D;
        const float* l1b = ln1b + l * D;
        const float* l2w = ln2w + l * D;
        const float* l2b = ln2b + l * D;

        // pre-norm -> half operand
        ln_kernel<true><<<ROWS, 256>>>(px, nullptr, l1w, l1b, pxn);

        // fused QKV projection (split epilogue, half outputs)
        dim3 gqkv(1536 / BN, ROWS / BM);
        mma_gemm<5,true,true><<<gqkv, 128, SMEM_NT>>>(pxn, wqkv_h + (size_t)l*1536*512,
                                                      pbq + (size_t)l*1536, nullptr,
                                                      pq, pk, pv, 1536, 512, 0, 0, 0,
                                                      nullptr, nullptr);

        // zero row sums, then scores -> unnormalized half probs + row sums
        cudaMemsetAsync(prs, 0, (size_t)B * S * sizeof(float));
        dim3 gsc(S / BN, S / BM, B);
        mma_gemm<6,true,true><<<gsc, 128, SMEM_NT>>>(pq, pk, nullptr, nullptr, pp, nullptr, nullptr,
                                                     S, D, (size_t)S*D, (size_t)S*D, (size_t)S*S,
                                                     pbt + (size_t)l*S, prs);

        // att_out = (P @ V) / rowsum (NN, normalized in epilogue) -> fp32
        dim3 gpv(D / BN, S / BM, B);
        mma_gemm<7,false,false><<<gpv, 128, SMEM_NN>>>(pp, pv, nullptr, nullptr, patt, nullptr, nullptr,
                                                       D, S, (size_t)S*S, (size_t)S*D, (size_t)S*D,
                                                       prs, nullptr);

        // fused: x = LN1(x + att) ; xn = LN2(x) (half)
        ln_pair_kernel<<<ROWS, 256>>>(px, patt, l1w, l1b, l2w, l2b, px, pxn);

        // FF1 + relu -> half
        dim3 gff1(FF / BN, ROWS / BM);
        mma_gemm<1,true,true><<<gff1, 128, SMEM_NT>>>(pxn, ff1_h + (size_t)l*FF*D, ff1b + l*FF, nullptr,
                                                      ph, nullptr, nullptr, FF, D, 0, 0, 0,
                                                      nullptr, nullptr);

        // FF2 + residual -> fp32 x (in place)
        dim3 gff2(D / BN, ROWS / BM);
        mma_gemm<2,false,true><<<gff2, 128, SMEM_NT>>>(ph, ff2_h + (size_t)l*D*FF, ff2b + l*D, px,
                                                       px, nullptr, nullptr, D, FF, 0, 0, 0,
                                                       nullptr, nullptr);
    }

    out_kernel<<<ROWS, 256>>>(px, outw, outb, out);
}

// round 13
// speedup vs baseline: 8.4459x; 1.0063x over previous
#include <cuda_runtime.h>
#include <cuda_fp16.h>
#include <math.h>
#include <stdint.h>

#define NL 6
#define D 512
#define S 2048
#define B 8
#define FF 2048
#define ROWS 16384

// GEMM tiling: 128x128 CTA tile, 4 warps x (64x64), fp16 operands, 2 CTAs/SM
#define BM 128
#define BN 128
#define BK 32                              // halves per chunk
#define RSTR 40                            // NT row stride in halves (80 B)
#define NNROWB 272                         // NN B-tile row stride in bytes (256+16)
#define A_BYTES (BM*RSTR*2)                // 10240
#define NSTAGE 5

// ---------------- scratch (device globals: allocation-free) ----------------
__device__ float  g_x  [ROWS*(size_t)D];
__device__ float  g_att[ROWS*(size_t)D];
__device__ float  g_bt [NL*S];
__device__ float  g_bq [NL*1536];
__device__ float  g_rs [B*S];               // per-row sum of unnormalized probs
__device__ __half h_xn [ROWS*(size_t)D];
__device__ __half h_q  [ROWS*(size_t)D];
__device__ __half h_k  [ROWS*(size_t)D];
__device__ __half h_v  [ROWS*(size_t)D];
__device__ __half h_p  [(size_t)B*S*S];     // half unnormalized probs
__device__ __half h_h  [ROWS*(size_t)FF];
__device__ __half g_wh [17301504];          // half weights: wqkv(concat) | ff1 | ff2

// ---------------- helpers ---------------------------------------------------
__device__ __forceinline__ uint32_t smem_u32(const void* p) {
    uint32_t a;
    asm("{ .reg .u64 t; cvta.to.shared.u64 t, %1; cvt.u32.u64 %0, t; }"
        : "=r"(a) : "l"(p));
    return a;
}

__device__ __forceinline__ void mma_f16(float* c, const unsigned* a, const unsigned* b) {
    asm volatile(
        "mma.sync.aligned.m16n8k16.row.col.f32.f16.f16.f32 "
        "{%0,%1,%2,%3}, {%4,%5,%6,%7}, {%8,%9}, {%0,%1,%2,%3};\n"
        : "+f"(c[0]), "+f"(c[1]), "+f"(c[2]), "+f"(c[3])
        : "r"(a[0]), "r"(a[1]), "r"(a[2]), "r"(a[3]), "r"(b[0]), "r"(b[1]));
}

__device__ __forceinline__ void ldsm_x4(unsigned* r, uint32_t addr) {
    asm volatile("ldmatrix.sync.aligned.m8n8.x4.shared.b16 {%0,%1,%2,%3}, [%4];"
        : "=r"(r[0]), "=r"(r[1]), "=r"(r[2]), "=r"(r[3]) : "r"(addr));
}

__device__ __forceinline__ void ldsm_x4_t(unsigned* r, uint32_t addr) {
    asm volatile("ldmatrix.sync.aligned.m8n8.x4.trans.shared.b16 {%0,%1,%2,%3}, [%4];"
        : "=r"(r[0]), "=r"(r[1]), "=r"(r[2]), "=r"(r[3]) : "r"(addr));
}

__device__ __forceinline__ void cp16(uint32_t dst, const void* src) {
    asm volatile("cp.async.cg.shared.global [%0], [%1], 16;"
        :: "r"(dst), "l"(__cvta_generic_to_global(src)) : "memory");
}

// ---------------- tensor-core GEMM (mma.sync fp16 -> fp32 acc, ldmatrix) -----
// TRB=true : C = A[M,K] @ Bm[N,K]^T  (NT; both K-major)
// TRB=false: C = A[M,K] @ Bm[K,N]    (NN; B k-row-major, trans ldmatrix)
// EPI: 1=bias+relu 2=bias+resid 5=bias+qkv-split
//      6=scores: p=exp(v*scale+table)->half, rowsum atomics into rsum
//      7=pv-normalize: v /= rsum[row] (rsum passed via table)
template<int EPI, bool OUTH, bool TRB>
__global__ void __launch_bounds__(128, 2) mma_gemm(
    const __half* __restrict__ A, const __half* __restrict__ Bm,
    const float* __restrict__ bias, const float* __restrict__ resid,
    void* __restrict__ Cv, void* __restrict__ C2v, void* __restrict__ C3v,
    int N, int K, size_t sA, size_t sB, size_t sC,
    const float* __restrict__ table, float* __restrict__ rsum)
{
    constexpr int BTB = TRB ? (BN*RSTR*2) : (BK*NNROWB);   // B tile bytes
    constexpr int STB = A_BYTES + BTB;                      // stage bytes

    extern __shared__ __half smh[];
    const uint32_t smbase = smem_u32(smh);

    const int tid  = threadIdx.x;
    const int wid  = tid >> 5;
    const int lane = tid & 31;
    const int g    = lane >> 2;
    const int tg   = lane & 3;
    const int m0   = (wid >> 1) * 64;
    const int n0   = (wid & 1) * 64;

    const uint32_t aoff = (uint32_t)(((lane & 7) + ((lane >> 3) & 1) * 8) * RSTR + (lane >> 4) * 8);
    const uint32_t boff = (uint32_t)(((lane & 7) + ((lane >> 4) & 1) * 8) * RSTR + ((lane >> 3) & 1) * 8);
    const uint32_t btoff = (uint32_t)(((lane & 7) + ((lane >> 3) & 1) * 8) * NNROWB + ((lane >> 4) & 1) * 16);

    A  += (size_t)blockIdx.z * sA;
    Bm += (size_t)blockIdx.z * sB;
    const int rowBase = blockIdx.y * BM;
    const int colBase = blockIdx.x * BN;
    const __half* Ag = A + (size_t)rowBase * K;
    const __half* Bg = TRB ? (Bm + (size_t)colBase * K) : (Bm + colBase);

    float acc[4][8][4] = {};

    const int nc = K / BK;

    auto load_chunk = [&](int j, int stage) {
        const uint32_t st = smbase + (uint32_t)stage * STB;
        const __half* asrc = Ag + (size_t)j * BK;
        #pragma unroll
        for (int u = 0; u < 4; u++) {
            int idx = tid + u * 128;
            int row = idx >> 2, c4 = idx & 3;
            cp16(st + row * 80 + c4 * 16, asrc + (size_t)row * K + c4 * 8);
        }
        const uint32_t stb = st + A_BYTES;
        if (TRB) {
            const __half* bsrc = Bg + (size_t)j * BK;
            #pragma unroll
            for (int u = 0; u < 4; u++) {
                int idx = tid + u * 128;
                int row = idx >> 2, c4 = idx & 3;
                cp16(stb + row * 80 + c4 * 16, bsrc + (size_t)row * K + c4 * 8);
            }
        } else {
            const __half* bsrc = Bg + (size_t)j * BK * N;
            #pragma unroll
            for (int u = 0; u < 4; u++) {
                int idx = tid + u * 128;
                int row = idx >> 4, c16 = idx & 15;
                cp16(stb + row * NNROWB + c16 * 16, bsrc + (size_t)row * N + c16 * 8);
            }
        }
        asm volatile("cp.async.commit_group;" ::: "memory");
    };

    load_chunk(0, 0);
    load_chunk(1, 1);
    load_chunk(2, 2);
    load_chunk(3, 3);

    int cs = 0;
    int ps = 4 % NSTAGE;
    for (int i = 0; i < nc; i++) {
        if (i < nc - 3)       asm volatile("cp.async.wait_group 3;" ::: "memory");
        else if (i == nc - 3) asm volatile("cp.async.wait_group 2;" ::: "memory");
        else if (i == nc - 2) asm volatile("cp.async.wait_group 1;" ::: "memory");
        else                  asm volatile("cp.async.wait_group 0;" ::: "memory");
        __syncthreads();

        if (i + 4 < nc) {
            load_chunk(i + 4, ps);
            if (++ps == NSTAGE) ps = 0;
        }

        const uint32_t sa = smbase + (uint32_t)cs * STB;
        const uint32_t sb = sa + A_BYTES;
        if (++cs == NSTAGE) cs = 0;

        // ---- intra-chunk pipelining: issue ALL 16 LDSM up front, then 64 MMA
        unsigned af[2][4][4];
        unsigned bq[2][4][4];
        #pragma unroll
        for (int ks = 0; ks < 2; ks++) {
            #pragma unroll
            for (int mt = 0; mt < 4; mt++)
                ldsm_x4(af[ks][mt], sa + 2u * (aoff + (uint32_t)((m0 + mt*16) * RSTR + ks*16)));
            #pragma unroll
            for (int j = 0; j < 4; j++) {
                if (TRB)
                    ldsm_x4(bq[ks][j], sb + 2u * (boff + (uint32_t)((n0 + j*16) * RSTR + ks*16)));
                else
                    ldsm_x4_t(bq[ks][j], sb + btoff + (uint32_t)((n0 + j*16) * 2 + ks*16*NNROWB));
            }
        }
        #pragma unroll
        for (int ks = 0; ks < 2; ks++)
            #pragma unroll
            for (int mt = 0; mt < 4; mt++)
                #pragma unroll
                for (int j = 0; j < 4; j++) {
                    mma_f16(acc[mt][2*j    ], af[ks][mt], &bq[ks][j][0]);
                    mma_f16(acc[mt][2*j + 1], af[ks][mt], &bq[ks][j][2]);
                }
    }

    // ---- epilogue ----
    const size_t cBatch = (size_t)blockIdx.z * sC;
    const float scale = 0.044194173824159216f;   // 1/sqrt(512)

    if (EPI == 6) {
        // scores: unnormalized exp-probs (half) + row-sum atomics
        __half* P = (__half*)Cv + cBatch;
        float* rsbase = rsum + (size_t)blockIdx.z * S;
        #pragma unroll
        for (int mt = 0; mt < 4; mt++) {
            #pragma unroll
            for (int half_ = 0; half_ < 2; half_++) {
                const int r = rowBase + m0 + mt*16 + g + half_*8;
                float rsumv = 0.f;
                #pragma unroll
                for (int nt = 0; nt < 8; nt++) {
                    const int cb = colBase + n0 + nt*8 + tg*2;
                    float v0 = __expf(acc[mt][nt][half_*2 + 0] * scale + table[abs(r - cb)]);
                    float v1 = __expf(acc[mt][nt][half_*2 + 1] * scale + table[abs(r - cb - 1)]);
                    __half hv0 = __float2half_rn(v0);
                    __half hv1 = __float2half_rn(v1);
                    *(__half2*)(P + (size_t)r * N + cb) = __halves2half2(hv0, hv1);
                    rsumv += __half2float(hv0) + __half2float(hv1);   // sum the rounded values
                }
                rsumv += __shfl_xor_sync(0xffffffffu, rsumv, 1);
                rsumv += __shfl_xor_sync(0xffffffffu, rsumv, 2);
                if (tg == 0) atomicAdd(rsbase + r, rsumv);
            }
        }
        return;
    }

    void* Cout = Cv;
    int Nout = N;
    int colDelta = 0;
    if (EPI == 5) {
        const int sec = colBase >> 9;
        Cout = (sec == 0) ? Cv : (sec == 1 ? C2v : C3v);
        colDelta = sec << 9;
        Nout = 512;
    }
    #pragma unroll
    for (int mt = 0; mt < 4; mt++) {
        #pragma unroll
        for (int half_ = 0; half_ < 2; half_++) {
            const int r = rowBase + m0 + mt*16 + g + half_*8;
            float inv = 1.0f;
            if (EPI == 7) inv = 1.0f / table[(size_t)blockIdx.z * S + r];   // table = rowsum
            #pragma unroll
            for (int nt = 0; nt < 8; nt++) {
                const float* c = acc[mt][nt];
                const int cb = colBase + n0 + nt*8 + tg*2;
                float v0 = c[half_*2 + 0];
                float v1 = c[half_*2 + 1];
                if (EPI == 1 || EPI == 2 || EPI == 5) {
                    v0 += bias[cb];
                    v1 += bias[cb + 1];
                    if (EPI == 1) { v0 = fmaxf(v0, 0.f); v1 = fmaxf(v1, 0.f); }
                    if (EPI == 2) {
                        v0 += resid[cBatch + (size_t)r * N + cb];
                        v1 += resid[cBatch + (size_t)r * N + cb + 1];
                    }
                } else if (EPI == 7) {
                    v0 *= inv;
                    v1 *= inv;
                }
                const size_t off = cBatch + (size_t)r * Nout + (cb - colDelta);
                if (OUTH) {
                    *(__half2*)((__half*)Cout + off) = __floats2half2_rn(v0, v1);
                } else {
                    *(float2*)((float*)Cout + off) = make_float2(v0, v1);
                }
            }
        }
    }
}

// ---------------- prep kernels -----------------------------------------------
__global__ void f2h4_kernel(const float4* __restrict__ in, __half* __restrict__ out, int n4) {
    int i = blockIdx.x * blockDim.x + threadIdx.x;
    if (i >= n4) return;
    float4 a = in[i];
    *(__half2*)(out + (size_t)i*4)     = __floats2half2_rn(a.x, a.y);
    *(__half2*)(out + (size_t)i*4 + 2) = __floats2half2_rn(a.z, a.w);
}

__global__ void concat_h_kernel(const float4* __restrict__ src, __half* __restrict__ dst, int sec) {
    const int per = 512 * 128;
    int i = blockIdx.x * blockDim.x + threadIdx.x;
    if (i >= NL * per) return;
    int l = i / per, j = i % per;
    float4 a = src[(size_t)l * per + j];
    __half* d = dst + ((size_t)l * 3 + sec) * (512*512) + (size_t)j * 4;
    *(__half2*)(d)     = __floats2half2_rn(a.x, a.y);
    *(__half2*)(d + 2) = __floats2half2_rn(a.z, a.w);
}

__global__ void concat_bias_kernel(const float* __restrict__ bq, const float* __restrict__ bk,
                                   const float* __restrict__ bv, float* __restrict__ dst) {
    int i = blockIdx.x * blockDim.x + threadIdx.x;
    if (i >= NL * 1536) return;
    int l = i / 1536, j = i % 1536;
    const float* src = (j < 512) ? bq : (j < 1024 ? bk : bv);
    dst[i] = src[l * 512 + (j & 511)];
}

__global__ void bias_table_kernel(const float* __restrict__ beta, float* __restrict__ bt) {
    int i = blockIdx.x * blockDim.x + threadIdx.x;
    if (i >= NL * S) return;
    int l = i / S;
    float d = (float)(i % S);
    bt[i] = beta[l*2 + 0] * cosf(6.283185307179586f * d / 24.0f)
          + beta[l*2 + 1] * cosf(6.283185307179586f * d / 720.0f);
}

__global__ void encoder_kernel(const float* __restrict__ z, const float* __restrict__ c,
                               const float* __restrict__ ew, const float* __restrict__ eb,
                               float* __restrict__ x) {
    int i = blockIdx.x * blockDim.x + threadIdx.x;
    if (i >= ROWS * D) return;
    int d  = i % D;
    int bs = i / D;
    int s  = bs % S;
    float val = z[bs] * ew[d*2+0] + c[bs] * ew[d*2+1] + eb[d];
    int k2 = d & ~1;
    float div = expf(-(float)k2 * (logf(10000.0f) / (float)D));
    float ang = (float)s * div;
    val += (d & 1) ? cosf(ang) : sinf(ang);
    x[i] = val;
}

// single layernorm; OUTH selects half vs fp32 output
template<bool OUTH>
__global__ void ln_kernel(const float* __restrict__ in, const float* __restrict__ res,
                          const float* __restrict__ w, const float* __restrict__ b,
                          void* __restrict__ outv) {
    int row = blockIdx.x;
    const float* ip = in + (size_t)row * D;
    int t = threadIdx.x;
    float v0 = ip[t];
    float v1 = ip[t + 256];
    if (res) {
        const float* rp = res + (size_t)row * D;
        v0 += rp[t];
        v1 += rp[t + 256];
    }
    float s = v0 + v1, ss = v0*v0 + v1*v1;
    #pragma unroll
    for (int o = 16; o; o >>= 1) {
        s  += __shfl_xor_sync(0xffffffffu, s,  o);
        ss += __shfl_xor_sync(0xffffffffu, ss, o);
    }
    __shared__ float sh_s[8], sh_ss[8];
    int wid = t >> 5, lid = t & 31;
    if (lid == 0) { sh_s[wid] = s; sh_ss[wid] = ss; }
    __syncthreads();
    float ts = 0.f, tss = 0.f;
    #pragma unroll
    for (int i = 0; i < 8; i++) { ts += sh_s[i]; tss += sh_ss[i]; }
    float mean = ts * (1.0f / D);
    float var  = tss * (1.0f / D) - mean * mean;
    float rstd = rsqrtf(var + 1e-5f);
    float o0 = (v0 - mean) * rstd * w[t]       + b[t];
    float o1 = (v1 - mean) * rstd * w[t + 256] + b[t + 256];
    if (OUTH) {
        __half* op = (__half*)outv + (size_t)row * D;
        op[t]       = __float2half_rn(o0);
        op[t + 256] = __float2half_rn(o1);
    } else {
        float* op = (float*)outv + (size_t)row * D;
        op[t]       = o0;
        op[t + 256] = o1;
    }
}

// fused pair: x' = LN1(x + att) -> out1 (fp32); LN2(x') -> out2 (half)
__global__ void ln_pair_kernel(const float* __restrict__ in, const float* __restrict__ res,
                               const float* __restrict__ w1, const float* __restrict__ b1,
                               const float* __restrict__ w2, const float* __restrict__ b2,
                               float* __restrict__ out1, __half* __restrict__ out2) {
    int row = blockIdx.x;
    int t = threadIdx.x;
    const float* ip = in  + (size_t)row * D;
    const float* rp = res + (size_t)row * D;
    float v0 = ip[t]       + rp[t];
    float v1 = ip[t + 256] + rp[t + 256];

    __shared__ float sh_s[8], sh_ss[8];
    int wid = t >> 5, lid = t & 31;

    float s = v0 + v1, ss = v0*v0 + v1*v1;
    #pragma unroll
    for (int o = 16; o; o >>= 1) {
        s  += __shfl_xor_sync(0xffffffffu, s,  o);
        ss += __shfl_xor_sync(0xffffffffu, ss, o);
    }
    if (lid == 0) { sh_s[wid] = s; sh_ss[wid] = ss; }
    __syncthreads();
    float ts = 0.f, tss = 0.f;
    #pragma unroll
    for (int i = 0; i < 8; i++) { ts += sh_s[i]; tss += sh_ss[i]; }
    float mean = ts * (1.0f / D);
    float var  = tss * (1.0f / D) - mean * mean;
    float rstd = rsqrtf(var + 1e-5f);
    float o0 = (v0 - mean) * rstd * w1[t]       + b1[t];
    float o1 = (v1 - mean) * rstd * w1[t + 256] + b1[t + 256];
    float* op1 = out1 + (size_t)row * D;
    op1[t]       = o0;
    op1[t + 256] = o1;
    __syncthreads();

    s = o0 + o1; ss = o0*o0 + o1*o1;
    #pragma unroll
    for (int o = 16; o; o >>= 1) {
        s  += __shfl_xor_sync(0xffffffffu, s,  o);
        ss += __shfl_xor_sync(0xffffffffu, ss, o);
    }
    if (lid == 0) { sh_s[wid] = s; sh_ss[wid] = ss; }
    __syncthreads();
    ts = 0.f; tss = 0.f;
    #pragma unroll
    for (int i = 0; i < 8; i++) { ts += sh_s[i]; tss += sh_ss[i]; }
    mean = ts * (1.0f / D);
    var  = tss * (1.0f / D) - mean * mean;
    rstd = rsqrtf(var + 1e-5f);
    __half* op2 = out2 + (size_t)row * D;
    op2[t]       = __float2half_rn((o0 - mean) * rstd * w2[t]       + b2[t]);
    op2[t + 256] = __float2half_rn((o1 - mean) * rstd * w2[t + 256] + b2[t + 256]);
}

__global__ void out_kernel(const float* __restrict__ x, const float* __restrict__ ow,
                           const float* __restrict__ ob, float* __restrict__ out) {
    int row = blockIdx.x;
    const float* p = x + (size_t)row * D;
    int t = threadIdx.x;
    float s = p[t] * ow[t] + p[t + 256] * ow[t + 256];
    #pragma unroll
    for (int o = 16; o; o >>= 1) s += __shfl_xor_sync(0xffffffffu, s, o);
    __shared__ float sh[8];
    int wid = t >> 5, lid = t & 31;
    if (lid == 0) sh[wid] = s;
    __syncthreads();
    if (t == 0) {
        float ts = 0.f;
        #pragma unroll
        for (int i = 0; i < 8; i++) ts += sh[i];
        out[row] = ts + ob[0];
    }
}

// ---------------------------------------------------------------------------
extern "C" void kernel_launch(void* const* d_in, const int* in_sizes, int n_in,
                              void* d_out, int out_size) {
    const float* z     = (const float*)d_in[0];
    const float* c     = (const float*)d_in[1];
    const float* enc_w = (const float*)d_in[2];
    const float* enc_b = (const float*)d_in[3];
    const float* beta  = (const float*)d_in[4];
    const float* wq    = (const float*)d_in[5];
    const float* bq    = (const float*)d_in[6];
    const float* wk    = (const float*)d_in[7];
    const float* bk    = (const float*)d_in[8];
    const float* wv    = (const float*)d_in[9];
    const float* bv    = (const float*)d_in[10];
    const float* ln1w  = (const float*)d_in[11];
    const float* ln1b  = (const float*)d_in[12];
    const float* ln2w  = (const float*)d_in[13];
    const float* ln2b  = (const float*)d_in[14];
    const float* ff1w  = (const float*)d_in[15];
    const float* ff1b  = (const float*)d_in[16];
    const float* ff2w  = (const float*)d_in[17];
    const float* ff2b  = (const float*)d_in[18];
    const float* outw  = (const float*)d_in[19];
    const float* outb  = (const float*)d_in[20];
    float* out = (float*)d_out;

    float *px, *patt, *pbt, *pbq, *prs;
    __half *pxn, *pq, *pk, *pv, *pp, *ph, *pwh;
    cudaGetSymbolAddress((void**)&px,   g_x);
    cudaGetSymbolAddress((void**)&patt, g_att);
    cudaGetSymbolAddress((void**)&pbt,  g_bt);
    cudaGetSymbolAddress((void**)&pbq,  g_bq);
    cudaGetSymbolAddress((void**)&prs,  g_rs);
    cudaGetSymbolAddress((void**)&pxn,  h_xn);
    cudaGetSymbolAddress((void**)&pq,   h_q);
    cudaGetSymbolAddress((void**)&pk,   h_k);
    cudaGetSymbolAddress((void**)&pv,   h_v);
    cudaGetSymbolAddress((void**)&pp,   h_p);
    cudaGetSymbolAddress((void**)&ph,   h_h);
    cudaGetSymbolAddress((void**)&pwh,  g_wh);

    const int SMEM_NT = NSTAGE * (A_BYTES + BN*RSTR*2);    // 102400
    const int SMEM_NN = NSTAGE * (A_BYTES + BK*NNROWB);    // 94720

    cudaFuncSetAttribute((const void*)mma_gemm<5,true ,true >, cudaFuncAttributeMaxDynamicSharedMemorySize, SMEM_NT);
    cudaFuncSetAttribute((const void*)mma_gemm<1,true ,true >, cudaFuncAttributeMaxDynamicSharedMemorySize, SMEM_NT);
    cudaFuncSetAttribute((const void*)mma_gemm<2,false,true >, cudaFuncAttributeMaxDynamicSharedMemorySize, SMEM_NT);
    cudaFuncSetAttribute((const void*)mma_gemm<6,true ,true >, cudaFuncAttributeMaxDynamicSharedMemorySize, SMEM_NT);
    cudaFuncSetAttribute((const void*)mma_gemm<7,false,false>, cudaFuncAttributeMaxDynamicSharedMemorySize, SMEM_NN);

    // half weights: concat-qkv | ff1 | ff2
    const size_t nqkv = (size_t)NL * 1536 * 512;
    const size_t nff  = (size_t)NL * FF * D;
    __half* wqkv_h = pwh;
    __half* ff1_h  = wqkv_h + nqkv;
    __half* ff2_h  = ff1_h + nff;
    {
        int n4 = NL * 512 * 128;
        concat_h_kernel<<<(n4 + 255)/256, 256>>>((const float4*)wq, wqkv_h, 0);
        concat_h_kernel<<<(n4 + 255)/256, 256>>>((const float4*)wk, wqkv_h, 1);
        concat_h_kernel<<<(n4 + 255)/256, 256>>>((const float4*)wv, wqkv_h, 2);
        concat_bias_kernel<<<(NL*1536 + 255)/256, 256>>>(bq, bk, bv, pbq);
        f2h4_kernel<<<(int)((nff/4 + 255)/256), 256>>>((const float4*)ff1w, ff1_h, (int)(nff/4));
        f2h4_kernel<<<(int)((nff/4 + 255)/256), 256>>>((const float4*)ff2w, ff2_h, (int)(nff/4));
    }

    bias_table_kernel<<<(NL*S + 255)/256, 256>>>(beta, pbt);
    encoder_kernel<<<(ROWS*D + 255)/256, 256>>>(z, c, enc_w, enc_b, px);

    for (int l = 0; l < NL; l++) {
        const float* l1w = ln1w + l * D;
        const float* l1b = ln1b + l * D;
        const float* l2w = ln2w + l * D;
        const float* l2b = ln2b + l * D;

        // pre-norm -> half operand
        ln_kernel<true><<<ROWS, 256>>>(px, nullptr, l1w, l1b, pxn);

        // fused QKV projection (split epilogue, half outputs)
        dim3 gqkv(1536 / BN, ROWS / BM);
        mma_gemm<5,true,true><<<gqkv, 128, SMEM_NT>>>(pxn, wqkv_h + (size_t)l*1536*512,
                                                      pbq + (size_t)l*1536, nullptr,
                                                      pq, pk, pv, 1536, 512, 0, 0, 0,
                                                      nullptr, nullptr);

        // zero row sums, then scores -> unnormalized half probs + row sums
        cudaMemsetAsync(prs, 0, (size_t)B * S * sizeof(float));
        dim3 gsc(S / BN, S / BM, B);
        mma_gemm<6,true,true><<<gsc, 128, SMEM_NT>>>(pq, pk, nullptr, nullptr, pp, nullptr, nullptr,
                                                     S, D, (size_t)S*D, (size_t)S*D, (size_t)S*S,
                                                     pbt + (size_t)l*S, prs);

        // att_out = (P @ V) / rowsum (NN, normalized in epilogue) -> fp32
        dim3 gpv(D / BN, S / BM, B);
        mma_gemm<7,false,false><<<gpv, 128, SMEM_NN>>>(pp, pv, nullptr, nullptr, patt, nullptr, nullptr,
                                                       D, S, (size_t)S*S, (size_t)S*D, (size_t)S*D,
                                                       prs, nullptr);

        // fused: x = LN1(x + att) ; xn = LN2(x) (half)
        ln_pair_kernel<<<ROWS, 256>>>(px, patt, l1w, l1b, l2w, l2b, px, pxn);

        // FF1 + relu -> half
        dim3 gff1(FF / BN, ROWS / BM);
        mma_gemm<1,true,true><<<gff1, 128, SMEM_NT>>>(pxn, ff1_h + (size_t)l*FF*D, ff1b + l*FF, nullptr,
                                                      ph, nullptr, nullptr, FF, D, 0, 0, 0,
                                                      nullptr, nullptr);

        // FF2 + residual -> fp32 x (in place)
        dim3 gff2(D / BN, ROWS / BM);
        mma_gemm<2,false,true><<<gff2, 128, SMEM_NT>>>(ph, ff2_h + (size_t)l*D*FF, ff2b + l*D, px,
                                                       px, nullptr, nullptr, D, FF, 0, 0, 0,
                                                       nullptr, nullptr);
    }

    out_kernel<<<ROWS, 256>>>(px, outw, outb, out);
}